// round 3
// baseline (speedup 1.0000x reference)
#include <cuda_runtime.h>
#include <math.h>

// ---------------------------------------------------------------------------
// Problem constants
//   x:      (4, 2048, 1024) f32
//   w_qkv:  (1024, 3072)    f32
//   b_qkv:  (3072,)         f32
//   w_out:  (1024, 1024)    f32
//   b_out:  (1024,)         f32
//   out:    (4, 2048, 1024) f32
// ---------------------------------------------------------------------------
#define B_   4
#define T_   2048
#define C_   1024
#define H_   16
#define DH_  64
#define M_   (B_ * T_)       // 8192
#define C3_  (3 * C_)        // 3072

// Scratch (allocation-free rule: __device__ globals)
__device__ float g_qkv[(size_t)M_ * C3_];   // 96 MB
__device__ float g_att[(size_t)M_ * C_];    // 32 MB

// ---------------------------------------------------------------------------
// Tiled SGEMM with bias:  C[M,N] = A[M,K] * B[K,N] + bias[N]
// 128x128 tile, BK=16, 256 threads, 8x8 register tile per thread.
// Requires M%128==0, N%128==0, K%16==0 (true for all our shapes).
// ---------------------------------------------------------------------------
#define BM 128
#define BN 128
#define BK 16
#define TM 8
#define TN 8

__global__ __launch_bounds__(256) void gemm_bias_kernel(
    const float* __restrict__ A, const float* __restrict__ Bm,
    const float* __restrict__ bias, float* __restrict__ Cm,
    int M, int N, int K)
{
    __shared__ float As[BK][BM + 4];   // transposed A tile; row stride 132 floats (16B-mult)
    __shared__ float Bs[BK][BN];

    const int tid = threadIdx.x;
    const int tx = tid & 15;           // 0..15 -> N direction
    const int ty = tid >> 4;           // 0..15 -> M direction
    const int bx = blockIdx.x;         // N tile
    const int by = blockIdx.y;         // M tile

    const float* Ab = A + (size_t)by * BM * K;
    const float* Bb = Bm + (size_t)bx * BN;

    float acc[TM][TN];
#pragma unroll
    for (int i = 0; i < TM; i++)
#pragma unroll
        for (int j = 0; j < TN; j++) acc[i][j] = 0.f;

    for (int k0 = 0; k0 < K; k0 += BK) {
        // Load A tile 128x16 (512 float4, 2/thread), store transposed
#pragma unroll
        for (int it = 0; it < 2; it++) {
            int idx = tid + it * 256;          // 0..511
            int row = idx >> 2;                // 0..127
            int k4  = (idx & 3) << 2;          // 0,4,8,12
            float4 v = *(const float4*)(Ab + (size_t)row * K + k0 + k4);
            As[k4 + 0][row] = v.x;
            As[k4 + 1][row] = v.y;
            As[k4 + 2][row] = v.z;
            As[k4 + 3][row] = v.w;
        }
        // Load B tile 16x128 (512 float4, 2/thread), direct
#pragma unroll
        for (int it = 0; it < 2; it++) {
            int idx = tid + it * 256;
            int row = idx >> 5;                // 0..15
            int c4  = (idx & 31) << 2;         // 0..124
            *(float4*)(&Bs[row][c4]) =
                *(const float4*)(Bb + (size_t)(k0 + row) * N + c4);
        }
        __syncthreads();

#pragma unroll
        for (int kk = 0; kk < BK; kk++) {
            float a[TM], b[TN];
            float4 a0 = *(const float4*)(&As[kk][ty * TM + 0]);
            float4 a1 = *(const float4*)(&As[kk][ty * TM + 4]);
            a[0]=a0.x; a[1]=a0.y; a[2]=a0.z; a[3]=a0.w;
            a[4]=a1.x; a[5]=a1.y; a[6]=a1.z; a[7]=a1.w;
            float4 b0 = *(const float4*)(&Bs[kk][tx * TN + 0]);
            float4 b1 = *(const float4*)(&Bs[kk][tx * TN + 4]);
            b[0]=b0.x; b[1]=b0.y; b[2]=b0.z; b[3]=b0.w;
            b[4]=b1.x; b[5]=b1.y; b[6]=b1.z; b[7]=b1.w;
#pragma unroll
            for (int i = 0; i < TM; i++)
#pragma unroll
                for (int j = 0; j < TN; j++)
                    acc[i][j] += a[i] * b[j];
        }
        __syncthreads();
    }

    // Epilogue: add bias, store
#pragma unroll
    for (int i = 0; i < TM; i++) {
        int row = by * BM + ty * TM + i;
#pragma unroll
        for (int j = 0; j < TN; j += 4) {
            int col = bx * BN + tx * TN + j;
            float4 o;
            o.x = acc[i][j + 0] + bias[col + 0];
            o.y = acc[i][j + 1] + bias[col + 1];
            o.z = acc[i][j + 2] + bias[col + 2];
            o.w = acc[i][j + 3] + bias[col + 3];
            *(float4*)(Cm + (size_t)row * N + col) = o;
        }
    }
}

// ---------------------------------------------------------------------------
// Flash attention (causal), fp32.
// Grid: (T/64, H, B). Block: 256 threads = 16x16, each thread owns a 4x4
// fragment of the 64x64 S tile and a 4(x)x4(dim) fragment of the O tile.
// Q,K in smem transposed [d][pos] (stride 68 -> 16B-aligned float4 rows),
// V in smem [pos][d], P staged via smem for the P*V product.
// ---------------------------------------------------------------------------
#define QSTRIDE 68   // padded row stride for Qs/Ks/Ps (68*4 bytes, 16B multiple)

__global__ __launch_bounds__(256) void attn_kernel(
    const float* __restrict__ qkv, float* __restrict__ out)
{
    extern __shared__ float sm[];
    float* Qs = sm;                       // [64][68]  (d-major, transposed)
    float* Ks = Qs + 64 * QSTRIDE;        // [64][68]  (d-major, transposed)
    float* Ps = Ks + 64 * QSTRIDE;        // [64][68]  (q-major)
    float* Vs = Ps + 64 * QSTRIDE;        // [64][64]  (kpos-major)

    const int qt = blockIdx.x;            // q tile 0..31
    const int h  = blockIdx.y;
    const int b  = blockIdx.z;
    const int tid = threadIdx.x;
    const int tx = tid & 15;              // column group (key pos / head dim)
    const int ty = tid >> 4;              // row group (query pos)
    const int q0 = qt * 64;
    const float scale = 0.125f;           // 1/sqrt(64)

    // Load Q tile transposed, pre-scaled
    const float* Qg = qkv + ((size_t)(b * T_ + q0)) * C3_ + h * DH_;
    for (int i = tid; i < 64 * 64; i += 256) {
        int pos = i >> 6, d = i & 63;
        Qs[d * QSTRIDE + pos] = Qg[(size_t)pos * C3_ + d] * scale;
    }

    float m_prev[4], l[4], o[4][4];
#pragma unroll
    for (int i = 0; i < 4; i++) {
        m_prev[i] = -1e30f; l[i] = 0.f;
#pragma unroll
        for (int j = 0; j < 4; j++) o[i][j] = 0.f;
    }

    for (int kt = 0; kt <= qt; kt++) {
        __syncthreads();   // prior iter done reading Ks/Vs/Ps; Qs writes visible

        const int k0 = kt * 64;
        const float* Kg = qkv + ((size_t)(b * T_ + k0)) * C3_ + C_ + h * DH_;
        const float* Vg = Kg + C_;
        for (int i = tid; i < 64 * 64; i += 256) {
            int pos = i >> 6, d = i & 63;
            Ks[d * QSTRIDE + pos] = Kg[(size_t)pos * C3_ + d];
            Vs[pos * 64 + d]      = Vg[(size_t)pos * C3_ + d];
        }
        __syncthreads();

        // S = Q K^T  (4x4 fragment per thread)
        float s[4][4];
#pragma unroll
        for (int i = 0; i < 4; i++)
#pragma unroll
            for (int j = 0; j < 4; j++) s[i][j] = 0.f;

#pragma unroll 8
        for (int d = 0; d < 64; d++) {
            float4 av = *(const float4*)(&Qs[d * QSTRIDE + ty * 4]);
            float4 bv = *(const float4*)(&Ks[d * QSTRIDE + tx * 4]);
            float a[4] = {av.x, av.y, av.z, av.w};
            float bb[4] = {bv.x, bv.y, bv.z, bv.w};
#pragma unroll
            for (int i = 0; i < 4; i++)
#pragma unroll
                for (int j = 0; j < 4; j++)
                    s[i][j] += a[i] * bb[j];
        }

        // Causal mask (only the diagonal tile needs it: k0 == q0)
        if (kt == qt) {
#pragma unroll
            for (int i = 0; i < 4; i++)
#pragma unroll
                for (int j = 0; j < 4; j++)
                    if (tx * 4 + j > ty * 4 + i) s[i][j] = -1e30f;
        }

        // Online softmax (rows shared by the 16 tx-lanes within a half-warp)
#pragma unroll
        for (int i = 0; i < 4; i++) {
            float mx = fmaxf(fmaxf(s[i][0], s[i][1]), fmaxf(s[i][2], s[i][3]));
            mx = fmaxf(mx, __shfl_xor_sync(0xffffffffu, mx, 1));
            mx = fmaxf(mx, __shfl_xor_sync(0xffffffffu, mx, 2));
            mx = fmaxf(mx, __shfl_xor_sync(0xffffffffu, mx, 4));
            mx = fmaxf(mx, __shfl_xor_sync(0xffffffffu, mx, 8));
            float nm = fmaxf(m_prev[i], mx);
            float corr = __expf(m_prev[i] - nm);
            float rs = 0.f;
#pragma unroll
            for (int j = 0; j < 4; j++) {
                float p = __expf(s[i][j] - nm);
                s[i][j] = p;
                rs += p;
            }
            rs += __shfl_xor_sync(0xffffffffu, rs, 1);
            rs += __shfl_xor_sync(0xffffffffu, rs, 2);
            rs += __shfl_xor_sync(0xffffffffu, rs, 4);
            rs += __shfl_xor_sync(0xffffffffu, rs, 8);
            l[i] = l[i] * corr + rs;
            m_prev[i] = nm;
#pragma unroll
            for (int j = 0; j < 4; j++) o[i][j] *= corr;
            // stage P
            *(float4*)(&Ps[(ty * 4 + i) * QSTRIDE + tx * 4]) =
                make_float4(s[i][0], s[i][1], s[i][2], s[i][3]);
        }
        __syncthreads();

        // O += P * V   (thread owns rows ty*4+i, head dims tx*4+j)
#pragma unroll 8
        for (int kk = 0; kk < 64; kk++) {
            float4 vv = *(const float4*)(&Vs[kk * 64 + tx * 4]);
            float pv[4] = {vv.x, vv.y, vv.z, vv.w};
#pragma unroll
            for (int i = 0; i < 4; i++) {
                float pr = Ps[(ty * 4 + i) * QSTRIDE + kk];
#pragma unroll
                for (int j = 0; j < 4; j++)
                    o[i][j] += pr * pv[j];
            }
        }
    }

    // Write O / l  into (b, t, h*64+d) layout
    float* Og = out + ((size_t)(b * T_ + q0)) * C_ + h * DH_;
#pragma unroll
    for (int i = 0; i < 4; i++) {
        float inv = 1.f / l[i];
        float4 ov = make_float4(o[i][0] * inv, o[i][1] * inv,
                                o[i][2] * inv, o[i][3] * inv);
        *(float4*)(Og + (size_t)(ty * 4 + i) * C_ + tx * 4) = ov;
    }
}

// ---------------------------------------------------------------------------
// Launch
// ---------------------------------------------------------------------------
extern "C" void kernel_launch(void* const* d_in, const int* in_sizes, int n_in,
                              void* d_out, int out_size)
{
    const float* x     = (const float*)d_in[0];
    const float* w_qkv = (const float*)d_in[1];
    const float* b_qkv = (const float*)d_in[2];
    const float* w_out = (const float*)d_in[3];
    const float* b_out = (const float*)d_in[4];
    float* out = (float*)d_out;

    float* qkv_buf = nullptr;
    float* att_buf = nullptr;
    cudaGetSymbolAddress((void**)&qkv_buf, g_qkv);
    cudaGetSymbolAddress((void**)&att_buf, g_att);

    const int attn_smem = (3 * 64 * QSTRIDE + 64 * 64) * (int)sizeof(float); // 68608
    cudaFuncSetAttribute(attn_kernel,
                         cudaFuncAttributeMaxDynamicSharedMemorySize, attn_smem);

    // 1) QKV = X @ Wqkv + b   -> (8192, 3072)
    gemm_bias_kernel<<<dim3(C3_ / BN, M_ / BM), 256>>>(
        x, w_qkv, b_qkv, qkv_buf, M_, C3_, C_);

    // 2) causal flash attention -> (8192, 1024) head-concat layout
    attn_kernel<<<dim3(T_ / 64, H_, B_), 256, attn_smem>>>(qkv_buf, att_buf);

    // 3) out = att @ Wout + b -> (8192, 1024)
    gemm_bias_kernel<<<dim3(C_ / BN, M_ / BM), 256>>>(
        att_buf, w_out, b_out, out, M_, C_, C_);
}

// round 6
// speedup vs baseline: 1.4469x; 1.4469x over previous
#include <cuda_runtime.h>
#include <cuda_bf16.h>
#include <cstdint>
#include <math.h>

// ---------------------------------------------------------------------------
// Problem:
//   x:      (4, 2048, 1024) f32
//   w_qkv:  (1024, 3072)    f32     b_qkv: (3072,) f32
//   w_out:  (1024, 1024)    f32     b_out: (1024,) f32
//   out:    (4, 2048, 1024) f32
// Pipeline:
//   split(x) -> bf16 hi/lo
//   transpose+split(W) -> Wt bf16 hi/lo   (mma wants B as [N][K] K-major)
//   GEMM1 (mma.sync bf16 3-term split): qkv = x @ Wqkv + b   (fp32 out)
//   flash attention (fp32 FFMA), epilogue writes bf16 hi/lo
//   GEMM2 (mma.sync): out = att @ Wout + b
// NOTE: tcgen05 is ptxas-rejected at this bench's compute_103 target; the
// tensor path here is legacy mma.sync (HMMA), which IS supported.
// ---------------------------------------------------------------------------
#define B_   4
#define T_   2048
#define C_   1024
#define H_   16
#define DH_  64
#define M_   (B_ * T_)       // 8192
#define C3_  (3 * C_)        // 3072

// Scratch (__device__ globals: allocation-free rule)
__device__ __nv_bfloat16 g_xhi[(size_t)M_ * C_];
__device__ __nv_bfloat16 g_xlo[(size_t)M_ * C_];
__device__ __nv_bfloat16 g_wqhi[(size_t)C3_ * C_];   // Wqkv^T [3072][1024]
__device__ __nv_bfloat16 g_wqlo[(size_t)C3_ * C_];
__device__ __nv_bfloat16 g_wohi[(size_t)C_ * C_];    // Wout^T [1024][1024]
__device__ __nv_bfloat16 g_wolo[(size_t)C_ * C_];
__device__ float         g_qkv[(size_t)M_ * C3_];    // fp32 qkv
__device__ __nv_bfloat16 g_ahi[(size_t)M_ * C_];     // attention out hi
__device__ __nv_bfloat16 g_alo[(size_t)M_ * C_];     // attention out lo

// ---------------------------------------------------------------------------
// PTX helpers (sm_80+ features only — safe at compute_103)
// ---------------------------------------------------------------------------
__device__ __forceinline__ uint32_t smem_u32(const void* p) {
    uint32_t a;
    asm("{ .reg .u64 t; cvta.to.shared.u64 t, %1; cvt.u32.u64 %0, t; }"
        : "=r"(a) : "l"(p));
    return a;
}

#define LDSM4(r0, r1, r2, r3, addr) \
    asm volatile("ldmatrix.sync.aligned.m8n8.x4.shared.b16 {%0,%1,%2,%3}, [%4];" \
        : "=r"(r0), "=r"(r1), "=r"(r2), "=r"(r3) : "r"(addr))

#define MMA16816(c, a, b) \
    asm volatile("mma.sync.aligned.m16n8k16.row.col.f32.bf16.bf16.f32 " \
        "{%0,%1,%2,%3}, {%4,%5,%6,%7}, {%8,%9}, {%0,%1,%2,%3};" \
        : "+f"((c)[0]), "+f"((c)[1]), "+f"((c)[2]), "+f"((c)[3]) \
        : "r"((a)[0]), "r"((a)[1]), "r"((a)[2]), "r"((a)[3]), \
          "r"((b)[0]), "r"((b)[1]))

#define CP_ASYNC16(dst, src) \
    asm volatile("cp.async.cg.shared.global [%0], [%1], 16;" :: "r"(dst), "l"(src))
#define CP_COMMIT() asm volatile("cp.async.commit_group;" ::: "memory")
#define CP_WAIT1()  asm volatile("cp.async.wait_group 1;" ::: "memory")
#define CP_WAIT0()  asm volatile("cp.async.wait_group 0;" ::: "memory")

// ---------------------------------------------------------------------------
// Prep kernels
// ---------------------------------------------------------------------------
__global__ __launch_bounds__(256) void split_kernel(
    const float* __restrict__ in, __nv_bfloat16* __restrict__ hi,
    __nv_bfloat16* __restrict__ lo, int n)
{
    int i = (blockIdx.x * 256 + threadIdx.x) * 4;
    if (i >= n) return;
    float4 v = *(const float4*)(in + i);
    __nv_bfloat16 h0 = __float2bfloat16(v.x), h1 = __float2bfloat16(v.y);
    __nv_bfloat16 h2 = __float2bfloat16(v.z), h3 = __float2bfloat16(v.w);
    __nv_bfloat162 ha; ha.x = h0; ha.y = h1;
    __nv_bfloat162 hb; hb.x = h2; hb.y = h3;
    *(__nv_bfloat162*)(hi + i)     = ha;
    *(__nv_bfloat162*)(hi + i + 2) = hb;
    __nv_bfloat162 la, lb;
    la.x = __float2bfloat16(v.x - __bfloat162float(h0));
    la.y = __float2bfloat16(v.y - __bfloat162float(h1));
    lb.x = __float2bfloat16(v.z - __bfloat162float(h2));
    lb.y = __float2bfloat16(v.w - __bfloat162float(h3));
    *(__nv_bfloat162*)(lo + i)     = la;
    *(__nv_bfloat162*)(lo + i + 2) = lb;
}

// w[K][N] -> t[N][K] with bf16 hi/lo split.  Block (32,8), grid (N/32, K/32).
__global__ __launch_bounds__(256) void transpose_split_kernel(
    const float* __restrict__ w, __nv_bfloat16* __restrict__ thi,
    __nv_bfloat16* __restrict__ tlo, int K, int N)
{
    __shared__ float tile[32][33];
    int n0 = blockIdx.x * 32, k0 = blockIdx.y * 32;
    int tx = threadIdx.x, ty = threadIdx.y;
#pragma unroll
    for (int j = 0; j < 32; j += 8)
        tile[ty + j][tx] = w[(size_t)(k0 + ty + j) * N + n0 + tx];
    __syncthreads();
#pragma unroll
    for (int j = 0; j < 32; j += 8) {
        float v = tile[tx][ty + j];
        __nv_bfloat16 h = __float2bfloat16(v);
        size_t idx = (size_t)(n0 + ty + j) * K + k0 + tx;
        thi[idx] = h;
        tlo[idx] = __float2bfloat16(v - __bfloat162float(h));
    }
}

// ---------------------------------------------------------------------------
// mma.sync GEMM:  C[M,N] = (Ahi+Alo)[M,K] @ (Bhi+Blo)[N,K]^T + bias
// 3-term split: hi*hi + hi*lo + lo*hi, fp32 accum.
// CTA tile 128x128, BK=32 bf16, 256 threads = 8 warps (2x4), warp tile 64x32.
// Smem: 2 stages x 4 tiles x 128 rows x 40 bf16 (stride 80B, ldmatrix
// conflict-free). cp.async double buffer.
// ---------------------------------------------------------------------------
#define KSTRIDE 40                       // bf16 elems per smem row
#define TILE_E  (128 * KSTRIDE)          // 5120 bf16 per tile
#define STAGE_E (4 * TILE_E)             // 20480 bf16 per stage
#define GEMM_SMEM (2 * STAGE_E * 2)      // 81920 bytes

__global__ __launch_bounds__(256, 1)
void gemm_mma_kernel(
    const __nv_bfloat16* __restrict__ Ahi, const __nv_bfloat16* __restrict__ Alo,
    const __nv_bfloat16* __restrict__ Bhi, const __nv_bfloat16* __restrict__ Blo,
    const float* __restrict__ bias, float* __restrict__ Cm, int N, int K)
{
    extern __shared__ __nv_bfloat16 smb[];
    const uint32_t sbase = smem_u32(smb);

    const int tid  = threadIdx.x;
    const int lane = tid & 31;
    const int wid  = tid >> 5;
    const int wm   = wid >> 2;           // 0..1  -> m offset wm*64
    const int wn   = wid & 3;            // 0..3  -> n offset wn*32
    const int bx = blockIdx.x, by = blockIdx.y;

    const __nv_bfloat16* srcs[4];
    srcs[0] = Ahi + (size_t)(by * 128) * K;
    srcs[1] = Alo + (size_t)(by * 128) * K;
    srcs[2] = Bhi + (size_t)(bx * 128) * K;
    srcs[3] = Blo + (size_t)(bx * 128) * K;

    float acc[4][4][4];
#pragma unroll
    for (int mi = 0; mi < 4; mi++)
#pragma unroll
        for (int nf = 0; nf < 4; nf++)
#pragma unroll
            for (int r = 0; r < 4; r++) acc[mi][nf][r] = 0.f;

    // ---- async stage loader: 4 tiles x 128 rows x 4 x16B chunks = 2048 ----
    auto load_stage = [&](int stage, int k0) {
#pragma unroll
        for (int i = 0; i < 8; i++) {
            int idx  = tid + i * 256;          // 0..2047
            int tile = idx >> 9;               // 0..3
            int r    = (idx >> 2) & 127;       // 0..127
            int c    = idx & 3;                // 0..3 (8 bf16 each)
            const __nv_bfloat16* g = srcs[tile] + (size_t)r * K + k0 + c * 8;
            uint32_t d = sbase +
                (uint32_t)(stage * STAGE_E + tile * TILE_E + r * KSTRIDE + c * 8) * 2;
            CP_ASYNC16(d, g);
        }
    };

    // ---- fragment compute on one stage ----
    auto compute = [&](int stage) {
        const uint32_t As_h = sbase + (uint32_t)(stage * STAGE_E) * 2;
        const uint32_t As_l = As_h + TILE_E * 2;
        const uint32_t Bs_h = As_h + 2 * TILE_E * 2;
        const uint32_t Bs_l = As_h + 3 * TILE_E * 2;

#pragma unroll
        for (int ks = 0; ks < 2; ks++) {
            uint32_t a_hi[4][4], a_lo[4][4];
            uint32_t b_hi[4][2], b_lo[4][2];

            // A frags: row = wm*64 + mi*16 + (lane&15), col = ks*16 + (lane>>4)*8
            const int ar = wm * 64 + (lane & 15);
            const int ac = ks * 16 + (lane >> 4) * 8;
#pragma unroll
            for (int mi = 0; mi < 4; mi++) {
                uint32_t off = (uint32_t)((ar + mi * 16) * KSTRIDE + ac) * 2;
                LDSM4(a_hi[mi][0], a_hi[mi][1], a_hi[mi][2], a_hi[mi][3], As_h + off);
                LDSM4(a_lo[mi][0], a_lo[mi][1], a_lo[mi][2], a_lo[mi][3], As_l + off);
            }
            // B frags: x4 covers 16 n-rows x k16.
            // row = nb + (lane>>4)*8 + (lane&7), col = ks*16 + ((lane>>3)&1)*8
            const int br = wn * 32 + ((lane >> 4) << 3) + (lane & 7);
            const int bc = ks * 16 + ((lane >> 3) & 1) * 8;
#pragma unroll
            for (int p = 0; p < 2; p++) {
                uint32_t off = (uint32_t)((br + p * 16) * KSTRIDE + bc) * 2;
                LDSM4(b_hi[2*p][0], b_hi[2*p][1], b_hi[2*p+1][0], b_hi[2*p+1][1],
                      Bs_h + off);
                LDSM4(b_lo[2*p][0], b_lo[2*p][1], b_lo[2*p+1][0], b_lo[2*p+1][1],
                      Bs_l + off);
            }
#pragma unroll
            for (int mi = 0; mi < 4; mi++)
#pragma unroll
                for (int nf = 0; nf < 4; nf++) {
                    MMA16816(acc[mi][nf], a_hi[mi], b_hi[nf]);
                    MMA16816(acc[mi][nf], a_hi[mi], b_lo[nf]);
                    MMA16816(acc[mi][nf], a_lo[mi], b_hi[nf]);
                }
        }
    };

    const int nch = K / 32;   // 32
    load_stage(0, 0);
    CP_COMMIT();
    for (int ch = 0; ch < nch; ch++) {
        if (ch + 1 < nch) {
            load_stage((ch + 1) & 1, (ch + 1) * 32);
            CP_COMMIT();
            CP_WAIT1();
        } else {
            CP_WAIT0();
        }
        __syncthreads();
        compute(ch & 1);
        __syncthreads();
    }

    // ---- epilogue: bias + store ----
#pragma unroll
    for (int nf = 0; nf < 4; nf++) {
        const int col = bx * 128 + wn * 32 + nf * 8 + (lane & 3) * 2;
        const float b0 = bias[col], b1 = bias[col + 1];
#pragma unroll
        for (int mi = 0; mi < 4; mi++) {
            const int r0 = by * 128 + wm * 64 + mi * 16 + (lane >> 2);
            float2 v0, v1;
            v0.x = acc[mi][nf][0] + b0;  v0.y = acc[mi][nf][1] + b1;
            v1.x = acc[mi][nf][2] + b0;  v1.y = acc[mi][nf][3] + b1;
            *(float2*)(Cm + (size_t)r0 * N + col)       = v0;
            *(float2*)(Cm + (size_t)(r0 + 8) * N + col) = v1;
        }
    }
}

// ---------------------------------------------------------------------------
// Flash attention (causal), fp32 FFMA. Epilogue writes bf16 hi/lo for GEMM2.
// Grid (T/64, H, B), block 256 = 16x16, 4x4 fragments.
// ---------------------------------------------------------------------------
#define QSTRIDE 68

__global__ __launch_bounds__(256) void attn_kernel(
    const float* __restrict__ qkv,
    __nv_bfloat16* __restrict__ ohi, __nv_bfloat16* __restrict__ olo)
{
    extern __shared__ float smf[];
    float* Qs = smf;
    float* Ks = Qs + 64 * QSTRIDE;
    float* Ps = Ks + 64 * QSTRIDE;
    float* Vs = Ps + 64 * QSTRIDE;

    const int qt = blockIdx.x;
    const int h  = blockIdx.y;
    const int b  = blockIdx.z;
    const int tid = threadIdx.x;
    const int tx = tid & 15;
    const int ty = tid >> 4;
    const int q0 = qt * 64;
    const float scale = 0.125f;

    const float* Qg = qkv + ((size_t)(b * T_ + q0)) * C3_ + h * DH_;
    for (int i = tid; i < 64 * 64; i += 256) {
        int pos = i >> 6, d = i & 63;
        Qs[d * QSTRIDE + pos] = Qg[(size_t)pos * C3_ + d] * scale;
    }

    float m_prev[4], l[4], o[4][4];
#pragma unroll
    for (int i = 0; i < 4; i++) {
        m_prev[i] = -1e30f; l[i] = 0.f;
#pragma unroll
        for (int j = 0; j < 4; j++) o[i][j] = 0.f;
    }

    for (int kt = 0; kt <= qt; kt++) {
        __syncthreads();
        const int k0 = kt * 64;
        const float* Kg = qkv + ((size_t)(b * T_ + k0)) * C3_ + C_ + h * DH_;
        const float* Vg = Kg + C_;
        for (int i = tid; i < 64 * 64; i += 256) {
            int pos = i >> 6, d = i & 63;
            Ks[d * QSTRIDE + pos] = Kg[(size_t)pos * C3_ + d];
            Vs[pos * 64 + d]      = Vg[(size_t)pos * C3_ + d];
        }
        __syncthreads();

        float s[4][4];
#pragma unroll
        for (int i = 0; i < 4; i++)
#pragma unroll
            for (int j = 0; j < 4; j++) s[i][j] = 0.f;

#pragma unroll 8
        for (int d = 0; d < 64; d++) {
            float4 av = *(const float4*)(&Qs[d * QSTRIDE + ty * 4]);
            float4 bv = *(const float4*)(&Ks[d * QSTRIDE + tx * 4]);
            float a[4] = {av.x, av.y, av.z, av.w};
            float bb[4] = {bv.x, bv.y, bv.z, bv.w};
#pragma unroll
            for (int i = 0; i < 4; i++)
#pragma unroll
                for (int j = 0; j < 4; j++)
                    s[i][j] += a[i] * bb[j];
        }

        if (kt == qt) {
#pragma unroll
            for (int i = 0; i < 4; i++)
#pragma unroll
                for (int j = 0; j < 4; j++)
                    if (tx * 4 + j > ty * 4 + i) s[i][j] = -1e30f;
        }

#pragma unroll
        for (int i = 0; i < 4; i++) {
            float mx = fmaxf(fmaxf(s[i][0], s[i][1]), fmaxf(s[i][2], s[i][3]));
            mx = fmaxf(mx, __shfl_xor_sync(0xffffffffu, mx, 1));
            mx = fmaxf(mx, __shfl_xor_sync(0xffffffffu, mx, 2));
            mx = fmaxf(mx, __shfl_xor_sync(0xffffffffu, mx, 4));
            mx = fmaxf(mx, __shfl_xor_sync(0xffffffffu, mx, 8));
            float nm = fmaxf(m_prev[i], mx);
            float corr = __expf(m_prev[i] - nm);
            float rs = 0.f;
#pragma unroll
            for (int j = 0; j < 4; j++) {
                float p = __expf(s[i][j] - nm);
                s[i][j] = p;
                rs += p;
            }
            rs += __shfl_xor_sync(0xffffffffu, rs, 1);
            rs += __shfl_xor_sync(0xffffffffu, rs, 2);
            rs += __shfl_xor_sync(0xffffffffu, rs, 4);
            rs += __shfl_xor_sync(0xffffffffu, rs, 8);
            l[i] = l[i] * corr + rs;
            m_prev[i] = nm;
#pragma unroll
            for (int j = 0; j < 4; j++) o[i][j] *= corr;
            *(float4*)(&Ps[(ty * 4 + i) * QSTRIDE + tx * 4]) =
                make_float4(s[i][0], s[i][1], s[i][2], s[i][3]);
        }
        __syncthreads();

#pragma unroll 8
        for (int kk = 0; kk < 64; kk++) {
            float4 vv = *(const float4*)(&Vs[kk * 64 + tx * 4]);
            float pv[4] = {vv.x, vv.y, vv.z, vv.w};
#pragma unroll
            for (int i = 0; i < 4; i++) {
                float pr = Ps[(ty * 4 + i) * QSTRIDE + kk];
#pragma unroll
                for (int j = 0; j < 4; j++)
                    o[i][j] += pr * pv[j];
            }
        }
    }

    // Epilogue: write bf16 hi/lo (feeds GEMM2's A operand)
    size_t base = ((size_t)(b * T_ + q0)) * C_ + h * DH_;
#pragma unroll
    for (int i = 0; i < 4; i++) {
        float inv = 1.f / l[i];
        float v0 = o[i][0] * inv, v1 = o[i][1] * inv;
        float v2 = o[i][2] * inv, v3 = o[i][3] * inv;
        __nv_bfloat16 h0 = __float2bfloat16(v0), h1 = __float2bfloat16(v1);
        __nv_bfloat16 h2 = __float2bfloat16(v2), h3 = __float2bfloat16(v3);
        size_t off = base + (size_t)(ty * 4 + i) * C_ + tx * 4;
        __nv_bfloat162 ha; ha.x = h0; ha.y = h1;
        __nv_bfloat162 hb; hb.x = h2; hb.y = h3;
        *(__nv_bfloat162*)(ohi + off)     = ha;
        *(__nv_bfloat162*)(ohi + off + 2) = hb;
        __nv_bfloat162 la, lb;
        la.x = __float2bfloat16(v0 - __bfloat162float(h0));
        la.y = __float2bfloat16(v1 - __bfloat162float(h1));
        lb.x = __float2bfloat16(v2 - __bfloat162float(h2));
        lb.y = __float2bfloat16(v3 - __bfloat162float(h3));
        *(__nv_bfloat162*)(olo + off)     = la;
        *(__nv_bfloat162*)(olo + off + 2) = lb;
    }
}

// ---------------------------------------------------------------------------
// Launch
// ---------------------------------------------------------------------------
extern "C" void kernel_launch(void* const* d_in, const int* in_sizes, int n_in,
                              void* d_out, int out_size)
{
    const float* x     = (const float*)d_in[0];
    const float* w_qkv = (const float*)d_in[1];
    const float* b_qkv = (const float*)d_in[2];
    const float* w_out = (const float*)d_in[3];
    const float* b_out = (const float*)d_in[4];
    float* out = (float*)d_out;

    __nv_bfloat16 *xhi, *xlo, *wqhi, *wqlo, *wohi, *wolo, *ahi, *alo;
    float* qkv;
    cudaGetSymbolAddress((void**)&xhi,  g_xhi);
    cudaGetSymbolAddress((void**)&xlo,  g_xlo);
    cudaGetSymbolAddress((void**)&wqhi, g_wqhi);
    cudaGetSymbolAddress((void**)&wqlo, g_wqlo);
    cudaGetSymbolAddress((void**)&wohi, g_wohi);
    cudaGetSymbolAddress((void**)&wolo, g_wolo);
    cudaGetSymbolAddress((void**)&ahi,  g_ahi);
    cudaGetSymbolAddress((void**)&alo,  g_alo);
    cudaGetSymbolAddress((void**)&qkv,  g_qkv);

    cudaFuncSetAttribute(gemm_mma_kernel,
                         cudaFuncAttributeMaxDynamicSharedMemorySize, GEMM_SMEM);
    const int attn_smem = (3 * 64 * QSTRIDE + 64 * 64) * (int)sizeof(float);
    cudaFuncSetAttribute(attn_kernel,
                         cudaFuncAttributeMaxDynamicSharedMemorySize, attn_smem);

    // prep: split x, transpose+split weights
    split_kernel<<<(M_ * C_) / 4 / 256, 256>>>(x, xhi, xlo, M_ * C_);
    transpose_split_kernel<<<dim3(C3_ / 32, C_ / 32), dim3(32, 8)>>>(
        w_qkv, wqhi, wqlo, C_, C3_);
    transpose_split_kernel<<<dim3(C_ / 32, C_ / 32), dim3(32, 8)>>>(
        w_out, wohi, wolo, C_, C_);

    // GEMM1: qkv = x @ Wqkv + b   (M=8192, N=3072, K=1024)
    gemm_mma_kernel<<<dim3(C3_ / 128, M_ / 128), 256, GEMM_SMEM>>>(
        xhi, xlo, wqhi, wqlo, b_qkv, qkv, C3_, C_);

    // attention -> bf16 hi/lo
    attn_kernel<<<dim3(T_ / 64, H_, B_), 256, attn_smem>>>(qkv, ahi, alo);

    // GEMM2: out = att @ Wout + b  (M=8192, N=1024, K=1024)
    gemm_mma_kernel<<<dim3(C_ / 128, M_ / 128), 256, GEMM_SMEM>>>(
        ahi, alo, wohi, wolo, b_out, out, C_, C_);
}

// round 8
// speedup vs baseline: 2.3507x; 1.6247x over previous
#include <cuda_runtime.h>
#include <cuda_bf16.h>
#include <cstdint>
#include <math.h>

// ---------------------------------------------------------------------------
// Problem:
//   x (4,2048,1024) f32; w_qkv (1024,3072); b_qkv (3072,);
//   w_out (1024,1024); b_out (1024,); out (4,2048,1024) f32
// Pipeline (all tensor work on mma.sync bf16 3-term hi/lo split):
//   split(x) -> bf16 hi/lo ; transpose+split(W)
//   GEMM1: qkv = x @ Wqkv + b  -> bf16 hi/lo  (qhi/qlo buffers)
//   flash attention, mma.sync, causal -> bf16 hi/lo (ahi/alo)
//   GEMM2: out = att @ Wout + b -> fp32
// ---------------------------------------------------------------------------
#define B_   4
#define T_   2048
#define C_   1024
#define H_   16
#define DH_  64
#define M_   (B_ * T_)       // 8192
#define C3_  (3 * C_)        // 3072

__device__ __nv_bfloat16 g_xhi[(size_t)M_ * C_];
__device__ __nv_bfloat16 g_xlo[(size_t)M_ * C_];
__device__ __nv_bfloat16 g_wqhi[(size_t)C3_ * C_];
__device__ __nv_bfloat16 g_wqlo[(size_t)C3_ * C_];
__device__ __nv_bfloat16 g_wohi[(size_t)C_ * C_];
__device__ __nv_bfloat16 g_wolo[(size_t)C_ * C_];
__device__ __nv_bfloat16 g_qhi[(size_t)M_ * C3_];   // qkv hi
__device__ __nv_bfloat16 g_qlo[(size_t)M_ * C3_];   // qkv lo
__device__ __nv_bfloat16 g_ahi[(size_t)M_ * C_];
__device__ __nv_bfloat16 g_alo[(size_t)M_ * C_];

// ---------------------------------------------------------------------------
__device__ __forceinline__ uint32_t smem_u32(const void* p) {
    uint32_t a;
    asm("{ .reg .u64 t; cvta.to.shared.u64 t, %1; cvt.u32.u64 %0, t; }"
        : "=r"(a) : "l"(p));
    return a;
}

#define LDSM4(r0, r1, r2, r3, addr) \
    asm volatile("ldmatrix.sync.aligned.m8n8.x4.shared.b16 {%0,%1,%2,%3}, [%4];" \
        : "=r"(r0), "=r"(r1), "=r"(r2), "=r"(r3) : "r"(addr))
#define LDSM4T(r0, r1, r2, r3, addr) \
    asm volatile("ldmatrix.sync.aligned.m8n8.x4.trans.shared.b16 {%0,%1,%2,%3}, [%4];" \
        : "=r"(r0), "=r"(r1), "=r"(r2), "=r"(r3) : "r"(addr))

#define MMAF(c, a, b0r, b1r) \
    asm volatile("mma.sync.aligned.m16n8k16.row.col.f32.bf16.bf16.f32 " \
        "{%0,%1,%2,%3}, {%4,%5,%6,%7}, {%8,%9}, {%0,%1,%2,%3};" \
        : "+f"((c)[0]), "+f"((c)[1]), "+f"((c)[2]), "+f"((c)[3]) \
        : "r"((a)[0]), "r"((a)[1]), "r"((a)[2]), "r"((a)[3]), \
          "r"(b0r), "r"(b1r))

#define CP_ASYNC16(dst, src) \
    asm volatile("cp.async.cg.shared.global [%0], [%1], 16;" :: "r"(dst), "l"(src))
#define CP_COMMIT() asm volatile("cp.async.commit_group;" ::: "memory")
#define CP_WAIT1()  asm volatile("cp.async.wait_group 1;" ::: "memory")
#define CP_WAIT0()  asm volatile("cp.async.wait_group 0;" ::: "memory")

// pack two floats -> bf16x2 hi reg + residual lo reg
__device__ __forceinline__ void pack2(float x, float y, uint32_t& hi, uint32_t& lo) {
    __nv_bfloat16 hx = __float2bfloat16(x), hy = __float2bfloat16(y);
    __nv_bfloat162 hh; hh.x = hx; hh.y = hy;
    hi = *reinterpret_cast<uint32_t*>(&hh);
    __nv_bfloat162 ll;
    ll.x = __float2bfloat16(x - __bfloat162float(hx));
    ll.y = __float2bfloat16(y - __bfloat162float(hy));
    lo = *reinterpret_cast<uint32_t*>(&ll);
}

// ---------------------------------------------------------------------------
// Prep kernels
// ---------------------------------------------------------------------------
__global__ __launch_bounds__(256) void split_kernel(
    const float* __restrict__ in, __nv_bfloat16* __restrict__ hi,
    __nv_bfloat16* __restrict__ lo, int n)
{
    int i = (blockIdx.x * 256 + threadIdx.x) * 4;
    if (i >= n) return;
    float4 v = *(const float4*)(in + i);
    uint32_t h0, l0, h1, l1;
    pack2(v.x, v.y, h0, l0);
    pack2(v.z, v.w, h1, l1);
    *(uint32_t*)(hi + i)     = h0;  *(uint32_t*)(hi + i + 2) = h1;
    *(uint32_t*)(lo + i)     = l0;  *(uint32_t*)(lo + i + 2) = l1;
}

__global__ __launch_bounds__(256) void transpose_split_kernel(
    const float* __restrict__ w, __nv_bfloat16* __restrict__ thi,
    __nv_bfloat16* __restrict__ tlo, int K, int N)
{
    __shared__ float tile[32][33];
    int n0 = blockIdx.x * 32, k0 = blockIdx.y * 32;
    int tx = threadIdx.x, ty = threadIdx.y;
#pragma unroll
    for (int j = 0; j < 32; j += 8)
        tile[ty + j][tx] = w[(size_t)(k0 + ty + j) * N + n0 + tx];
    __syncthreads();
#pragma unroll
    for (int j = 0; j < 32; j += 8) {
        float v = tile[tx][ty + j];
        __nv_bfloat16 h = __float2bfloat16(v);
        size_t idx = (size_t)(n0 + ty + j) * K + k0 + tx;
        thi[idx] = h;
        tlo[idx] = __float2bfloat16(v - __bfloat162float(h));
    }
}

// ---------------------------------------------------------------------------
// mma.sync GEMM: C = (Ahi+Alo) @ (Bhi+Blo)^T + bias
// Output either fp32 (Cf) or bf16 hi/lo split (Chi/Clo).
// ---------------------------------------------------------------------------
#define KSTRIDE 40
#define TILE_E  (128 * KSTRIDE)
#define STAGE_E (4 * TILE_E)
#define GEMM_SMEM (2 * STAGE_E * 2)      // 81920 B

__global__ __launch_bounds__(256, 1)
void gemm_mma_kernel(
    const __nv_bfloat16* __restrict__ Ahi, const __nv_bfloat16* __restrict__ Alo,
    const __nv_bfloat16* __restrict__ Bhi, const __nv_bfloat16* __restrict__ Blo,
    const float* __restrict__ bias,
    float* __restrict__ Cf,
    __nv_bfloat16* __restrict__ Chi, __nv_bfloat16* __restrict__ Clo,
    int N, int K)
{
    extern __shared__ __nv_bfloat16 smb[];
    const uint32_t sbase = smem_u32(smb);

    const int tid  = threadIdx.x;
    const int lane = tid & 31;
    const int wid  = tid >> 5;
    const int wm   = wid >> 2;
    const int wn   = wid & 3;
    const int bx = blockIdx.x, by = blockIdx.y;

    const __nv_bfloat16* srcs[4];
    srcs[0] = Ahi + (size_t)(by * 128) * K;
    srcs[1] = Alo + (size_t)(by * 128) * K;
    srcs[2] = Bhi + (size_t)(bx * 128) * K;
    srcs[3] = Blo + (size_t)(bx * 128) * K;

    float acc[4][4][4];
#pragma unroll
    for (int mi = 0; mi < 4; mi++)
#pragma unroll
        for (int nf = 0; nf < 4; nf++)
#pragma unroll
            for (int r = 0; r < 4; r++) acc[mi][nf][r] = 0.f;

    auto load_stage = [&](int stage, int k0) {
#pragma unroll
        for (int i = 0; i < 8; i++) {
            int idx  = tid + i * 256;
            int tile = idx >> 9;
            int r    = (idx >> 2) & 127;
            int c    = idx & 3;
            const __nv_bfloat16* g = srcs[tile] + (size_t)r * K + k0 + c * 8;
            uint32_t d = sbase +
                (uint32_t)(stage * STAGE_E + tile * TILE_E + r * KSTRIDE + c * 8) * 2;
            CP_ASYNC16(d, g);
        }
    };

    auto compute = [&](int stage) {
        const uint32_t As_h = sbase + (uint32_t)(stage * STAGE_E) * 2;
        const uint32_t As_l = As_h + TILE_E * 2;
        const uint32_t Bs_h = As_h + 2 * TILE_E * 2;
        const uint32_t Bs_l = As_h + 3 * TILE_E * 2;
#pragma unroll
        for (int ks = 0; ks < 2; ks++) {
            uint32_t a_hi[4][4], a_lo[4][4];
            uint32_t b_hi[4][2], b_lo[4][2];
            const int ar = wm * 64 + (lane & 15);
            const int ac = ks * 16 + (lane >> 4) * 8;
#pragma unroll
            for (int mi = 0; mi < 4; mi++) {
                uint32_t off = (uint32_t)((ar + mi * 16) * KSTRIDE + ac) * 2;
                LDSM4(a_hi[mi][0], a_hi[mi][1], a_hi[mi][2], a_hi[mi][3], As_h + off);
                LDSM4(a_lo[mi][0], a_lo[mi][1], a_lo[mi][2], a_lo[mi][3], As_l + off);
            }
            const int br = wn * 32 + ((lane >> 4) << 3) + (lane & 7);
            const int bc = ks * 16 + ((lane >> 3) & 1) * 8;
#pragma unroll
            for (int p = 0; p < 2; p++) {
                uint32_t off = (uint32_t)((br + p * 16) * KSTRIDE + bc) * 2;
                LDSM4(b_hi[2*p][0], b_hi[2*p][1], b_hi[2*p+1][0], b_hi[2*p+1][1],
                      Bs_h + off);
                LDSM4(b_lo[2*p][0], b_lo[2*p][1], b_lo[2*p+1][0], b_lo[2*p+1][1],
                      Bs_l + off);
            }
#pragma unroll
            for (int mi = 0; mi < 4; mi++)
#pragma unroll
                for (int nf = 0; nf < 4; nf++) {
                    MMAF(acc[mi][nf], a_hi[mi], b_hi[nf][0], b_hi[nf][1]);
                    MMAF(acc[mi][nf], a_hi[mi], b_lo[nf][0], b_lo[nf][1]);
                    MMAF(acc[mi][nf], a_lo[mi], b_hi[nf][0], b_hi[nf][1]);
                }
        }
    };

    const int nch = K / 32;
    load_stage(0, 0);
    CP_COMMIT();
    for (int ch = 0; ch < nch; ch++) {
        if (ch + 1 < nch) {
            load_stage((ch + 1) & 1, (ch + 1) * 32);
            CP_COMMIT();
            CP_WAIT1();
        } else {
            CP_WAIT0();
        }
        __syncthreads();
        compute(ch & 1);
        __syncthreads();
    }

#pragma unroll
    for (int nf = 0; nf < 4; nf++) {
        const int col = bx * 128 + wn * 32 + nf * 8 + (lane & 3) * 2;
        const float b0 = bias[col], b1 = bias[col + 1];
#pragma unroll
        for (int mi = 0; mi < 4; mi++) {
            const int r0 = by * 128 + wm * 64 + mi * 16 + (lane >> 2);
            float v0 = acc[mi][nf][0] + b0, v1 = acc[mi][nf][1] + b1;
            float v2 = acc[mi][nf][2] + b0, v3 = acc[mi][nf][3] + b1;
            if (Cf) {
                float2 w0; w0.x = v0; w0.y = v1;
                float2 w1; w1.x = v2; w1.y = v3;
                *(float2*)(Cf + (size_t)r0 * N + col)       = w0;
                *(float2*)(Cf + (size_t)(r0 + 8) * N + col) = w1;
            } else {
                uint32_t h0, l0, h1, l1;
                pack2(v0, v1, h0, l0);
                pack2(v2, v3, h1, l1);
                *(uint32_t*)(Chi + (size_t)r0 * N + col)       = h0;
                *(uint32_t*)(Clo + (size_t)r0 * N + col)       = l0;
                *(uint32_t*)(Chi + (size_t)(r0 + 8) * N + col) = h1;
                *(uint32_t*)(Clo + (size_t)(r0 + 8) * N + col) = l1;
            }
        }
    }
}

// ---------------------------------------------------------------------------
// Flash attention, mma.sync bf16 3-term split, causal.
// CTA: 128 q-rows x (b,h); 8 warps, warp w owns q-rows w*16..w*16+15.
// K-tiles of 64 keys, double-buffered cp.async.
// ---------------------------------------------------------------------------
#define ASTR 72
#define KVT_B (64 * ASTR * 2)       // 9216 B per tile
#define ASTAGE_B (4 * KVT_B)        // 36864 B
#define Q_OFF ASTAGE_B
#define ATTN_SMEM (2 * ASTAGE_B)    // 73728 B

__global__ __launch_bounds__(256)
void attn_mma_kernel(
    const __nv_bfloat16* __restrict__ qhi, const __nv_bfloat16* __restrict__ qlo,
    __nv_bfloat16* __restrict__ ohi, __nv_bfloat16* __restrict__ olo)
{
    extern __shared__ char sma[];
    const uint32_t sb = smem_u32(sma);

    const int tid  = threadIdx.x;
    const int lane = tid & 31;
    const int w    = tid >> 5;
    const int qt = (int)gridDim.x - 1 - blockIdx.x;   // heavy tiles first
    const int h  = blockIdx.y;
    const int b  = blockIdx.z;
    const int q0 = qt * 128;
    const float scale = 0.125f;

    const __nv_bfloat16* qsrc[2] = {qhi, qlo};

    auto load_kv = [&](int stage, int kt) {
        const int k0 = kt * 64;
#pragma unroll
        for (int i = 0; i < 8; i++) {
            int idx  = tid + i * 256;            // 0..2047
            int tile = idx >> 9;                 // 0:Khi 1:Klo 2:Vhi 3:Vlo
            int r    = (idx >> 3) & 63;
            int c    = idx & 7;
            int colb = (tile < 2) ? C_ : 2 * C_;
            const __nv_bfloat16* g = qsrc[tile & 1] +
                (size_t)(b * T_ + k0 + r) * C3_ + colb + h * DH_ + c * 8;
            uint32_t d = sb + stage * ASTAGE_B + tile * KVT_B +
                         (uint32_t)(r * ASTR + c * 8) * 2;
            CP_ASYNC16(d, g);
        }
    };

    // ---- prologue: Q into smem (stage-1 region), then to registers ----
#pragma unroll
    for (int i = 0; i < 8; i++) {
        int idx = tid + i * 256;                 // 0..2047
        int t   = idx >> 10;                     // 0:hi 1:lo
        int r   = (idx >> 3) & 127;
        int c   = idx & 7;
        const __nv_bfloat16* g = qsrc[t] +
            (size_t)(b * T_ + q0 + r) * C3_ + h * DH_ + c * 8;
        uint32_t d = sb + Q_OFF + t * (128 * ASTR * 2) +
                     (uint32_t)(r * ASTR + c * 8) * 2;
        CP_ASYNC16(d, g);
    }
    CP_COMMIT();
    load_kv(0, 0);
    CP_COMMIT();
    CP_WAIT1();              // Q arrived (oldest group)
    __syncthreads();

    uint32_t qf_h[4][4], qf_l[4][4];
    {
        const int r = w * 16 + (lane & 15);
        const int cb = (lane >> 4) * 8;
#pragma unroll
        for (int kf = 0; kf < 4; kf++) {
            uint32_t off = sb + Q_OFF + (uint32_t)(r * ASTR + kf * 16 + cb) * 2;
            LDSM4(qf_h[kf][0], qf_h[kf][1], qf_h[kf][2], qf_h[kf][3], off);
            LDSM4(qf_l[kf][0], qf_l[kf][1], qf_l[kf][2], qf_l[kf][3],
                  off + 128 * ASTR * 2);
        }
    }
    __syncthreads();         // Q region now reusable as stage 1

    float oacc[8][4];
#pragma unroll
    for (int nf = 0; nf < 8; nf++)
#pragma unroll
        for (int r = 0; r < 4; r++) oacc[nf][r] = 0.f;
    float m0 = -1e30f, m1 = -1e30f, l0 = 0.f, l1 = 0.f;

    const int nkt = 2 * qt + 2;
    for (int kt = 0; kt < nkt; kt++) {
        const int s = kt & 1;
        if (kt + 1 < nkt) { load_kv(s ^ 1, kt + 1); CP_COMMIT(); CP_WAIT1(); }
        else              { CP_WAIT0(); }
        __syncthreads();

        const uint32_t kb_h = sb + s * ASTAGE_B;
        const uint32_t kb_l = kb_h + KVT_B;
        const uint32_t vb_h = kb_h + 2 * KVT_B;
        const uint32_t vb_l = kb_h + 3 * KVT_B;

        // ---- S = Q K^T ----
        float sfr[8][4];
#pragma unroll
        for (int nf = 0; nf < 8; nf++)
#pragma unroll
            for (int r = 0; r < 4; r++) sfr[nf][r] = 0.f;

#pragma unroll
        for (int kf = 0; kf < 4; kf++) {
            uint32_t bh[4][4], bl[4][4];
            const int rr = (lane >> 4) * 8 + (lane & 7);
            const int cc = kf * 16 + ((lane >> 3) & 1) * 8;
#pragma unroll
            for (int p = 0; p < 4; p++) {
                uint32_t off = (uint32_t)((p * 16 + rr) * ASTR + cc) * 2;
                LDSM4(bh[p][0], bh[p][1], bh[p][2], bh[p][3], kb_h + off);
                LDSM4(bl[p][0], bl[p][1], bl[p][2], bl[p][3], kb_l + off);
            }
#pragma unroll
            for (int nf = 0; nf < 8; nf++) {
                uint32_t bh0 = bh[nf >> 1][(nf & 1) * 2];
                uint32_t bh1 = bh[nf >> 1][(nf & 1) * 2 + 1];
                uint32_t bl0 = bl[nf >> 1][(nf & 1) * 2];
                uint32_t bl1 = bl[nf >> 1][(nf & 1) * 2 + 1];
                MMAF(sfr[nf], qf_h[kf], bh0, bh1);
                MMAF(sfr[nf], qf_h[kf], bl0, bl1);
                MMAF(sfr[nf], qf_l[kf], bh0, bh1);
            }
        }

#pragma unroll
        for (int nf = 0; nf < 8; nf++)
#pragma unroll
            for (int r = 0; r < 4; r++) sfr[nf][r] *= scale;

        // ---- causal mask (last two k-tiles only) ----
        if (kt >= 2 * qt) {
            const int k0 = kt * 64;
            const int r0g = q0 + w * 16 + (lane >> 2);
            const int r1g = r0g + 8;
#pragma unroll
            for (int nf = 0; nf < 8; nf++) {
                const int c0 = k0 + nf * 8 + (lane & 3) * 2;
                if (c0     > r0g) sfr[nf][0] = -1e30f;
                if (c0 + 1 > r0g) sfr[nf][1] = -1e30f;
                if (c0     > r1g) sfr[nf][2] = -1e30f;
                if (c0 + 1 > r1g) sfr[nf][3] = -1e30f;
            }
        }

        // ---- online softmax (rows are quad-local: shfl over lanes^1,^2) ----
        float mx0 = -1e30f, mx1 = -1e30f;
#pragma unroll
        for (int nf = 0; nf < 8; nf++) {
            mx0 = fmaxf(mx0, fmaxf(sfr[nf][0], sfr[nf][1]));
            mx1 = fmaxf(mx1, fmaxf(sfr[nf][2], sfr[nf][3]));
        }
        mx0 = fmaxf(mx0, __shfl_xor_sync(0xffffffffu, mx0, 1));
        mx0 = fmaxf(mx0, __shfl_xor_sync(0xffffffffu, mx0, 2));
        mx1 = fmaxf(mx1, __shfl_xor_sync(0xffffffffu, mx1, 1));
        mx1 = fmaxf(mx1, __shfl_xor_sync(0xffffffffu, mx1, 2));
        const float nm0 = fmaxf(m0, mx0), nm1 = fmaxf(m1, mx1);
        const float corr0 = __expf(m0 - nm0), corr1 = __expf(m1 - nm1);
        float rs0 = 0.f, rs1 = 0.f;
#pragma unroll
        for (int nf = 0; nf < 8; nf++) {
            sfr[nf][0] = __expf(sfr[nf][0] - nm0);
            sfr[nf][1] = __expf(sfr[nf][1] - nm0);
            sfr[nf][2] = __expf(sfr[nf][2] - nm1);
            sfr[nf][3] = __expf(sfr[nf][3] - nm1);
            rs0 += sfr[nf][0] + sfr[nf][1];
            rs1 += sfr[nf][2] + sfr[nf][3];
        }
        rs0 += __shfl_xor_sync(0xffffffffu, rs0, 1);
        rs0 += __shfl_xor_sync(0xffffffffu, rs0, 2);
        rs1 += __shfl_xor_sync(0xffffffffu, rs1, 1);
        rs1 += __shfl_xor_sync(0xffffffffu, rs1, 2);
        l0 = l0 * corr0 + rs0;  m0 = nm0;
        l1 = l1 * corr1 + rs1;  m1 = nm1;
#pragma unroll
        for (int nf = 0; nf < 8; nf++) {
            oacc[nf][0] *= corr0;  oacc[nf][1] *= corr0;
            oacc[nf][2] *= corr1;  oacc[nf][3] *= corr1;
        }

        // ---- repack P (S C-frags -> A-frags, registers only) ----
        // A-frag order: a0=rows0-7/k0-7, a1=rows8-15/k0-7,
        //               a2=rows0-7/k8-15, a3=rows8-15/k8-15
        // => pa[kf] = { sfr[2kf][0,1], sfr[2kf][2,3],
        //               sfr[2kf+1][0,1], sfr[2kf+1][2,3] }
        uint32_t pa_h[4][4], pa_l[4][4];
#pragma unroll
        for (int kf = 0; kf < 4; kf++) {
            pack2(sfr[2*kf  ][0], sfr[2*kf  ][1], pa_h[kf][0], pa_l[kf][0]);
            pack2(sfr[2*kf  ][2], sfr[2*kf  ][3], pa_h[kf][1], pa_l[kf][1]);
            pack2(sfr[2*kf+1][0], sfr[2*kf+1][1], pa_h[kf][2], pa_l[kf][2]);
            pack2(sfr[2*kf+1][2], sfr[2*kf+1][3], pa_h[kf][3], pa_l[kf][3]);
        }

        // ---- O += P V  (V consumed via ldmatrix.trans from [key][d]) ----
#pragma unroll
        for (int kf = 0; kf < 4; kf++) {
            uint32_t vh[4][4], vl[4][4];
            const int rr = kf * 16 + (lane & 7) + ((lane >> 3) & 1) * 8;
            const int cc = (lane >> 4) * 8;
#pragma unroll
            for (int p = 0; p < 4; p++) {
                uint32_t off = (uint32_t)(rr * ASTR + p * 16 + cc) * 2;
                LDSM4T(vh[p][0], vh[p][1], vh[p][2], vh[p][3], vb_h + off);
                LDSM4T(vl[p][0], vl[p][1], vl[p][2], vl[p][3], vb_l + off);
            }
#pragma unroll
            for (int nf = 0; nf < 8; nf++) {
                uint32_t bh0 = vh[nf >> 1][(nf & 1) * 2];
                uint32_t bh1 = vh[nf >> 1][(nf & 1) * 2 + 1];
                uint32_t bl0 = vl[nf >> 1][(nf & 1) * 2];
                uint32_t bl1 = vl[nf >> 1][(nf & 1) * 2 + 1];
                MMAF(oacc[nf], pa_h[kf], bh0, bh1);
                MMAF(oacc[nf], pa_h[kf], bl0, bl1);
                MMAF(oacc[nf], pa_l[kf], bh0, bh1);
            }
        }
        __syncthreads();   // all warps done with stage s before next overwrite
    }

    // ---- epilogue: O/l -> bf16 hi/lo ----
    const float inv0 = 1.f / l0, inv1 = 1.f / l1;
    const int r0g = q0 + w * 16 + (lane >> 2);
#pragma unroll
    for (int nf = 0; nf < 8; nf++) {
        const int col = h * DH_ + nf * 8 + (lane & 3) * 2;
        uint32_t h0, lo0, h1, lo1;
        pack2(oacc[nf][0] * inv0, oacc[nf][1] * inv0, h0, lo0);
        pack2(oacc[nf][2] * inv1, oacc[nf][3] * inv1, h1, lo1);
        size_t a0 = (size_t)(b * T_ + r0g) * C_ + col;
        size_t a1 = a0 + (size_t)8 * C_;
        *(uint32_t*)(ohi + a0) = h0;   *(uint32_t*)(olo + a0) = lo0;
        *(uint32_t*)(ohi + a1) = h1;   *(uint32_t*)(olo + a1) = lo1;
    }
}

// ---------------------------------------------------------------------------
// Launch
// ---------------------------------------------------------------------------
extern "C" void kernel_launch(void* const* d_in, const int* in_sizes, int n_in,
                              void* d_out, int out_size)
{
    const float* x     = (const float*)d_in[0];
    const float* w_qkv = (const float*)d_in[1];
    const float* b_qkv = (const float*)d_in[2];
    const float* w_out = (const float*)d_in[3];
    const float* b_out = (const float*)d_in[4];
    float* out = (float*)d_out;

    __nv_bfloat16 *xhi, *xlo, *wqhi, *wqlo, *wohi, *wolo, *qhi, *qlo, *ahi, *alo;
    cudaGetSymbolAddress((void**)&xhi,  g_xhi);
    cudaGetSymbolAddress((void**)&xlo,  g_xlo);
    cudaGetSymbolAddress((void**)&wqhi, g_wqhi);
    cudaGetSymbolAddress((void**)&wqlo, g_wqlo);
    cudaGetSymbolAddress((void**)&wohi, g_wohi);
    cudaGetSymbolAddress((void**)&wolo, g_wolo);
    cudaGetSymbolAddress((void**)&qhi,  g_qhi);
    cudaGetSymbolAddress((void**)&qlo,  g_qlo);
    cudaGetSymbolAddress((void**)&ahi,  g_ahi);
    cudaGetSymbolAddress((void**)&alo,  g_alo);

    cudaFuncSetAttribute(gemm_mma_kernel,
                         cudaFuncAttributeMaxDynamicSharedMemorySize, GEMM_SMEM);
    cudaFuncSetAttribute(attn_mma_kernel,
                         cudaFuncAttributeMaxDynamicSharedMemorySize, ATTN_SMEM);

    split_kernel<<<(M_ * C_) / 4 / 256, 256>>>(x, xhi, xlo, M_ * C_);
    transpose_split_kernel<<<dim3(C3_ / 32, C_ / 32), dim3(32, 8)>>>(
        w_qkv, wqhi, wqlo, C_, C3_);
    transpose_split_kernel<<<dim3(C_ / 32, C_ / 32), dim3(32, 8)>>>(
        w_out, wohi, wolo, C_, C_);

    // GEMM1: qkv = x @ Wqkv + b  -> bf16 hi/lo
    gemm_mma_kernel<<<dim3(C3_ / 128, M_ / 128), 256, GEMM_SMEM>>>(
        xhi, xlo, wqhi, wqlo, b_qkv, nullptr, qhi, qlo, C3_, C_);

    // attention (mma.sync) -> bf16 hi/lo
    attn_mma_kernel<<<dim3(T_ / 128, H_, B_), 256, ATTN_SMEM>>>(
        qhi, qlo, ahi, alo);

    // GEMM2: out = att @ Wout + b -> fp32
    gemm_mma_kernel<<<dim3(C_ / 128, M_ / 128), 256, GEMM_SMEM>>>(
        ahi, alo, wohi, wolo, b_out, out, nullptr, nullptr, C_, C_);
}

// round 9
// speedup vs baseline: 2.3827x; 1.0136x over previous
#include <cuda_runtime.h>
#include <cuda_bf16.h>
#include <cstdint>
#include <math.h>

// ---------------------------------------------------------------------------
// Problem:
//   x (4,2048,1024) f32; w_qkv (1024,3072); b_qkv (3072,);
//   w_out (1024,1024); b_out (1024,); out (4,2048,1024) f32
// Pipeline (all tensor work on mma.sync bf16 3-term hi/lo split):
//   split(x) -> bf16 hi/lo ; transpose+split(W)
//   GEMM1: qkv = x @ Wqkv + b  -> bf16 hi/lo  (qhi/qlo buffers)
//   flash attention, mma.sync, causal -> bf16 hi/lo (ahi/alo)
//   GEMM2: out = att @ Wout + b -> fp32
// GEMM tile 128x64, 2 CTAs/SM (occupancy was the round-8 bottleneck).
// ---------------------------------------------------------------------------
#define B_   4
#define T_   2048
#define C_   1024
#define H_   16
#define DH_  64
#define M_   (B_ * T_)       // 8192
#define C3_  (3 * C_)        // 3072

__device__ __nv_bfloat16 g_xhi[(size_t)M_ * C_];
__device__ __nv_bfloat16 g_xlo[(size_t)M_ * C_];
__device__ __nv_bfloat16 g_wqhi[(size_t)C3_ * C_];
__device__ __nv_bfloat16 g_wqlo[(size_t)C3_ * C_];
__device__ __nv_bfloat16 g_wohi[(size_t)C_ * C_];
__device__ __nv_bfloat16 g_wolo[(size_t)C_ * C_];
__device__ __nv_bfloat16 g_qhi[(size_t)M_ * C3_];   // qkv hi
__device__ __nv_bfloat16 g_qlo[(size_t)M_ * C3_];   // qkv lo
__device__ __nv_bfloat16 g_ahi[(size_t)M_ * C_];
__device__ __nv_bfloat16 g_alo[(size_t)M_ * C_];

// ---------------------------------------------------------------------------
__device__ __forceinline__ uint32_t smem_u32(const void* p) {
    uint32_t a;
    asm("{ .reg .u64 t; cvta.to.shared.u64 t, %1; cvt.u32.u64 %0, t; }"
        : "=r"(a) : "l"(p));
    return a;
}

#define LDSM4(r0, r1, r2, r3, addr) \
    asm volatile("ldmatrix.sync.aligned.m8n8.x4.shared.b16 {%0,%1,%2,%3}, [%4];" \
        : "=r"(r0), "=r"(r1), "=r"(r2), "=r"(r3) : "r"(addr))
#define LDSM4T(r0, r1, r2, r3, addr) \
    asm volatile("ldmatrix.sync.aligned.m8n8.x4.trans.shared.b16 {%0,%1,%2,%3}, [%4];" \
        : "=r"(r0), "=r"(r1), "=r"(r2), "=r"(r3) : "r"(addr))

#define MMAF(c, a, b0r, b1r) \
    asm volatile("mma.sync.aligned.m16n8k16.row.col.f32.bf16.bf16.f32 " \
        "{%0,%1,%2,%3}, {%4,%5,%6,%7}, {%8,%9}, {%0,%1,%2,%3};" \
        : "+f"((c)[0]), "+f"((c)[1]), "+f"((c)[2]), "+f"((c)[3]) \
        : "r"((a)[0]), "r"((a)[1]), "r"((a)[2]), "r"((a)[3]), \
          "r"(b0r), "r"(b1r))

#define CP_ASYNC16(dst, src) \
    asm volatile("cp.async.cg.shared.global [%0], [%1], 16;" :: "r"(dst), "l"(src))
#define CP_COMMIT() asm volatile("cp.async.commit_group;" ::: "memory")
#define CP_WAIT1()  asm volatile("cp.async.wait_group 1;" ::: "memory")
#define CP_WAIT0()  asm volatile("cp.async.wait_group 0;" ::: "memory")

// pack two floats -> bf16x2 hi reg + residual lo reg
__device__ __forceinline__ void pack2(float x, float y, uint32_t& hi, uint32_t& lo) {
    __nv_bfloat16 hx = __float2bfloat16(x), hy = __float2bfloat16(y);
    __nv_bfloat162 hh; hh.x = hx; hh.y = hy;
    hi = *reinterpret_cast<uint32_t*>(&hh);
    __nv_bfloat162 ll;
    ll.x = __float2bfloat16(x - __bfloat162float(hx));
    ll.y = __float2bfloat16(y - __bfloat162float(hy));
    lo = *reinterpret_cast<uint32_t*>(&ll);
}

// ---------------------------------------------------------------------------
// Prep kernels
// ---------------------------------------------------------------------------
__global__ __launch_bounds__(256) void split_kernel(
    const float* __restrict__ in, __nv_bfloat16* __restrict__ hi,
    __nv_bfloat16* __restrict__ lo, int n)
{
    int i = (blockIdx.x * 256 + threadIdx.x) * 4;
    if (i >= n) return;
    float4 v = *(const float4*)(in + i);
    uint32_t h0, l0, h1, l1;
    pack2(v.x, v.y, h0, l0);
    pack2(v.z, v.w, h1, l1);
    *(uint32_t*)(hi + i)     = h0;  *(uint32_t*)(hi + i + 2) = h1;
    *(uint32_t*)(lo + i)     = l0;  *(uint32_t*)(lo + i + 2) = l1;
}

__global__ __launch_bounds__(256) void transpose_split_kernel(
    const float* __restrict__ w, __nv_bfloat16* __restrict__ thi,
    __nv_bfloat16* __restrict__ tlo, int K, int N)
{
    __shared__ float tile[32][33];
    int n0 = blockIdx.x * 32, k0 = blockIdx.y * 32;
    int tx = threadIdx.x, ty = threadIdx.y;
#pragma unroll
    for (int j = 0; j < 32; j += 8)
        tile[ty + j][tx] = w[(size_t)(k0 + ty + j) * N + n0 + tx];
    __syncthreads();
#pragma unroll
    for (int j = 0; j < 32; j += 8) {
        float v = tile[tx][ty + j];
        __nv_bfloat16 h = __float2bfloat16(v);
        size_t idx = (size_t)(n0 + ty + j) * K + k0 + tx;
        thi[idx] = h;
        tlo[idx] = __float2bfloat16(v - __bfloat162float(h));
    }
}

// ---------------------------------------------------------------------------
// mma.sync GEMM: C = (Ahi+Alo) @ (Bhi+Blo)^T + bias
// CTA tile 128x64, BK=32, 8 warps (2x4), warp tile 64x16.
// 2-stage cp.async pipeline, 2 CTAs/SM.
// Smem per stage (elems, KSTRIDE=40): Ahi[128][40] @0, Alo @5120,
// Bhi[64][40] @10240, Blo @12800; stage span 15360 elems (30720 B).
// ---------------------------------------------------------------------------
#define KSTRIDE 40
#define G_ATILE (128 * KSTRIDE)          // 5120 elems
#define G_BTILE (64 * KSTRIDE)           // 2560 elems
#define G_STAGE (2 * G_ATILE + 2 * G_BTILE)   // 15360 elems
#define GEMM_SMEM (2 * G_STAGE * 2)      // 61440 B

__global__ __launch_bounds__(256, 2)
void gemm_mma_kernel(
    const __nv_bfloat16* __restrict__ Ahi, const __nv_bfloat16* __restrict__ Alo,
    const __nv_bfloat16* __restrict__ Bhi, const __nv_bfloat16* __restrict__ Blo,
    const float* __restrict__ bias,
    float* __restrict__ Cf,
    __nv_bfloat16* __restrict__ Chi, __nv_bfloat16* __restrict__ Clo,
    int N, int K)
{
    extern __shared__ __nv_bfloat16 smb[];
    const uint32_t sbase = smem_u32(smb);

    const int tid  = threadIdx.x;
    const int lane = tid & 31;
    const int wid  = tid >> 5;
    const int wm   = wid >> 2;           // 0..1 -> m offset wm*64
    const int wn   = wid & 3;            // 0..3 -> n offset wn*16
    const int bx = blockIdx.x, by = blockIdx.y;

    const __nv_bfloat16* srcs[4];
    srcs[0] = Ahi + (size_t)(by * 128) * K;   // 128 rows
    srcs[1] = Alo + (size_t)(by * 128) * K;   // 128 rows
    srcs[2] = Bhi + (size_t)(bx * 64) * K;    // 64 rows
    srcs[3] = Blo + (size_t)(bx * 64) * K;    // 64 rows
    const uint32_t tbase[4] = {0, G_ATILE, 2 * G_ATILE, 2 * G_ATILE + G_BTILE};

    float acc[4][2][4];
#pragma unroll
    for (int mi = 0; mi < 4; mi++)
#pragma unroll
        for (int nf = 0; nf < 2; nf++)
#pragma unroll
            for (int r = 0; r < 4; r++) acc[mi][nf][r] = 0.f;

    // 1536 x16B chunks per stage, 6 per thread
    auto load_stage = [&](int stage, int k0) {
#pragma unroll
        for (int i = 0; i < 6; i++) {
            int idx = tid + i * 256;           // 0..1535
            int tile, r;
            if (idx < 1024) { tile = idx >> 9;              r = (idx >> 2) & 127; }
            else            { tile = 2 + ((idx - 1024) >> 8); r = ((idx - 1024) >> 2) & 63; }
            int c = idx & 3;                   // 16B chunk within 32-elem row
            const __nv_bfloat16* g = srcs[tile] + (size_t)r * K + k0 + c * 8;
            uint32_t d = sbase +
                (uint32_t)(stage * G_STAGE + tbase[tile] + r * KSTRIDE + c * 8) * 2;
            CP_ASYNC16(d, g);
        }
    };

    auto compute = [&](int stage) {
        const uint32_t As_h = sbase + (uint32_t)(stage * G_STAGE) * 2;
        const uint32_t As_l = As_h + G_ATILE * 2;
        const uint32_t Bs_h = As_h + 2 * G_ATILE * 2;
        const uint32_t Bs_l = Bs_h + G_BTILE * 2;
#pragma unroll
        for (int ks = 0; ks < 2; ks++) {
            uint32_t a_hi[4][4], a_lo[4][4];
            uint32_t bh[4], bl[4];
            const int ar = wm * 64 + (lane & 15);
            const int ac = ks * 16 + (lane >> 4) * 8;
#pragma unroll
            for (int mi = 0; mi < 4; mi++) {
                uint32_t off = (uint32_t)((ar + mi * 16) * KSTRIDE + ac) * 2;
                LDSM4(a_hi[mi][0], a_hi[mi][1], a_hi[mi][2], a_hi[mi][3], As_h + off);
                LDSM4(a_lo[mi][0], a_lo[mi][1], a_lo[mi][2], a_lo[mi][3], As_l + off);
            }
            const int br = wn * 16 + ((lane >> 4) << 3) + (lane & 7);
            const int bc = ks * 16 + ((lane >> 3) & 1) * 8;
            {
                uint32_t off = (uint32_t)(br * KSTRIDE + bc) * 2;
                LDSM4(bh[0], bh[1], bh[2], bh[3], Bs_h + off);
                LDSM4(bl[0], bl[1], bl[2], bl[3], Bs_l + off);
            }
#pragma unroll
            for (int mi = 0; mi < 4; mi++)
#pragma unroll
                for (int nf = 0; nf < 2; nf++) {
                    MMAF(acc[mi][nf], a_hi[mi], bh[nf * 2], bh[nf * 2 + 1]);
                    MMAF(acc[mi][nf], a_hi[mi], bl[nf * 2], bl[nf * 2 + 1]);
                    MMAF(acc[mi][nf], a_lo[mi], bh[nf * 2], bh[nf * 2 + 1]);
                }
        }
    };

    const int nch = K / 32;
    load_stage(0, 0);
    CP_COMMIT();
    for (int ch = 0; ch < nch; ch++) {
        if (ch + 1 < nch) {
            load_stage((ch + 1) & 1, (ch + 1) * 32);
            CP_COMMIT();
            CP_WAIT1();
        } else {
            CP_WAIT0();
        }
        __syncthreads();
        compute(ch & 1);
        __syncthreads();
    }

#pragma unroll
    for (int nf = 0; nf < 2; nf++) {
        const int col = bx * 64 + wn * 16 + nf * 8 + (lane & 3) * 2;
        const float b0 = bias[col], b1 = bias[col + 1];
#pragma unroll
        for (int mi = 0; mi < 4; mi++) {
            const int r0 = by * 128 + wm * 64 + mi * 16 + (lane >> 2);
            float v0 = acc[mi][nf][0] + b0, v1 = acc[mi][nf][1] + b1;
            float v2 = acc[mi][nf][2] + b0, v3 = acc[mi][nf][3] + b1;
            if (Cf) {
                float2 w0; w0.x = v0; w0.y = v1;
                float2 w1; w1.x = v2; w1.y = v3;
                *(float2*)(Cf + (size_t)r0 * N + col)       = w0;
                *(float2*)(Cf + (size_t)(r0 + 8) * N + col) = w1;
            } else {
                uint32_t h0, l0, h1, l1;
                pack2(v0, v1, h0, l0);
                pack2(v2, v3, h1, l1);
                *(uint32_t*)(Chi + (size_t)r0 * N + col)       = h0;
                *(uint32_t*)(Clo + (size_t)r0 * N + col)       = l0;
                *(uint32_t*)(Chi + (size_t)(r0 + 8) * N + col) = h1;
                *(uint32_t*)(Clo + (size_t)(r0 + 8) * N + col) = l1;
            }
        }
    }
}

// ---------------------------------------------------------------------------
// Flash attention, mma.sync bf16 3-term split, causal. (unchanged from R8)
// CTA: 128 q-rows x (b,h); 8 warps, warp w owns q-rows w*16..w*16+15.
// K-tiles of 64 keys, double-buffered cp.async.
// ---------------------------------------------------------------------------
#define ASTR 72
#define KVT_B (64 * ASTR * 2)       // 9216 B per tile
#define ASTAGE_B (4 * KVT_B)        // 36864 B
#define Q_OFF ASTAGE_B
#define ATTN_SMEM (2 * ASTAGE_B)    // 73728 B

__global__ __launch_bounds__(256)
void attn_mma_kernel(
    const __nv_bfloat16* __restrict__ qhi, const __nv_bfloat16* __restrict__ qlo,
    __nv_bfloat16* __restrict__ ohi, __nv_bfloat16* __restrict__ olo)
{
    extern __shared__ char sma[];
    const uint32_t sb = smem_u32(sma);

    const int tid  = threadIdx.x;
    const int lane = tid & 31;
    const int w    = tid >> 5;
    const int qt = (int)gridDim.x - 1 - blockIdx.x;   // heavy tiles first
    const int h  = blockIdx.y;
    const int b  = blockIdx.z;
    const int q0 = qt * 128;
    const float scale = 0.125f;

    const __nv_bfloat16* qsrc[2] = {qhi, qlo};

    auto load_kv = [&](int stage, int kt) {
        const int k0 = kt * 64;
#pragma unroll
        for (int i = 0; i < 8; i++) {
            int idx  = tid + i * 256;            // 0..2047
            int tile = idx >> 9;                 // 0:Khi 1:Klo 2:Vhi 3:Vlo
            int r    = (idx >> 3) & 63;
            int c    = idx & 7;
            int colb = (tile < 2) ? C_ : 2 * C_;
            const __nv_bfloat16* g = qsrc[tile & 1] +
                (size_t)(b * T_ + k0 + r) * C3_ + colb + h * DH_ + c * 8;
            uint32_t d = sb + stage * ASTAGE_B + tile * KVT_B +
                         (uint32_t)(r * ASTR + c * 8) * 2;
            CP_ASYNC16(d, g);
        }
    };

    // ---- prologue: Q into smem (stage-1 region), then to registers ----
#pragma unroll
    for (int i = 0; i < 8; i++) {
        int idx = tid + i * 256;                 // 0..2047
        int t   = idx >> 10;                     // 0:hi 1:lo
        int r   = (idx >> 3) & 127;
        int c   = idx & 7;
        const __nv_bfloat16* g = qsrc[t] +
            (size_t)(b * T_ + q0 + r) * C3_ + h * DH_ + c * 8;
        uint32_t d = sb + Q_OFF + t * (128 * ASTR * 2) +
                     (uint32_t)(r * ASTR + c * 8) * 2;
        CP_ASYNC16(d, g);
    }
    CP_COMMIT();
    load_kv(0, 0);
    CP_COMMIT();
    CP_WAIT1();              // Q arrived (oldest group)
    __syncthreads();

    uint32_t qf_h[4][4], qf_l[4][4];
    {
        const int r = w * 16 + (lane & 15);
        const int cb = (lane >> 4) * 8;
#pragma unroll
        for (int kf = 0; kf < 4; kf++) {
            uint32_t off = sb + Q_OFF + (uint32_t)(r * ASTR + kf * 16 + cb) * 2;
            LDSM4(qf_h[kf][0], qf_h[kf][1], qf_h[kf][2], qf_h[kf][3], off);
            LDSM4(qf_l[kf][0], qf_l[kf][1], qf_l[kf][2], qf_l[kf][3],
                  off + 128 * ASTR * 2);
        }
    }
    __syncthreads();         // Q region now reusable as stage 1

    float oacc[8][4];
#pragma unroll
    for (int nf = 0; nf < 8; nf++)
#pragma unroll
        for (int r = 0; r < 4; r++) oacc[nf][r] = 0.f;
    float m0 = -1e30f, m1 = -1e30f, l0 = 0.f, l1 = 0.f;

    const int nkt = 2 * qt + 2;
    for (int kt = 0; kt < nkt; kt++) {
        const int s = kt & 1;
        if (kt + 1 < nkt) { load_kv(s ^ 1, kt + 1); CP_COMMIT(); CP_WAIT1(); }
        else              { CP_WAIT0(); }
        __syncthreads();

        const uint32_t kb_h = sb + s * ASTAGE_B;
        const uint32_t kb_l = kb_h + KVT_B;
        const uint32_t vb_h = kb_h + 2 * KVT_B;
        const uint32_t vb_l = kb_h + 3 * KVT_B;

        // ---- S = Q K^T ----
        float sfr[8][4];
#pragma unroll
        for (int nf = 0; nf < 8; nf++)
#pragma unroll
            for (int r = 0; r < 4; r++) sfr[nf][r] = 0.f;

#pragma unroll
        for (int kf = 0; kf < 4; kf++) {
            uint32_t bh[4][4], bl[4][4];
            const int rr = (lane >> 4) * 8 + (lane & 7);
            const int cc = kf * 16 + ((lane >> 3) & 1) * 8;
#pragma unroll
            for (int p = 0; p < 4; p++) {
                uint32_t off = (uint32_t)((p * 16 + rr) * ASTR + cc) * 2;
                LDSM4(bh[p][0], bh[p][1], bh[p][2], bh[p][3], kb_h + off);
                LDSM4(bl[p][0], bl[p][1], bl[p][2], bl[p][3], kb_l + off);
            }
#pragma unroll
            for (int nf = 0; nf < 8; nf++) {
                uint32_t bh0 = bh[nf >> 1][(nf & 1) * 2];
                uint32_t bh1 = bh[nf >> 1][(nf & 1) * 2 + 1];
                uint32_t bl0 = bl[nf >> 1][(nf & 1) * 2];
                uint32_t bl1 = bl[nf >> 1][(nf & 1) * 2 + 1];
                MMAF(sfr[nf], qf_h[kf], bh0, bh1);
                MMAF(sfr[nf], qf_h[kf], bl0, bl1);
                MMAF(sfr[nf], qf_l[kf], bh0, bh1);
            }
        }

#pragma unroll
        for (int nf = 0; nf < 8; nf++)
#pragma unroll
            for (int r = 0; r < 4; r++) sfr[nf][r] *= scale;

        // ---- causal mask (last two k-tiles only) ----
        if (kt >= 2 * qt) {
            const int k0 = kt * 64;
            const int r0g = q0 + w * 16 + (lane >> 2);
            const int r1g = r0g + 8;
#pragma unroll
            for (int nf = 0; nf < 8; nf++) {
                const int c0 = k0 + nf * 8 + (lane & 3) * 2;
                if (c0     > r0g) sfr[nf][0] = -1e30f;
                if (c0 + 1 > r0g) sfr[nf][1] = -1e30f;
                if (c0     > r1g) sfr[nf][2] = -1e30f;
                if (c0 + 1 > r1g) sfr[nf][3] = -1e30f;
            }
        }

        // ---- online softmax (rows are quad-local: shfl over lanes^1,^2) ----
        float mx0 = -1e30f, mx1 = -1e30f;
#pragma unroll
        for (int nf = 0; nf < 8; nf++) {
            mx0 = fmaxf(mx0, fmaxf(sfr[nf][0], sfr[nf][1]));
            mx1 = fmaxf(mx1, fmaxf(sfr[nf][2], sfr[nf][3]));
        }
        mx0 = fmaxf(mx0, __shfl_xor_sync(0xffffffffu, mx0, 1));
        mx0 = fmaxf(mx0, __shfl_xor_sync(0xffffffffu, mx0, 2));
        mx1 = fmaxf(mx1, __shfl_xor_sync(0xffffffffu, mx1, 1));
        mx1 = fmaxf(mx1, __shfl_xor_sync(0xffffffffu, mx1, 2));
        const float nm0 = fmaxf(m0, mx0), nm1 = fmaxf(m1, mx1);
        const float corr0 = __expf(m0 - nm0), corr1 = __expf(m1 - nm1);
        float rs0 = 0.f, rs1 = 0.f;
#pragma unroll
        for (int nf = 0; nf < 8; nf++) {
            sfr[nf][0] = __expf(sfr[nf][0] - nm0);
            sfr[nf][1] = __expf(sfr[nf][1] - nm0);
            sfr[nf][2] = __expf(sfr[nf][2] - nm1);
            sfr[nf][3] = __expf(sfr[nf][3] - nm1);
            rs0 += sfr[nf][0] + sfr[nf][1];
            rs1 += sfr[nf][2] + sfr[nf][3];
        }
        rs0 += __shfl_xor_sync(0xffffffffu, rs0, 1);
        rs0 += __shfl_xor_sync(0xffffffffu, rs0, 2);
        rs1 += __shfl_xor_sync(0xffffffffu, rs1, 1);
        rs1 += __shfl_xor_sync(0xffffffffu, rs1, 2);
        l0 = l0 * corr0 + rs0;  m0 = nm0;
        l1 = l1 * corr1 + rs1;  m1 = nm1;
#pragma unroll
        for (int nf = 0; nf < 8; nf++) {
            oacc[nf][0] *= corr0;  oacc[nf][1] *= corr0;
            oacc[nf][2] *= corr1;  oacc[nf][3] *= corr1;
        }

        // ---- repack P (S C-frags -> A-frags, registers only) ----
        // A-frag order: a0=rows0-7/k0-7, a1=rows8-15/k0-7,
        //               a2=rows0-7/k8-15, a3=rows8-15/k8-15
        uint32_t pa_h[4][4], pa_l[4][4];
#pragma unroll
        for (int kf = 0; kf < 4; kf++) {
            pack2(sfr[2*kf  ][0], sfr[2*kf  ][1], pa_h[kf][0], pa_l[kf][0]);
            pack2(sfr[2*kf  ][2], sfr[2*kf  ][3], pa_h[kf][1], pa_l[kf][1]);
            pack2(sfr[2*kf+1][0], sfr[2*kf+1][1], pa_h[kf][2], pa_l[kf][2]);
            pack2(sfr[2*kf+1][2], sfr[2*kf+1][3], pa_h[kf][3], pa_l[kf][3]);
        }

        // ---- O += P V  (V consumed via ldmatrix.trans from [key][d]) ----
#pragma unroll
        for (int kf = 0; kf < 4; kf++) {
            uint32_t vh[4][4], vl[4][4];
            const int rr = kf * 16 + (lane & 7) + ((lane >> 3) & 1) * 8;
            const int cc = (lane >> 4) * 8;
#pragma unroll
            for (int p = 0; p < 4; p++) {
                uint32_t off = (uint32_t)(rr * ASTR + p * 16 + cc) * 2;
                LDSM4T(vh[p][0], vh[p][1], vh[p][2], vh[p][3], vb_h + off);
                LDSM4T(vl[p][0], vl[p][1], vl[p][2], vl[p][3], vb_l + off);
            }
#pragma unroll
            for (int nf = 0; nf < 8; nf++) {
                uint32_t bh0 = vh[nf >> 1][(nf & 1) * 2];
                uint32_t bh1 = vh[nf >> 1][(nf & 1) * 2 + 1];
                uint32_t bl0 = vl[nf >> 1][(nf & 1) * 2];
                uint32_t bl1 = vl[nf >> 1][(nf & 1) * 2 + 1];
                MMAF(oacc[nf], pa_h[kf], bh0, bh1);
                MMAF(oacc[nf], pa_h[kf], bl0, bl1);
                MMAF(oacc[nf], pa_l[kf], bh0, bh1);
            }
        }
        __syncthreads();   // all warps done with stage s before next overwrite
    }

    // ---- epilogue: O/l -> bf16 hi/lo ----
    const float inv0 = 1.f / l0, inv1 = 1.f / l1;
    const int r0g = q0 + w * 16 + (lane >> 2);
#pragma unroll
    for (int nf = 0; nf < 8; nf++) {
        const int col = h * DH_ + nf * 8 + (lane & 3) * 2;
        uint32_t h0, lo0, h1, lo1;
        pack2(oacc[nf][0] * inv0, oacc[nf][1] * inv0, h0, lo0);
        pack2(oacc[nf][2] * inv1, oacc[nf][3] * inv1, h1, lo1);
        size_t a0 = (size_t)(b * T_ + r0g) * C_ + col;
        size_t a1 = a0 + (size_t)8 * C_;
        *(uint32_t*)(ohi + a0) = h0;   *(uint32_t*)(olo + a0) = lo0;
        *(uint32_t*)(ohi + a1) = h1;   *(uint32_t*)(olo + a1) = lo1;
    }
}

// ---------------------------------------------------------------------------
// Launch
// ---------------------------------------------------------------------------
extern "C" void kernel_launch(void* const* d_in, const int* in_sizes, int n_in,
                              void* d_out, int out_size)
{
    const float* x     = (const float*)d_in[0];
    const float* w_qkv = (const float*)d_in[1];
    const float* b_qkv = (const float*)d_in[2];
    const float* w_out = (const float*)d_in[3];
    const float* b_out = (const float*)d_in[4];
    float* out = (float*)d_out;

    __nv_bfloat16 *xhi, *xlo, *wqhi, *wqlo, *wohi, *wolo, *qhi, *qlo, *ahi, *alo;
    cudaGetSymbolAddress((void**)&xhi,  g_xhi);
    cudaGetSymbolAddress((void**)&xlo,  g_xlo);
    cudaGetSymbolAddress((void**)&wqhi, g_wqhi);
    cudaGetSymbolAddress((void**)&wqlo, g_wqlo);
    cudaGetSymbolAddress((void**)&wohi, g_wohi);
    cudaGetSymbolAddress((void**)&wolo, g_wolo);
    cudaGetSymbolAddress((void**)&qhi,  g_qhi);
    cudaGetSymbolAddress((void**)&qlo,  g_qlo);
    cudaGetSymbolAddress((void**)&ahi,  g_ahi);
    cudaGetSymbolAddress((void**)&alo,  g_alo);

    cudaFuncSetAttribute(gemm_mma_kernel,
                         cudaFuncAttributeMaxDynamicSharedMemorySize, GEMM_SMEM);
    cudaFuncSetAttribute(attn_mma_kernel,
                         cudaFuncAttributeMaxDynamicSharedMemorySize, ATTN_SMEM);

    split_kernel<<<(M_ * C_) / 4 / 256, 256>>>(x, xhi, xlo, M_ * C_);
    transpose_split_kernel<<<dim3(C3_ / 32, C_ / 32), dim3(32, 8)>>>(
        w_qkv, wqhi, wqlo, C_, C3_);
    transpose_split_kernel<<<dim3(C_ / 32, C_ / 32), dim3(32, 8)>>>(
        w_out, wohi, wolo, C_, C_);

    // GEMM1: qkv = x @ Wqkv + b  -> bf16 hi/lo
    gemm_mma_kernel<<<dim3(C3_ / 64, M_ / 128), 256, GEMM_SMEM>>>(
        xhi, xlo, wqhi, wqlo, b_qkv, nullptr, qhi, qlo, C3_, C_);

    // attention (mma.sync) -> bf16 hi/lo
    attn_mma_kernel<<<dim3(T_ / 128, H_, B_), 256, ATTN_SMEM>>>(
        qhi, qlo, ahi, alo);

    // GEMM2: out = att @ Wout + b -> fp32
    gemm_mma_kernel<<<dim3(C_ / 64, M_ / 128), 256, GEMM_SMEM>>>(
        ahi, alo, wohi, wolo, b_out, out, nullptr, nullptr, C_, C_);
}

// round 11
// speedup vs baseline: 2.3884x; 1.0024x over previous
#include <cuda_runtime.h>
#include <cuda_bf16.h>
#include <cstdint>
#include <math.h>

// ---------------------------------------------------------------------------
// Problem:
//   x (4,2048,1024) f32; w_qkv (1024,3072); b_qkv (3072,);
//   w_out (1024,1024); b_out (1024,); out (4,2048,1024) f32
// Pipeline (all tensor work on mma.sync bf16 3-term hi/lo split):
//   split(x) -> bf16 hi/lo ; transpose+split(W)
//   GEMM1: qkv = x @ Wqkv + b  -> bf16 hi/lo  (qhi/qlo buffers)
//   flash attention, mma.sync, causal -> bf16 hi/lo (ahi/alo)
//   GEMM2: out = att @ Wout + b -> fp32
// GEMM: tile 128x64, 3-stage cp.async pipeline, one barrier per chunk,
// ordering: WAIT -> __syncthreads -> issue loads -> compute
// (round-10 bug: wait AFTER sync with no barrier before compute = race).
// ---------------------------------------------------------------------------
#define B_   4
#define T_   2048
#define C_   1024
#define H_   16
#define DH_  64
#define M_   (B_ * T_)       // 8192
#define C3_  (3 * C_)        // 3072

__device__ __nv_bfloat16 g_xhi[(size_t)M_ * C_];
__device__ __nv_bfloat16 g_xlo[(size_t)M_ * C_];
__device__ __nv_bfloat16 g_wqhi[(size_t)C3_ * C_];
__device__ __nv_bfloat16 g_wqlo[(size_t)C3_ * C_];
__device__ __nv_bfloat16 g_wohi[(size_t)C_ * C_];
__device__ __nv_bfloat16 g_wolo[(size_t)C_ * C_];
__device__ __nv_bfloat16 g_qhi[(size_t)M_ * C3_];   // qkv hi
__device__ __nv_bfloat16 g_qlo[(size_t)M_ * C3_];   // qkv lo
__device__ __nv_bfloat16 g_ahi[(size_t)M_ * C_];
__device__ __nv_bfloat16 g_alo[(size_t)M_ * C_];

// ---------------------------------------------------------------------------
__device__ __forceinline__ uint32_t smem_u32(const void* p) {
    uint32_t a;
    asm("{ .reg .u64 t; cvta.to.shared.u64 t, %1; cvt.u32.u64 %0, t; }"
        : "=r"(a) : "l"(p));
    return a;
}

#define LDSM4(r0, r1, r2, r3, addr) \
    asm volatile("ldmatrix.sync.aligned.m8n8.x4.shared.b16 {%0,%1,%2,%3}, [%4];" \
        : "=r"(r0), "=r"(r1), "=r"(r2), "=r"(r3) : "r"(addr))
#define LDSM4T(r0, r1, r2, r3, addr) \
    asm volatile("ldmatrix.sync.aligned.m8n8.x4.trans.shared.b16 {%0,%1,%2,%3}, [%4];" \
        : "=r"(r0), "=r"(r1), "=r"(r2), "=r"(r3) : "r"(addr))

#define MMAF(c, a, b0r, b1r) \
    asm volatile("mma.sync.aligned.m16n8k16.row.col.f32.bf16.bf16.f32 " \
        "{%0,%1,%2,%3}, {%4,%5,%6,%7}, {%8,%9}, {%0,%1,%2,%3};" \
        : "+f"((c)[0]), "+f"((c)[1]), "+f"((c)[2]), "+f"((c)[3]) \
        : "r"((a)[0]), "r"((a)[1]), "r"((a)[2]), "r"((a)[3]), \
          "r"(b0r), "r"(b1r))

#define CP_ASYNC16(dst, src) \
    asm volatile("cp.async.cg.shared.global [%0], [%1], 16;" :: "r"(dst), "l"(src))
#define CP_COMMIT() asm volatile("cp.async.commit_group;" ::: "memory")
#define CP_WAIT1()  asm volatile("cp.async.wait_group 1;" ::: "memory")
#define CP_WAIT0()  asm volatile("cp.async.wait_group 0;" ::: "memory")

// pack two floats -> bf16x2 hi reg + residual lo reg
__device__ __forceinline__ void pack2(float x, float y, uint32_t& hi, uint32_t& lo) {
    __nv_bfloat16 hx = __float2bfloat16(x), hy = __float2bfloat16(y);
    __nv_bfloat162 hh; hh.x = hx; hh.y = hy;
    hi = *reinterpret_cast<uint32_t*>(&hh);
    __nv_bfloat162 ll;
    ll.x = __float2bfloat16(x - __bfloat162float(hx));
    ll.y = __float2bfloat16(y - __bfloat162float(hy));
    lo = *reinterpret_cast<uint32_t*>(&ll);
}

// ---------------------------------------------------------------------------
// Prep kernels
// ---------------------------------------------------------------------------
__global__ __launch_bounds__(256) void split_kernel(
    const float* __restrict__ in, __nv_bfloat16* __restrict__ hi,
    __nv_bfloat16* __restrict__ lo, int n)
{
    int i = (blockIdx.x * 256 + threadIdx.x) * 4;
    if (i >= n) return;
    float4 v = *(const float4*)(in + i);
    uint32_t h0, l0, h1, l1;
    pack2(v.x, v.y, h0, l0);
    pack2(v.z, v.w, h1, l1);
    *(uint32_t*)(hi + i)     = h0;  *(uint32_t*)(hi + i + 2) = h1;
    *(uint32_t*)(lo + i)     = l0;  *(uint32_t*)(lo + i + 2) = l1;
}

__global__ __launch_bounds__(256) void transpose_split_kernel(
    const float* __restrict__ w, __nv_bfloat16* __restrict__ thi,
    __nv_bfloat16* __restrict__ tlo, int K, int N)
{
    __shared__ float tile[32][33];
    int n0 = blockIdx.x * 32, k0 = blockIdx.y * 32;
    int tx = threadIdx.x, ty = threadIdx.y;
#pragma unroll
    for (int j = 0; j < 32; j += 8)
        tile[ty + j][tx] = w[(size_t)(k0 + ty + j) * N + n0 + tx];
    __syncthreads();
#pragma unroll
    for (int j = 0; j < 32; j += 8) {
        float v = tile[tx][ty + j];
        __nv_bfloat16 h = __float2bfloat16(v);
        size_t idx = (size_t)(n0 + ty + j) * K + k0 + tx;
        thi[idx] = h;
        tlo[idx] = __float2bfloat16(v - __bfloat162float(h));
    }
}

// ---------------------------------------------------------------------------
// mma.sync GEMM: C = (Ahi+Alo) @ (Bhi+Blo)^T + bias
// CTA tile 128x64, BK=32, 8 warps (2x4), warp tile 64x16.
// 3-stage cp.async pipeline, one __syncthreads per chunk, 2 CTAs/SM.
// Per-iter order: WAIT(chunk ch) -> sync -> issue loads(ch+2) -> compute(ch).
// ---------------------------------------------------------------------------
#define KSTRIDE 40
#define G_ATILE (128 * KSTRIDE)          // 5120 elems
#define G_BTILE (64 * KSTRIDE)           // 2560 elems
#define G_STAGE (2 * G_ATILE + 2 * G_BTILE)   // 15360 elems
#define G_NSTG  3
#define GEMM_SMEM (G_NSTG * G_STAGE * 2) // 92160 B

__global__ __launch_bounds__(256, 2)
void gemm_mma_kernel(
    const __nv_bfloat16* __restrict__ Ahi, const __nv_bfloat16* __restrict__ Alo,
    const __nv_bfloat16* __restrict__ Bhi, const __nv_bfloat16* __restrict__ Blo,
    const float* __restrict__ bias,
    float* __restrict__ Cf,
    __nv_bfloat16* __restrict__ Chi, __nv_bfloat16* __restrict__ Clo,
    int N, int K)
{
    extern __shared__ __nv_bfloat16 smb[];
    const uint32_t sbase = smem_u32(smb);

    const int tid  = threadIdx.x;
    const int lane = tid & 31;
    const int wid  = tid >> 5;
    const int wm   = wid >> 2;           // 0..1 -> m offset wm*64
    const int wn   = wid & 3;            // 0..3 -> n offset wn*16
    const int bx = blockIdx.x, by = blockIdx.y;

    const __nv_bfloat16* srcs[4];
    srcs[0] = Ahi + (size_t)(by * 128) * K;   // 128 rows
    srcs[1] = Alo + (size_t)(by * 128) * K;   // 128 rows
    srcs[2] = Bhi + (size_t)(bx * 64) * K;    // 64 rows
    srcs[3] = Blo + (size_t)(bx * 64) * K;    // 64 rows
    const uint32_t tbase[4] = {0, G_ATILE, 2 * G_ATILE, 2 * G_ATILE + G_BTILE};

    float acc[4][2][4];
#pragma unroll
    for (int mi = 0; mi < 4; mi++)
#pragma unroll
        for (int nf = 0; nf < 2; nf++)
#pragma unroll
            for (int r = 0; r < 4; r++) acc[mi][nf][r] = 0.f;

    // 1536 x16B chunks per stage, 6 per thread
    auto load_stage = [&](int stage, int k0) {
#pragma unroll
        for (int i = 0; i < 6; i++) {
            int idx = tid + i * 256;           // 0..1535
            int tile, r;
            if (idx < 1024) { tile = idx >> 9;              r = (idx >> 2) & 127; }
            else            { tile = 2 + ((idx - 1024) >> 8); r = ((idx - 1024) >> 2) & 63; }
            int c = idx & 3;                   // 16B chunk within 32-elem row
            const __nv_bfloat16* g = srcs[tile] + (size_t)r * K + k0 + c * 8;
            uint32_t d = sbase +
                (uint32_t)(stage * G_STAGE + tbase[tile] + r * KSTRIDE + c * 8) * 2;
            CP_ASYNC16(d, g);
        }
    };

    auto compute = [&](int stage) {
        const uint32_t As_h = sbase + (uint32_t)(stage * G_STAGE) * 2;
        const uint32_t As_l = As_h + G_ATILE * 2;
        const uint32_t Bs_h = As_h + 2 * G_ATILE * 2;
        const uint32_t Bs_l = Bs_h + G_BTILE * 2;
#pragma unroll
        for (int ks = 0; ks < 2; ks++) {
            uint32_t a_hi[4][4], a_lo[4][4];
            uint32_t bh[4], bl[4];
            const int ar = wm * 64 + (lane & 15);
            const int ac = ks * 16 + (lane >> 4) * 8;
#pragma unroll
            for (int mi = 0; mi < 4; mi++) {
                uint32_t off = (uint32_t)((ar + mi * 16) * KSTRIDE + ac) * 2;
                LDSM4(a_hi[mi][0], a_hi[mi][1], a_hi[mi][2], a_hi[mi][3], As_h + off);
                LDSM4(a_lo[mi][0], a_lo[mi][1], a_lo[mi][2], a_lo[mi][3], As_l + off);
            }
            const int br = wn * 16 + ((lane >> 4) << 3) + (lane & 7);
            const int bc = ks * 16 + ((lane >> 3) & 1) * 8;
            {
                uint32_t off = (uint32_t)(br * KSTRIDE + bc) * 2;
                LDSM4(bh[0], bh[1], bh[2], bh[3], Bs_h + off);
                LDSM4(bl[0], bl[1], bl[2], bl[3], Bs_l + off);
            }
#pragma unroll
            for (int mi = 0; mi < 4; mi++)
#pragma unroll
                for (int nf = 0; nf < 2; nf++) {
                    MMAF(acc[mi][nf], a_hi[mi], bh[nf * 2], bh[nf * 2 + 1]);
                    MMAF(acc[mi][nf], a_hi[mi], bl[nf * 2], bl[nf * 2 + 1]);
                    MMAF(acc[mi][nf], a_lo[mi], bh[nf * 2], bh[nf * 2 + 1]);
                }
        }
    };

    const int nch = K / 32;   // 32
    // prologue: chunks 0,1 -> stages 0,1
    load_stage(0, 0);
    CP_COMMIT();
    load_stage(1, 32);
    CP_COMMIT();

    int cs = 0;               // compute stage = ch % 3
    int ls = 2;               // load stage    = (ch+2) % 3
    for (int ch = 0; ch < nch; ch++) {
        // chunk ch's group done (per-thread): newest committed is chunk
        // min(ch+1, nch-1); allowed pending = that - ch.
        if (ch + 1 < nch) CP_WAIT1();
        else              CP_WAIT0();
        __syncthreads();      // publish all threads' chunk-ch data; also
                              // retires compute(ch-1) so stage ls is free
        if (ch + 2 < nch) {
            load_stage(ls, (ch + 2) * 32);
            CP_COMMIT();
        }
        compute(cs);
        cs = (cs == 2) ? 0 : cs + 1;
        ls = (ls == 2) ? 0 : ls + 1;
    }

#pragma unroll
    for (int nf = 0; nf < 2; nf++) {
        const int col = bx * 64 + wn * 16 + nf * 8 + (lane & 3) * 2;
        const float b0 = bias[col], b1 = bias[col + 1];
#pragma unroll
        for (int mi = 0; mi < 4; mi++) {
            const int r0 = by * 128 + wm * 64 + mi * 16 + (lane >> 2);
            float v0 = acc[mi][nf][0] + b0, v1 = acc[mi][nf][1] + b1;
            float v2 = acc[mi][nf][2] + b0, v3 = acc[mi][nf][3] + b1;
            if (Cf) {
                float2 w0; w0.x = v0; w0.y = v1;
                float2 w1; w1.x = v2; w1.y = v3;
                *(float2*)(Cf + (size_t)r0 * N + col)       = w0;
                *(float2*)(Cf + (size_t)(r0 + 8) * N + col) = w1;
            } else {
                uint32_t h0, l0, h1, l1;
                pack2(v0, v1, h0, l0);
                pack2(v2, v3, h1, l1);
                *(uint32_t*)(Chi + (size_t)r0 * N + col)       = h0;
                *(uint32_t*)(Clo + (size_t)r0 * N + col)       = l0;
                *(uint32_t*)(Chi + (size_t)(r0 + 8) * N + col) = h1;
                *(uint32_t*)(Clo + (size_t)(r0 + 8) * N + col) = l1;
            }
        }
    }
}

// ---------------------------------------------------------------------------
// Flash attention, mma.sync bf16 3-term split, causal. (unchanged from R9)
// CTA: 128 q-rows x (b,h); 8 warps, warp w owns q-rows w*16..w*16+15.
// K-tiles of 64 keys, double-buffered cp.async.
// ---------------------------------------------------------------------------
#define ASTR 72
#define KVT_B (64 * ASTR * 2)       // 9216 B per tile
#define ASTAGE_B (4 * KVT_B)        // 36864 B
#define Q_OFF ASTAGE_B
#define ATTN_SMEM (2 * ASTAGE_B)    // 73728 B

__global__ __launch_bounds__(256)
void attn_mma_kernel(
    const __nv_bfloat16* __restrict__ qhi, const __nv_bfloat16* __restrict__ qlo,
    __nv_bfloat16* __restrict__ ohi, __nv_bfloat16* __restrict__ olo)
{
    extern __shared__ char sma[];
    const uint32_t sb = smem_u32(sma);

    const int tid  = threadIdx.x;
    const int lane = tid & 31;
    const int w    = tid >> 5;
    const int qt = (int)gridDim.x - 1 - blockIdx.x;   // heavy tiles first
    const int h  = blockIdx.y;
    const int b  = blockIdx.z;
    const int q0 = qt * 128;
    const float scale = 0.125f;

    const __nv_bfloat16* qsrc[2] = {qhi, qlo};

    auto load_kv = [&](int stage, int kt) {
        const int k0 = kt * 64;
#pragma unroll
        for (int i = 0; i < 8; i++) {
            int idx  = tid + i * 256;            // 0..2047
            int tile = idx >> 9;                 // 0:Khi 1:Klo 2:Vhi 3:Vlo
            int r    = (idx >> 3) & 63;
            int c    = idx & 7;
            int colb = (tile < 2) ? C_ : 2 * C_;
            const __nv_bfloat16* g = qsrc[tile & 1] +
                (size_t)(b * T_ + k0 + r) * C3_ + colb + h * DH_ + c * 8;
            uint32_t d = sb + stage * ASTAGE_B + tile * KVT_B +
                         (uint32_t)(r * ASTR + c * 8) * 2;
            CP_ASYNC16(d, g);
        }
    };

    // ---- prologue: Q into smem (stage-1 region), then to registers ----
#pragma unroll
    for (int i = 0; i < 8; i++) {
        int idx = tid + i * 256;                 // 0..2047
        int t   = idx >> 10;                     // 0:hi 1:lo
        int r   = (idx >> 3) & 127;
        int c   = idx & 7;
        const __nv_bfloat16* g = qsrc[t] +
            (size_t)(b * T_ + q0 + r) * C3_ + h * DH_ + c * 8;
        uint32_t d = sb + Q_OFF + t * (128 * ASTR * 2) +
                     (uint32_t)(r * ASTR + c * 8) * 2;
        CP_ASYNC16(d, g);
    }
    CP_COMMIT();
    load_kv(0, 0);
    CP_COMMIT();
    CP_WAIT1();              // Q arrived (oldest group)
    __syncthreads();

    uint32_t qf_h[4][4], qf_l[4][4];
    {
        const int r = w * 16 + (lane & 15);
        const int cb = (lane >> 4) * 8;
#pragma unroll
        for (int kf = 0; kf < 4; kf++) {
            uint32_t off = sb + Q_OFF + (uint32_t)(r * ASTR + kf * 16 + cb) * 2;
            LDSM4(qf_h[kf][0], qf_h[kf][1], qf_h[kf][2], qf_h[kf][3], off);
            LDSM4(qf_l[kf][0], qf_l[kf][1], qf_l[kf][2], qf_l[kf][3],
                  off + 128 * ASTR * 2);
        }
    }
    __syncthreads();         // Q region now reusable as stage 1

    float oacc[8][4];
#pragma unroll
    for (int nf = 0; nf < 8; nf++)
#pragma unroll
        for (int r = 0; r < 4; r++) oacc[nf][r] = 0.f;
    float m0 = -1e30f, m1 = -1e30f, l0 = 0.f, l1 = 0.f;

    const int nkt = 2 * qt + 2;
    for (int kt = 0; kt < nkt; kt++) {
        const int s = kt & 1;
        if (kt + 1 < nkt) { load_kv(s ^ 1, kt + 1); CP_COMMIT(); CP_WAIT1(); }
        else              { CP_WAIT0(); }
        __syncthreads();

        const uint32_t kb_h = sb + s * ASTAGE_B;
        const uint32_t kb_l = kb_h + KVT_B;
        const uint32_t vb_h = kb_h + 2 * KVT_B;
        const uint32_t vb_l = kb_h + 3 * KVT_B;

        // ---- S = Q K^T ----
        float sfr[8][4];
#pragma unroll
        for (int nf = 0; nf < 8; nf++)
#pragma unroll
            for (int r = 0; r < 4; r++) sfr[nf][r] = 0.f;

#pragma unroll
        for (int kf = 0; kf < 4; kf++) {
            uint32_t bh[4][4], bl[4][4];
            const int rr = (lane >> 4) * 8 + (lane & 7);
            const int cc = kf * 16 + ((lane >> 3) & 1) * 8;
#pragma unroll
            for (int p = 0; p < 4; p++) {
                uint32_t off = (uint32_t)((p * 16 + rr) * ASTR + cc) * 2;
                LDSM4(bh[p][0], bh[p][1], bh[p][2], bh[p][3], kb_h + off);
                LDSM4(bl[p][0], bl[p][1], bl[p][2], bl[p][3], kb_l + off);
            }
#pragma unroll
            for (int nf = 0; nf < 8; nf++) {
                uint32_t bh0 = bh[nf >> 1][(nf & 1) * 2];
                uint32_t bh1 = bh[nf >> 1][(nf & 1) * 2 + 1];
                uint32_t bl0 = bl[nf >> 1][(nf & 1) * 2];
                uint32_t bl1 = bl[nf >> 1][(nf & 1) * 2 + 1];
                MMAF(sfr[nf], qf_h[kf], bh0, bh1);
                MMAF(sfr[nf], qf_h[kf], bl0, bl1);
                MMAF(sfr[nf], qf_l[kf], bh0, bh1);
            }
        }

#pragma unroll
        for (int nf = 0; nf < 8; nf++)
#pragma unroll
            for (int r = 0; r < 4; r++) sfr[nf][r] *= scale;

        // ---- causal mask (last two k-tiles only) ----
        if (kt >= 2 * qt) {
            const int k0 = kt * 64;
            const int r0g = q0 + w * 16 + (lane >> 2);
            const int r1g = r0g + 8;
#pragma unroll
            for (int nf = 0; nf < 8; nf++) {
                const int c0 = k0 + nf * 8 + (lane & 3) * 2;
                if (c0     > r0g) sfr[nf][0] = -1e30f;
                if (c0 + 1 > r0g) sfr[nf][1] = -1e30f;
                if (c0     > r1g) sfr[nf][2] = -1e30f;
                if (c0 + 1 > r1g) sfr[nf][3] = -1e30f;
            }
        }

        // ---- online softmax (rows are quad-local: shfl over lanes^1,^2) ----
        float mx0 = -1e30f, mx1 = -1e30f;
#pragma unroll
        for (int nf = 0; nf < 8; nf++) {
            mx0 = fmaxf(mx0, fmaxf(sfr[nf][0], sfr[nf][1]));
            mx1 = fmaxf(mx1, fmaxf(sfr[nf][2], sfr[nf][3]));
        }
        mx0 = fmaxf(mx0, __shfl_xor_sync(0xffffffffu, mx0, 1));
        mx0 = fmaxf(mx0, __shfl_xor_sync(0xffffffffu, mx0, 2));
        mx1 = fmaxf(mx1, __shfl_xor_sync(0xffffffffu, mx1, 1));
        mx1 = fmaxf(mx1, __shfl_xor_sync(0xffffffffu, mx1, 2));
        const float nm0 = fmaxf(m0, mx0), nm1 = fmaxf(m1, mx1);
        const float corr0 = __expf(m0 - nm0), corr1 = __expf(m1 - nm1);
        float rs0 = 0.f, rs1 = 0.f;
#pragma unroll
        for (int nf = 0; nf < 8; nf++) {
            sfr[nf][0] = __expf(sfr[nf][0] - nm0);
            sfr[nf][1] = __expf(sfr[nf][1] - nm0);
            sfr[nf][2] = __expf(sfr[nf][2] - nm1);
            sfr[nf][3] = __expf(sfr[nf][3] - nm1);
            rs0 += sfr[nf][0] + sfr[nf][1];
            rs1 += sfr[nf][2] + sfr[nf][3];
        }
        rs0 += __shfl_xor_sync(0xffffffffu, rs0, 1);
        rs0 += __shfl_xor_sync(0xffffffffu, rs0, 2);
        rs1 += __shfl_xor_sync(0xffffffffu, rs1, 1);
        rs1 += __shfl_xor_sync(0xffffffffu, rs1, 2);
        l0 = l0 * corr0 + rs0;  m0 = nm0;
        l1 = l1 * corr1 + rs1;  m1 = nm1;
#pragma unroll
        for (int nf = 0; nf < 8; nf++) {
            oacc[nf][0] *= corr0;  oacc[nf][1] *= corr0;
            oacc[nf][2] *= corr1;  oacc[nf][3] *= corr1;
        }

        // ---- repack P (S C-frags -> A-frags, registers only) ----
        // A-frag order: a0=rows0-7/k0-7, a1=rows8-15/k0-7,
        //               a2=rows0-7/k8-15, a3=rows8-15/k8-15
        uint32_t pa_h[4][4], pa_l[4][4];
#pragma unroll
        for (int kf = 0; kf < 4; kf++) {
            pack2(sfr[2*kf  ][0], sfr[2*kf  ][1], pa_h[kf][0], pa_l[kf][0]);
            pack2(sfr[2*kf  ][2], sfr[2*kf  ][3], pa_h[kf][1], pa_l[kf][1]);
            pack2(sfr[2*kf+1][0], sfr[2*kf+1][1], pa_h[kf][2], pa_l[kf][2]);
            pack2(sfr[2*kf+1][2], sfr[2*kf+1][3], pa_h[kf][3], pa_l[kf][3]);
        }

        // ---- O += P V  (V consumed via ldmatrix.trans from [key][d]) ----
#pragma unroll
        for (int kf = 0; kf < 4; kf++) {
            uint32_t vh[4][4], vl[4][4];
            const int rr = kf * 16 + (lane & 7) + ((lane >> 3) & 1) * 8;
            const int cc = (lane >> 4) * 8;
#pragma unroll
            for (int p = 0; p < 4; p++) {
                uint32_t off = (uint32_t)(rr * ASTR + p * 16 + cc) * 2;
                LDSM4T(vh[p][0], vh[p][1], vh[p][2], vh[p][3], vb_h + off);
                LDSM4T(vl[p][0], vl[p][1], vl[p][2], vl[p][3], vb_l + off);
            }
#pragma unroll
            for (int nf = 0; nf < 8; nf++) {
                uint32_t bh0 = vh[nf >> 1][(nf & 1) * 2];
                uint32_t bh1 = vh[nf >> 1][(nf & 1) * 2 + 1];
                uint32_t bl0 = vl[nf >> 1][(nf & 1) * 2];
                uint32_t bl1 = vl[nf >> 1][(nf & 1) * 2 + 1];
                MMAF(oacc[nf], pa_h[kf], bh0, bh1);
                MMAF(oacc[nf], pa_h[kf], bl0, bl1);
                MMAF(oacc[nf], pa_l[kf], bh0, bh1);
            }
        }
        __syncthreads();   // all warps done with stage s before next overwrite
    }

    // ---- epilogue: O/l -> bf16 hi/lo ----
    const float inv0 = 1.f / l0, inv1 = 1.f / l1;
    const int r0g = q0 + w * 16 + (lane >> 2);
#pragma unroll
    for (int nf = 0; nf < 8; nf++) {
        const int col = h * DH_ + nf * 8 + (lane & 3) * 2;
        uint32_t h0, lo0, h1, lo1;
        pack2(oacc[nf][0] * inv0, oacc[nf][1] * inv0, h0, lo0);
        pack2(oacc[nf][2] * inv1, oacc[nf][3] * inv1, h1, lo1);
        size_t a0 = (size_t)(b * T_ + r0g) * C_ + col;
        size_t a1 = a0 + (size_t)8 * C_;
        *(uint32_t*)(ohi + a0) = h0;   *(uint32_t*)(olo + a0) = lo0;
        *(uint32_t*)(ohi + a1) = h1;   *(uint32_t*)(olo + a1) = lo1;
    }
}

// ---------------------------------------------------------------------------
// Launch
// ---------------------------------------------------------------------------
extern "C" void kernel_launch(void* const* d_in, const int* in_sizes, int n_in,
                              void* d_out, int out_size)
{
    const float* x     = (const float*)d_in[0];
    const float* w_qkv = (const float*)d_in[1];
    const float* b_qkv = (const float*)d_in[2];
    const float* w_out = (const float*)d_in[3];
    const float* b_out = (const float*)d_in[4];
    float* out = (float*)d_out;

    __nv_bfloat16 *xhi, *xlo, *wqhi, *wqlo, *wohi, *wolo, *qhi, *qlo, *ahi, *alo;
    cudaGetSymbolAddress((void**)&xhi,  g_xhi);
    cudaGetSymbolAddress((void**)&xlo,  g_xlo);
    cudaGetSymbolAddress((void**)&wqhi, g_wqhi);
    cudaGetSymbolAddress((void**)&wqlo, g_wqlo);
    cudaGetSymbolAddress((void**)&wohi, g_wohi);
    cudaGetSymbolAddress((void**)&wolo, g_wolo);
    cudaGetSymbolAddress((void**)&qhi,  g_qhi);
    cudaGetSymbolAddress((void**)&qlo,  g_qlo);
    cudaGetSymbolAddress((void**)&ahi,  g_ahi);
    cudaGetSymbolAddress((void**)&alo,  g_alo);

    cudaFuncSetAttribute(gemm_mma_kernel,
                         cudaFuncAttributeMaxDynamicSharedMemorySize, GEMM_SMEM);
    cudaFuncSetAttribute(attn_mma_kernel,
                         cudaFuncAttributeMaxDynamicSharedMemorySize, ATTN_SMEM);

    split_kernel<<<(M_ * C_) / 4 / 256, 256>>>(x, xhi, xlo, M_ * C_);
    transpose_split_kernel<<<dim3(C3_ / 32, C_ / 32), dim3(32, 8)>>>(
        w_qkv, wqhi, wqlo, C_, C3_);
    transpose_split_kernel<<<dim3(C_ / 32, C_ / 32), dim3(32, 8)>>>(
        w_out, wohi, wolo, C_, C_);

    // GEMM1: qkv = x @ Wqkv + b  -> bf16 hi/lo
    gemm_mma_kernel<<<dim3(C3_ / 64, M_ / 128), 256, GEMM_SMEM>>>(
        xhi, xlo, wqhi, wqlo, b_qkv, nullptr, qhi, qlo, C3_, C_);

    // attention (mma.sync) -> bf16 hi/lo
    attn_mma_kernel<<<dim3(T_ / 128, H_, B_), 256, ATTN_SMEM>>>(
        qhi, qlo, ahi, alo);

    // GEMM2: out = att @ Wout + b -> fp32
    gemm_mma_kernel<<<dim3(C_ / 64, M_ / 128), 256, GEMM_SMEM>>>(
        ahi, alo, wohi, wolo, b_out, out, nullptr, nullptr, C_, C_);
}

// round 12
// speedup vs baseline: 2.7405x; 1.1474x over previous
#include <cuda_runtime.h>
#include <cuda_fp16.h>
#include <cstdint>
#include <math.h>

// ---------------------------------------------------------------------------
// Problem:
//   x (4,2048,1024) f32; w_qkv (1024,3072); b_qkv (3072,);
//   w_out (1024,1024); b_out (1024,); out (4,2048,1024) f32
// Precision scheme (fp16, 11-bit mantissa):
//   activations: 2-term hi/lo split (exact to 2^-22)
//   projection weights: SINGLE fp16 (delta ~2.8e-4) -> GEMMs use 2 MMAs/frag
//   attention: full 3-term (Qh.Kh + Qh.Kl + Ql.Kh ; Ph.Vh + Ph.Vl + Pl.Vh)
// Rationale: mma.sync HMMA pins at ~49% tensor across all schedules (rounds
// 8/9/11) -> instruction-rate ceiling; only fewer MMAs help.
// ---------------------------------------------------------------------------
#define B_   4
#define T_   2048
#define C_   1024
#define H_   16
#define DH_  64
#define M_   (B_ * T_)       // 8192
#define C3_  (3 * C_)        // 3072

__device__ __half g_xhi[(size_t)M_ * C_];
__device__ __half g_xlo[(size_t)M_ * C_];
__device__ __half g_wqhi[(size_t)C3_ * C_];   // Wqkv^T single fp16
__device__ __half g_wohi[(size_t)C_ * C_];    // Wout^T single fp16
__device__ __half g_qhi[(size_t)M_ * C3_];    // qkv hi
__device__ __half g_qlo[(size_t)M_ * C3_];    // qkv lo
__device__ __half g_ahi[(size_t)M_ * C_];
__device__ __half g_alo[(size_t)M_ * C_];

// ---------------------------------------------------------------------------
__device__ __forceinline__ uint32_t smem_u32(const void* p) {
    uint32_t a;
    asm("{ .reg .u64 t; cvta.to.shared.u64 t, %1; cvt.u32.u64 %0, t; }"
        : "=r"(a) : "l"(p));
    return a;
}

#define LDSM4(r0, r1, r2, r3, addr) \
    asm volatile("ldmatrix.sync.aligned.m8n8.x4.shared.b16 {%0,%1,%2,%3}, [%4];" \
        : "=r"(r0), "=r"(r1), "=r"(r2), "=r"(r3) : "r"(addr))
#define LDSM4T(r0, r1, r2, r3, addr) \
    asm volatile("ldmatrix.sync.aligned.m8n8.x4.trans.shared.b16 {%0,%1,%2,%3}, [%4];" \
        : "=r"(r0), "=r"(r1), "=r"(r2), "=r"(r3) : "r"(addr))

#define MMAF(c, a, b0r, b1r) \
    asm volatile("mma.sync.aligned.m16n8k16.row.col.f32.f16.f16.f32 " \
        "{%0,%1,%2,%3}, {%4,%5,%6,%7}, {%8,%9}, {%0,%1,%2,%3};" \
        : "+f"((c)[0]), "+f"((c)[1]), "+f"((c)[2]), "+f"((c)[3]) \
        : "r"((a)[0]), "r"((a)[1]), "r"((a)[2]), "r"((a)[3]), \
          "r"(b0r), "r"(b1r))

#define CP_ASYNC16(dst, src) \
    asm volatile("cp.async.cg.shared.global [%0], [%1], 16;" :: "r"(dst), "l"(src))
#define CP_COMMIT() asm volatile("cp.async.commit_group;" ::: "memory")
#define CP_WAIT1()  asm volatile("cp.async.wait_group 1;" ::: "memory")
#define CP_WAIT0()  asm volatile("cp.async.wait_group 0;" ::: "memory")

// pack two floats -> fp16x2 hi reg + residual lo reg
__device__ __forceinline__ void pack2(float x, float y, uint32_t& hi, uint32_t& lo) {
    __half hx = __float2half(x), hy = __float2half(y);
    __half2 hh; hh.x = hx; hh.y = hy;
    hi = *reinterpret_cast<uint32_t*>(&hh);
    __half2 ll;
    ll.x = __float2half(x - __half2float(hx));
    ll.y = __float2half(y - __half2float(hy));
    lo = *reinterpret_cast<uint32_t*>(&ll);
}

// ---------------------------------------------------------------------------
// Prep kernels
// ---------------------------------------------------------------------------
__global__ __launch_bounds__(256) void split_kernel(
    const float* __restrict__ in, __half* __restrict__ hi,
    __half* __restrict__ lo, int n)
{
    int i = (blockIdx.x * 256 + threadIdx.x) * 4;
    if (i >= n) return;
    float4 v = *(const float4*)(in + i);
    uint32_t h0, l0, h1, l1;
    pack2(v.x, v.y, h0, l0);
    pack2(v.z, v.w, h1, l1);
    *(uint32_t*)(hi + i)     = h0;  *(uint32_t*)(hi + i + 2) = h1;
    *(uint32_t*)(lo + i)     = l0;  *(uint32_t*)(lo + i + 2) = l1;
}

// w[K][N] -> t[N][K], single fp16.  Block (32,8), grid (N/32, K/32).
__global__ __launch_bounds__(256) void transpose_half_kernel(
    const float* __restrict__ w, __half* __restrict__ thi, int K, int N)
{
    __shared__ float tile[32][33];
    int n0 = blockIdx.x * 32, k0 = blockIdx.y * 32;
    int tx = threadIdx.x, ty = threadIdx.y;
#pragma unroll
    for (int j = 0; j < 32; j += 8)
        tile[ty + j][tx] = w[(size_t)(k0 + ty + j) * N + n0 + tx];
    __syncthreads();
#pragma unroll
    for (int j = 0; j < 32; j += 8) {
        size_t idx = (size_t)(n0 + ty + j) * K + k0 + tx;
        thi[idx] = __float2half(tile[tx][ty + j]);
    }
}

// ---------------------------------------------------------------------------
// mma.sync GEMM: C = (Ahi+Alo) @ Bhi^T + bias    (B single fp16)
// CTA tile 128x64, BK=32, 8 warps (2x4), warp tile 64x16, 2 MMAs per frag.
// 3-stage cp.async pipeline (round-11 ordering: WAIT->sync->load->compute).
// Smem/stage: Ahi[128][40], Alo[128][40], Bhi[64][40] = 12800 elems (25600 B).
// ---------------------------------------------------------------------------
#define KSTRIDE 40
#define G_ATILE (128 * KSTRIDE)          // 5120 elems
#define G_BTILE (64 * KSTRIDE)           // 2560 elems
#define G_STAGE (2 * G_ATILE + G_BTILE)  // 12800 elems
#define G_NSTG  3
#define GEMM_SMEM (G_NSTG * G_STAGE * 2) // 76800 B

__global__ __launch_bounds__(256, 2)
void gemm_mma_kernel(
    const __half* __restrict__ Ahi, const __half* __restrict__ Alo,
    const __half* __restrict__ Bhi,
    const float* __restrict__ bias,
    float* __restrict__ Cf,
    __half* __restrict__ Chi, __half* __restrict__ Clo,
    int N, int K)
{
    extern __shared__ __half smb[];
    const uint32_t sbase = smem_u32(smb);

    const int tid  = threadIdx.x;
    const int lane = tid & 31;
    const int wid  = tid >> 5;
    const int wm   = wid >> 2;           // 0..1 -> m offset wm*64
    const int wn   = wid & 3;            // 0..3 -> n offset wn*16
    const int bx = blockIdx.x, by = blockIdx.y;

    const __half* srcs[3];
    srcs[0] = Ahi + (size_t)(by * 128) * K;   // 128 rows
    srcs[1] = Alo + (size_t)(by * 128) * K;   // 128 rows
    srcs[2] = Bhi + (size_t)(bx * 64) * K;    // 64 rows
    const uint32_t tbase[3] = {0, G_ATILE, 2 * G_ATILE};

    float acc[4][2][4];
#pragma unroll
    for (int mi = 0; mi < 4; mi++)
#pragma unroll
        for (int nf = 0; nf < 2; nf++)
#pragma unroll
            for (int r = 0; r < 4; r++) acc[mi][nf][r] = 0.f;

    // 1280 x16B chunks per stage, 5 per thread
    auto load_stage = [&](int stage, int k0) {
#pragma unroll
        for (int i = 0; i < 5; i++) {
            int idx = tid + i * 256;           // 0..1279
            int tile, r;
            if (idx < 1024) { tile = idx >> 9;  r = (idx >> 2) & 127; }
            else            { tile = 2;         r = ((idx - 1024) >> 2) & 63; }
            int c = idx & 3;                   // 16B chunk within 32-elem row
            const __half* g = srcs[tile] + (size_t)r * K + k0 + c * 8;
            uint32_t d = sbase +
                (uint32_t)(stage * G_STAGE + tbase[tile] + r * KSTRIDE + c * 8) * 2;
            CP_ASYNC16(d, g);
        }
    };

    auto compute = [&](int stage) {
        const uint32_t As_h = sbase + (uint32_t)(stage * G_STAGE) * 2;
        const uint32_t As_l = As_h + G_ATILE * 2;
        const uint32_t Bs_h = As_h + 2 * G_ATILE * 2;
#pragma unroll
        for (int ks = 0; ks < 2; ks++) {
            uint32_t a_hi[4][4], a_lo[4][4];
            uint32_t bh[4];
            const int ar = wm * 64 + (lane & 15);
            const int ac = ks * 16 + (lane >> 4) * 8;
#pragma unroll
            for (int mi = 0; mi < 4; mi++) {
                uint32_t off = (uint32_t)((ar + mi * 16) * KSTRIDE + ac) * 2;
                LDSM4(a_hi[mi][0], a_hi[mi][1], a_hi[mi][2], a_hi[mi][3], As_h + off);
                LDSM4(a_lo[mi][0], a_lo[mi][1], a_lo[mi][2], a_lo[mi][3], As_l + off);
            }
            const int br = wn * 16 + ((lane >> 4) << 3) + (lane & 7);
            const int bc = ks * 16 + ((lane >> 3) & 1) * 8;
            {
                uint32_t off = (uint32_t)(br * KSTRIDE + bc) * 2;
                LDSM4(bh[0], bh[1], bh[2], bh[3], Bs_h + off);
            }
#pragma unroll
            for (int mi = 0; mi < 4; mi++)
#pragma unroll
                for (int nf = 0; nf < 2; nf++) {
                    MMAF(acc[mi][nf], a_hi[mi], bh[nf * 2], bh[nf * 2 + 1]);
                    MMAF(acc[mi][nf], a_lo[mi], bh[nf * 2], bh[nf * 2 + 1]);
                }
        }
    };

    const int nch = K / 32;   // 32
    load_stage(0, 0);
    CP_COMMIT();
    load_stage(1, 32);
    CP_COMMIT();

    int cs = 0, ls = 2;
    for (int ch = 0; ch < nch; ch++) {
        if (ch + 1 < nch) CP_WAIT1();
        else              CP_WAIT0();
        __syncthreads();      // publish chunk-ch data; retire compute(ch-1)
        if (ch + 2 < nch) {
            load_stage(ls, (ch + 2) * 32);
            CP_COMMIT();
        }
        compute(cs);
        cs = (cs == 2) ? 0 : cs + 1;
        ls = (ls == 2) ? 0 : ls + 1;
    }

#pragma unroll
    for (int nf = 0; nf < 2; nf++) {
        const int col = bx * 64 + wn * 16 + nf * 8 + (lane & 3) * 2;
        const float b0 = bias[col], b1 = bias[col + 1];
#pragma unroll
        for (int mi = 0; mi < 4; mi++) {
            const int r0 = by * 128 + wm * 64 + mi * 16 + (lane >> 2);
            float v0 = acc[mi][nf][0] + b0, v1 = acc[mi][nf][1] + b1;
            float v2 = acc[mi][nf][2] + b0, v3 = acc[mi][nf][3] + b1;
            if (Cf) {
                float2 w0; w0.x = v0; w0.y = v1;
                float2 w1; w1.x = v2; w1.y = v3;
                *(float2*)(Cf + (size_t)r0 * N + col)       = w0;
                *(float2*)(Cf + (size_t)(r0 + 8) * N + col) = w1;
            } else {
                uint32_t h0, l0, h1, l1;
                pack2(v0, v1, h0, l0);
                pack2(v2, v3, h1, l1);
                *(uint32_t*)(Chi + (size_t)r0 * N + col)       = h0;
                *(uint32_t*)(Clo + (size_t)r0 * N + col)       = l0;
                *(uint32_t*)(Chi + (size_t)(r0 + 8) * N + col) = h1;
                *(uint32_t*)(Clo + (size_t)(r0 + 8) * N + col) = l1;
            }
        }
    }
}

// ---------------------------------------------------------------------------
// Flash attention, mma.sync fp16 3-term split, causal. (structure = R11)
// CTA: 128 q-rows x (b,h); 8 warps; K-tiles of 64 keys, double-buffered.
// ---------------------------------------------------------------------------
#define ASTR 72
#define KVT_B (64 * ASTR * 2)       // 9216 B per tile
#define ASTAGE_B (4 * KVT_B)        // 36864 B
#define Q_OFF ASTAGE_B
#define ATTN_SMEM (2 * ASTAGE_B)    // 73728 B

__global__ __launch_bounds__(256)
void attn_mma_kernel(
    const __half* __restrict__ qhi, const __half* __restrict__ qlo,
    __half* __restrict__ ohi, __half* __restrict__ olo)
{
    extern __shared__ char sma[];
    const uint32_t sb = smem_u32(sma);

    const int tid  = threadIdx.x;
    const int lane = tid & 31;
    const int w    = tid >> 5;
    const int qt = (int)gridDim.x - 1 - blockIdx.x;   // heavy tiles first
    const int h  = blockIdx.y;
    const int b  = blockIdx.z;
    const int q0 = qt * 128;
    const float scale = 0.125f;

    const __half* qsrc[2] = {qhi, qlo};

    auto load_kv = [&](int stage, int kt) {
        const int k0 = kt * 64;
#pragma unroll
        for (int i = 0; i < 8; i++) {
            int idx  = tid + i * 256;            // 0..2047
            int tile = idx >> 9;                 // 0:Khi 1:Klo 2:Vhi 3:Vlo
            int r    = (idx >> 3) & 63;
            int c    = idx & 7;
            int colb = (tile < 2) ? C_ : 2 * C_;
            const __half* g = qsrc[tile & 1] +
                (size_t)(b * T_ + k0 + r) * C3_ + colb + h * DH_ + c * 8;
            uint32_t d = sb + stage * ASTAGE_B + tile * KVT_B +
                         (uint32_t)(r * ASTR + c * 8) * 2;
            CP_ASYNC16(d, g);
        }
    };

    // ---- prologue: Q into smem (stage-1 region), then to registers ----
#pragma unroll
    for (int i = 0; i < 8; i++) {
        int idx = tid + i * 256;                 // 0..2047
        int t   = idx >> 10;                     // 0:hi 1:lo
        int r   = (idx >> 3) & 127;
        int c   = idx & 7;
        const __half* g = qsrc[t] +
            (size_t)(b * T_ + q0 + r) * C3_ + h * DH_ + c * 8;
        uint32_t d = sb + Q_OFF + t * (128 * ASTR * 2) +
                     (uint32_t)(r * ASTR + c * 8) * 2;
        CP_ASYNC16(d, g);
    }
    CP_COMMIT();
    load_kv(0, 0);
    CP_COMMIT();
    CP_WAIT1();              // Q arrived (oldest group)
    __syncthreads();

    uint32_t qf_h[4][4], qf_l[4][4];
    {
        const int r = w * 16 + (lane & 15);
        const int cb = (lane >> 4) * 8;
#pragma unroll
        for (int kf = 0; kf < 4; kf++) {
            uint32_t off = sb + Q_OFF + (uint32_t)(r * ASTR + kf * 16 + cb) * 2;
            LDSM4(qf_h[kf][0], qf_h[kf][1], qf_h[kf][2], qf_h[kf][3], off);
            LDSM4(qf_l[kf][0], qf_l[kf][1], qf_l[kf][2], qf_l[kf][3],
                  off + 128 * ASTR * 2);
        }
    }
    __syncthreads();         // Q region now reusable as stage 1

    float oacc[8][4];
#pragma unroll
    for (int nf = 0; nf < 8; nf++)
#pragma unroll
        for (int r = 0; r < 4; r++) oacc[nf][r] = 0.f;
    float m0 = -1e30f, m1 = -1e30f, l0 = 0.f, l1 = 0.f;

    const int nkt = 2 * qt + 2;
    for (int kt = 0; kt < nkt; kt++) {
        const int s = kt & 1;
        if (kt + 1 < nkt) { load_kv(s ^ 1, kt + 1); CP_COMMIT(); CP_WAIT1(); }
        else              { CP_WAIT0(); }
        __syncthreads();

        const uint32_t kb_h = sb + s * ASTAGE_B;
        const uint32_t kb_l = kb_h + KVT_B;
        const uint32_t vb_h = kb_h + 2 * KVT_B;
        const uint32_t vb_l = kb_h + 3 * KVT_B;

        // ---- S = Q K^T ----
        float sfr[8][4];
#pragma unroll
        for (int nf = 0; nf < 8; nf++)
#pragma unroll
            for (int r = 0; r < 4; r++) sfr[nf][r] = 0.f;

#pragma unroll
        for (int kf = 0; kf < 4; kf++) {
            uint32_t bh[4][4], bl[4][4];
            const int rr = (lane >> 4) * 8 + (lane & 7);
            const int cc = kf * 16 + ((lane >> 3) & 1) * 8;
#pragma unroll
            for (int p = 0; p < 4; p++) {
                uint32_t off = (uint32_t)((p * 16 + rr) * ASTR + cc) * 2;
                LDSM4(bh[p][0], bh[p][1], bh[p][2], bh[p][3], kb_h + off);
                LDSM4(bl[p][0], bl[p][1], bl[p][2], bl[p][3], kb_l + off);
            }
#pragma unroll
            for (int nf = 0; nf < 8; nf++) {
                uint32_t bh0 = bh[nf >> 1][(nf & 1) * 2];
                uint32_t bh1 = bh[nf >> 1][(nf & 1) * 2 + 1];
                uint32_t bl0 = bl[nf >> 1][(nf & 1) * 2];
                uint32_t bl1 = bl[nf >> 1][(nf & 1) * 2 + 1];
                MMAF(sfr[nf], qf_h[kf], bh0, bh1);
                MMAF(sfr[nf], qf_h[kf], bl0, bl1);
                MMAF(sfr[nf], qf_l[kf], bh0, bh1);
            }
        }

#pragma unroll
        for (int nf = 0; nf < 8; nf++)
#pragma unroll
            for (int r = 0; r < 4; r++) sfr[nf][r] *= scale;

        // ---- causal mask (last two k-tiles only) ----
        if (kt >= 2 * qt) {
            const int k0 = kt * 64;
            const int r0g = q0 + w * 16 + (lane >> 2);
            const int r1g = r0g + 8;
#pragma unroll
            for (int nf = 0; nf < 8; nf++) {
                const int c0 = k0 + nf * 8 + (lane & 3) * 2;
                if (c0     > r0g) sfr[nf][0] = -1e30f;
                if (c0 + 1 > r0g) sfr[nf][1] = -1e30f;
                if (c0     > r1g) sfr[nf][2] = -1e30f;
                if (c0 + 1 > r1g) sfr[nf][3] = -1e30f;
            }
        }

        // ---- online softmax (rows quad-local: shfl lanes^1,^2) ----
        float mx0 = -1e30f, mx1 = -1e30f;
#pragma unroll
        for (int nf = 0; nf < 8; nf++) {
            mx0 = fmaxf(mx0, fmaxf(sfr[nf][0], sfr[nf][1]));
            mx1 = fmaxf(mx1, fmaxf(sfr[nf][2], sfr[nf][3]));
        }
        mx0 = fmaxf(mx0, __shfl_xor_sync(0xffffffffu, mx0, 1));
        mx0 = fmaxf(mx0, __shfl_xor_sync(0xffffffffu, mx0, 2));
        mx1 = fmaxf(mx1, __shfl_xor_sync(0xffffffffu, mx1, 1));
        mx1 = fmaxf(mx1, __shfl_xor_sync(0xffffffffu, mx1, 2));
        const float nm0 = fmaxf(m0, mx0), nm1 = fmaxf(m1, mx1);
        const float corr0 = __expf(m0 - nm0), corr1 = __expf(m1 - nm1);
        float rs0 = 0.f, rs1 = 0.f;
#pragma unroll
        for (int nf = 0; nf < 8; nf++) {
            sfr[nf][0] = __expf(sfr[nf][0] - nm0);
            sfr[nf][1] = __expf(sfr[nf][1] - nm0);
            sfr[nf][2] = __expf(sfr[nf][2] - nm1);
            sfr[nf][3] = __expf(sfr[nf][3] - nm1);
            rs0 += sfr[nf][0] + sfr[nf][1];
            rs1 += sfr[nf][2] + sfr[nf][3];
        }
        rs0 += __shfl_xor_sync(0xffffffffu, rs0, 1);
        rs0 += __shfl_xor_sync(0xffffffffu, rs0, 2);
        rs1 += __shfl_xor_sync(0xffffffffu, rs1, 1);
        rs1 += __shfl_xor_sync(0xffffffffu, rs1, 2);
        l0 = l0 * corr0 + rs0;  m0 = nm0;
        l1 = l1 * corr1 + rs1;  m1 = nm1;
#pragma unroll
        for (int nf = 0; nf < 8; nf++) {
            oacc[nf][0] *= corr0;  oacc[nf][1] *= corr0;
            oacc[nf][2] *= corr1;  oacc[nf][3] *= corr1;
        }

        // ---- repack P (S C-frags -> A-frags, registers only) ----
        // a0=rows0-7/k0-7, a1=rows8-15/k0-7, a2=rows0-7/k8-15, a3=rows8-15/k8-15
        uint32_t pa_h[4][4], pa_l[4][4];
#pragma unroll
        for (int kf = 0; kf < 4; kf++) {
            pack2(sfr[2*kf  ][0], sfr[2*kf  ][1], pa_h[kf][0], pa_l[kf][0]);
            pack2(sfr[2*kf  ][2], sfr[2*kf  ][3], pa_h[kf][1], pa_l[kf][1]);
            pack2(sfr[2*kf+1][0], sfr[2*kf+1][1], pa_h[kf][2], pa_l[kf][2]);
            pack2(sfr[2*kf+1][2], sfr[2*kf+1][3], pa_h[kf][3], pa_l[kf][3]);
        }

        // ---- O += P V  (V via ldmatrix.trans from [key][d]) ----
#pragma unroll
        for (int kf = 0; kf < 4; kf++) {
            uint32_t vh[4][4], vl[4][4];
            const int rr = kf * 16 + (lane & 7) + ((lane >> 3) & 1) * 8;
            const int cc = (lane >> 4) * 8;
#pragma unroll
            for (int p = 0; p < 4; p++) {
                uint32_t off = (uint32_t)(rr * ASTR + p * 16 + cc) * 2;
                LDSM4T(vh[p][0], vh[p][1], vh[p][2], vh[p][3], vb_h + off);
                LDSM4T(vl[p][0], vl[p][1], vl[p][2], vl[p][3], vb_l + off);
            }
#pragma unroll
            for (int nf = 0; nf < 8; nf++) {
                uint32_t bh0 = vh[nf >> 1][(nf & 1) * 2];
                uint32_t bh1 = vh[nf >> 1][(nf & 1) * 2 + 1];
                uint32_t bl0 = vl[nf >> 1][(nf & 1) * 2];
                uint32_t bl1 = vl[nf >> 1][(nf & 1) * 2 + 1];
                MMAF(oacc[nf], pa_h[kf], bh0, bh1);
                MMAF(oacc[nf], pa_h[kf], bl0, bl1);
                MMAF(oacc[nf], pa_l[kf], bh0, bh1);
            }
        }
        __syncthreads();   // all warps done with stage s before next overwrite
    }

    // ---- epilogue: O/l -> fp16 hi/lo ----
    const float inv0 = 1.f / l0, inv1 = 1.f / l1;
    const int r0g = q0 + w * 16 + (lane >> 2);
#pragma unroll
    for (int nf = 0; nf < 8; nf++) {
        const int col = h * DH_ + nf * 8 + (lane & 3) * 2;
        uint32_t h0, lo0, h1, lo1;
        pack2(oacc[nf][0] * inv0, oacc[nf][1] * inv0, h0, lo0);
        pack2(oacc[nf][2] * inv1, oacc[nf][3] * inv1, h1, lo1);
        size_t a0 = (size_t)(b * T_ + r0g) * C_ + col;
        size_t a1 = a0 + (size_t)8 * C_;
        *(uint32_t*)(ohi + a0) = h0;   *(uint32_t*)(olo + a0) = lo0;
        *(uint32_t*)(ohi + a1) = h1;   *(uint32_t*)(olo + a1) = lo1;
    }
}

// ---------------------------------------------------------------------------
// Launch
// ---------------------------------------------------------------------------
extern "C" void kernel_launch(void* const* d_in, const int* in_sizes, int n_in,
                              void* d_out, int out_size)
{
    const float* x     = (const float*)d_in[0];
    const float* w_qkv = (const float*)d_in[1];
    const float* b_qkv = (const float*)d_in[2];
    const float* w_out = (const float*)d_in[3];
    const float* b_out = (const float*)d_in[4];
    float* out = (float*)d_out;

    __half *xhi, *xlo, *wqhi, *wohi, *qhi, *qlo, *ahi, *alo;
    cudaGetSymbolAddress((void**)&xhi,  g_xhi);
    cudaGetSymbolAddress((void**)&xlo,  g_xlo);
    cudaGetSymbolAddress((void**)&wqhi, g_wqhi);
    cudaGetSymbolAddress((void**)&wohi, g_wohi);
    cudaGetSymbolAddress((void**)&qhi,  g_qhi);
    cudaGetSymbolAddress((void**)&qlo,  g_qlo);
    cudaGetSymbolAddress((void**)&ahi,  g_ahi);
    cudaGetSymbolAddress((void**)&alo,  g_alo);

    cudaFuncSetAttribute(gemm_mma_kernel,
                         cudaFuncAttributeMaxDynamicSharedMemorySize, GEMM_SMEM);
    cudaFuncSetAttribute(attn_mma_kernel,
                         cudaFuncAttributeMaxDynamicSharedMemorySize, ATTN_SMEM);

    split_kernel<<<(M_ * C_) / 4 / 256, 256>>>(x, xhi, xlo, M_ * C_);
    transpose_half_kernel<<<dim3(C3_ / 32, C_ / 32), dim3(32, 8)>>>(
        w_qkv, wqhi, C_, C3_);
    transpose_half_kernel<<<dim3(C_ / 32, C_ / 32), dim3(32, 8)>>>(
        w_out, wohi, C_, C_);

    // GEMM1: qkv = x @ Wqkv + b  -> fp16 hi/lo
    gemm_mma_kernel<<<dim3(C3_ / 64, M_ / 128), 256, GEMM_SMEM>>>(
        xhi, xlo, wqhi, b_qkv, nullptr, qhi, qlo, C3_, C_);

    // attention (mma.sync fp16, 3-term) -> fp16 hi/lo
    attn_mma_kernel<<<dim3(T_ / 128, H_, B_), 256, ATTN_SMEM>>>(
        qhi, qlo, ahi, alo);

    // GEMM2: out = att @ Wout + b -> fp32
    gemm_mma_kernel<<<dim3(C_ / 64, M_ / 128), 256, GEMM_SMEM>>>(
        ahi, alo, wohi, b_out, out, nullptr, nullptr, C_, C_);
}

// round 13
// speedup vs baseline: 3.1269x; 1.1410x over previous
#include <cuda_runtime.h>
#include <cuda_fp16.h>
#include <cstdint>
#include <math.h>

// ---------------------------------------------------------------------------
// Problem:
//   x (4,2048,1024) f32; w_qkv (1024,3072); b_qkv (3072,);
//   w_out (1024,1024); b_out (1024,); out (4,2048,1024) f32
// Precision scheme (fp16):
//   activations: 2-term hi/lo split; projection weights: single fp16
//   attention S: 3-term (Qh.Kh + Qh.Kl + Ql.Kh)
//   attention PV: 2-term (Ph+Pl).Vh   (V single fp16; error ~2.4e-4)
// R13 changes: GEMM warp tile 64x16 -> 32x32 (LDSM -33%, L1 was 52%);
//              drop Vlo from attention (smem/loads/LDSM/MMA all shrink).
// ---------------------------------------------------------------------------
#define B_   4
#define T_   2048
#define C_   1024
#define H_   16
#define DH_  64
#define M_   (B_ * T_)       // 8192
#define C3_  (3 * C_)        // 3072

__device__ __half g_xhi[(size_t)M_ * C_];
__device__ __half g_xlo[(size_t)M_ * C_];
__device__ __half g_wqhi[(size_t)C3_ * C_];   // Wqkv^T single fp16
__device__ __half g_wohi[(size_t)C_ * C_];    // Wout^T single fp16
__device__ __half g_qhi[(size_t)M_ * C3_];    // qkv hi
__device__ __half g_qlo[(size_t)M_ * C3_];    // qkv lo
__device__ __half g_ahi[(size_t)M_ * C_];
__device__ __half g_alo[(size_t)M_ * C_];

// ---------------------------------------------------------------------------
__device__ __forceinline__ uint32_t smem_u32(const void* p) {
    uint32_t a;
    asm("{ .reg .u64 t; cvta.to.shared.u64 t, %1; cvt.u32.u64 %0, t; }"
        : "=r"(a) : "l"(p));
    return a;
}

#define LDSM4(r0, r1, r2, r3, addr) \
    asm volatile("ldmatrix.sync.aligned.m8n8.x4.shared.b16 {%0,%1,%2,%3}, [%4];" \
        : "=r"(r0), "=r"(r1), "=r"(r2), "=r"(r3) : "r"(addr))
#define LDSM4T(r0, r1, r2, r3, addr) \
    asm volatile("ldmatrix.sync.aligned.m8n8.x4.trans.shared.b16 {%0,%1,%2,%3}, [%4];" \
        : "=r"(r0), "=r"(r1), "=r"(r2), "=r"(r3) : "r"(addr))

#define MMAF(c, a, b0r, b1r) \
    asm volatile("mma.sync.aligned.m16n8k16.row.col.f32.f16.f16.f32 " \
        "{%0,%1,%2,%3}, {%4,%5,%6,%7}, {%8,%9}, {%0,%1,%2,%3};" \
        : "+f"((c)[0]), "+f"((c)[1]), "+f"((c)[2]), "+f"((c)[3]) \
        : "r"((a)[0]), "r"((a)[1]), "r"((a)[2]), "r"((a)[3]), \
          "r"(b0r), "r"(b1r))

#define CP_ASYNC16(dst, src) \
    asm volatile("cp.async.cg.shared.global [%0], [%1], 16;" :: "r"(dst), "l"(src))
#define CP_COMMIT() asm volatile("cp.async.commit_group;" ::: "memory")
#define CP_WAIT1()  asm volatile("cp.async.wait_group 1;" ::: "memory")
#define CP_WAIT0()  asm volatile("cp.async.wait_group 0;" ::: "memory")

// pack two floats -> fp16x2 hi reg + residual lo reg
__device__ __forceinline__ void pack2(float x, float y, uint32_t& hi, uint32_t& lo) {
    __half hx = __float2half(x), hy = __float2half(y);
    __half2 hh; hh.x = hx; hh.y = hy;
    hi = *reinterpret_cast<uint32_t*>(&hh);
    __half2 ll;
    ll.x = __float2half(x - __half2float(hx));
    ll.y = __float2half(y - __half2float(hy));
    lo = *reinterpret_cast<uint32_t*>(&ll);
}

// ---------------------------------------------------------------------------
// Prep kernels
// ---------------------------------------------------------------------------
__global__ __launch_bounds__(256) void split_kernel(
    const float* __restrict__ in, __half* __restrict__ hi,
    __half* __restrict__ lo, int n)
{
    int i = (blockIdx.x * 256 + threadIdx.x) * 4;
    if (i >= n) return;
    float4 v = *(const float4*)(in + i);
    uint32_t h0, l0, h1, l1;
    pack2(v.x, v.y, h0, l0);
    pack2(v.z, v.w, h1, l1);
    *(uint32_t*)(hi + i)     = h0;  *(uint32_t*)(hi + i + 2) = h1;
    *(uint32_t*)(lo + i)     = l0;  *(uint32_t*)(lo + i + 2) = l1;
}

// w[K][N] -> t[N][K], single fp16.  Block (32,8), grid (N/32, K/32).
__global__ __launch_bounds__(256) void transpose_half_kernel(
    const float* __restrict__ w, __half* __restrict__ thi, int K, int N)
{
    __shared__ float tile[32][33];
    int n0 = blockIdx.x * 32, k0 = blockIdx.y * 32;
    int tx = threadIdx.x, ty = threadIdx.y;
#pragma unroll
    for (int j = 0; j < 32; j += 8)
        tile[ty + j][tx] = w[(size_t)(k0 + ty + j) * N + n0 + tx];
    __syncthreads();
#pragma unroll
    for (int j = 0; j < 32; j += 8) {
        size_t idx = (size_t)(n0 + ty + j) * K + k0 + tx;
        thi[idx] = __float2half(tile[tx][ty + j]);
    }
}

// ---------------------------------------------------------------------------
// mma.sync GEMM: C = (Ahi+Alo) @ Bhi^T + bias    (B single fp16)
// CTA tile 128x64, BK=32, 8 warps (4x2), warp tile 32x32 (mi=2, nf=4).
// 3-stage cp.async pipeline (WAIT -> sync -> load -> compute).
// ---------------------------------------------------------------------------
#define KSTRIDE 40
#define G_ATILE (128 * KSTRIDE)          // 5120 elems
#define G_BTILE (64 * KSTRIDE)           // 2560 elems
#define G_STAGE (2 * G_ATILE + G_BTILE)  // 12800 elems
#define G_NSTG  3
#define GEMM_SMEM (G_NSTG * G_STAGE * 2) // 76800 B

__global__ __launch_bounds__(256, 2)
void gemm_mma_kernel(
    const __half* __restrict__ Ahi, const __half* __restrict__ Alo,
    const __half* __restrict__ Bhi,
    const float* __restrict__ bias,
    float* __restrict__ Cf,
    __half* __restrict__ Chi, __half* __restrict__ Clo,
    int N, int K)
{
    extern __shared__ __half smb[];
    const uint32_t sbase = smem_u32(smb);

    const int tid  = threadIdx.x;
    const int lane = tid & 31;
    const int wid  = tid >> 5;
    const int wm   = wid & 3;            // 0..3 -> m offset wm*32
    const int wn   = wid >> 2;           // 0..1 -> n offset wn*32
    const int bx = blockIdx.x, by = blockIdx.y;

    const __half* srcs[3];
    srcs[0] = Ahi + (size_t)(by * 128) * K;   // 128 rows
    srcs[1] = Alo + (size_t)(by * 128) * K;   // 128 rows
    srcs[2] = Bhi + (size_t)(bx * 64) * K;    // 64 rows
    const uint32_t tbase[3] = {0, G_ATILE, 2 * G_ATILE};

    float acc[2][4][4];
#pragma unroll
    for (int mi = 0; mi < 2; mi++)
#pragma unroll
        for (int nf = 0; nf < 4; nf++)
#pragma unroll
            for (int r = 0; r < 4; r++) acc[mi][nf][r] = 0.f;

    // 1280 x16B chunks per stage, 5 per thread
    auto load_stage = [&](int stage, int k0) {
#pragma unroll
        for (int i = 0; i < 5; i++) {
            int idx = tid + i * 256;           // 0..1279
            int tile, r;
            if (idx < 1024) { tile = idx >> 9;  r = (idx >> 2) & 127; }
            else            { tile = 2;         r = ((idx - 1024) >> 2) & 63; }
            int c = idx & 3;                   // 16B chunk within 32-elem row
            const __half* g = srcs[tile] + (size_t)r * K + k0 + c * 8;
            uint32_t d = sbase +
                (uint32_t)(stage * G_STAGE + tbase[tile] + r * KSTRIDE + c * 8) * 2;
            CP_ASYNC16(d, g);
        }
    };

    auto compute = [&](int stage) {
        const uint32_t As_h = sbase + (uint32_t)(stage * G_STAGE) * 2;
        const uint32_t As_l = As_h + G_ATILE * 2;
        const uint32_t Bs_h = As_h + 2 * G_ATILE * 2;
#pragma unroll
        for (int ks = 0; ks < 2; ks++) {
            uint32_t a_hi[2][4], a_lo[2][4];
            uint32_t bh[2][4];
            const int ar = wm * 32 + (lane & 15);
            const int ac = ks * 16 + (lane >> 4) * 8;
#pragma unroll
            for (int mi = 0; mi < 2; mi++) {
                uint32_t off = (uint32_t)((ar + mi * 16) * KSTRIDE + ac) * 2;
                LDSM4(a_hi[mi][0], a_hi[mi][1], a_hi[mi][2], a_hi[mi][3], As_h + off);
                LDSM4(a_lo[mi][0], a_lo[mi][1], a_lo[mi][2], a_lo[mi][3], As_l + off);
            }
            const int br = wn * 32 + ((lane >> 4) << 3) + (lane & 7);
            const int bc = ks * 16 + ((lane >> 3) & 1) * 8;
#pragma unroll
            for (int p = 0; p < 2; p++) {
                uint32_t off = (uint32_t)((br + p * 16) * KSTRIDE + bc) * 2;
                LDSM4(bh[p][0], bh[p][1], bh[p][2], bh[p][3], Bs_h + off);
            }
#pragma unroll
            for (int mi = 0; mi < 2; mi++)
#pragma unroll
                for (int nf = 0; nf < 4; nf++) {
                    uint32_t b0 = bh[nf >> 1][(nf & 1) * 2];
                    uint32_t b1 = bh[nf >> 1][(nf & 1) * 2 + 1];
                    MMAF(acc[mi][nf], a_hi[mi], b0, b1);
                    MMAF(acc[mi][nf], a_lo[mi], b0, b1);
                }
        }
    };

    const int nch = K / 32;   // 32
    load_stage(0, 0);
    CP_COMMIT();
    load_stage(1, 32);
    CP_COMMIT();

    int cs = 0, ls = 2;
    for (int ch = 0; ch < nch; ch++) {
        if (ch + 1 < nch) CP_WAIT1();
        else              CP_WAIT0();
        __syncthreads();      // publish chunk-ch data; retire compute(ch-1)
        if (ch + 2 < nch) {
            load_stage(ls, (ch + 2) * 32);
            CP_COMMIT();
        }
        compute(cs);
        cs = (cs == 2) ? 0 : cs + 1;
        ls = (ls == 2) ? 0 : ls + 1;
    }

#pragma unroll
    for (int nf = 0; nf < 4; nf++) {
        const int col = bx * 64 + wn * 32 + nf * 8 + (lane & 3) * 2;
        const float b0 = bias[col], b1 = bias[col + 1];
#pragma unroll
        for (int mi = 0; mi < 2; mi++) {
            const int r0 = by * 128 + wm * 32 + mi * 16 + (lane >> 2);
            float v0 = acc[mi][nf][0] + b0, v1 = acc[mi][nf][1] + b1;
            float v2 = acc[mi][nf][2] + b0, v3 = acc[mi][nf][3] + b1;
            if (Cf) {
                float2 w0; w0.x = v0; w0.y = v1;
                float2 w1; w1.x = v2; w1.y = v3;
                *(float2*)(Cf + (size_t)r0 * N + col)       = w0;
                *(float2*)(Cf + (size_t)(r0 + 8) * N + col) = w1;
            } else {
                uint32_t h0, l0, h1, l1;
                pack2(v0, v1, h0, l0);
                pack2(v2, v3, h1, l1);
                *(uint32_t*)(Chi + (size_t)r0 * N + col)       = h0;
                *(uint32_t*)(Clo + (size_t)r0 * N + col)       = l0;
                *(uint32_t*)(Chi + (size_t)(r0 + 8) * N + col) = h1;
                *(uint32_t*)(Clo + (size_t)(r0 + 8) * N + col) = l1;
            }
        }
    }
}

// ---------------------------------------------------------------------------
// Flash attention, mma.sync fp16, causal.
// S: 3-term; PV: (Ph+Pl).Vh  (single-fp16 V -> no Vlo tile).
// CTA: 128 q-rows x (b,h); 8 warps; K-tiles of 64 keys, double-buffered.
// Stage = 3 tiles (Khi, Klo, Vhi). Q staged past stage-0, consumed to regs.
// ---------------------------------------------------------------------------
#define ASTR 72
#define KVT_B (64 * ASTR * 2)       // 9216 B per tile
#define ASTAGE_B (3 * KVT_B)        // 27648 B
#define Q_OFF ASTAGE_B
#define QREG_B (128 * ASTR * 2)     // 18432 B per Q tile (hi or lo)
#define ATTN_SMEM (Q_OFF + 2 * QREG_B)   // 64512 B

__global__ __launch_bounds__(256)
void attn_mma_kernel(
    const __half* __restrict__ qhi, const __half* __restrict__ qlo,
    __half* __restrict__ ohi, __half* __restrict__ olo)
{
    extern __shared__ char sma[];
    const uint32_t sb = smem_u32(sma);

    const int tid  = threadIdx.x;
    const int lane = tid & 31;
    const int w    = tid >> 5;
    const int qt = (int)gridDim.x - 1 - blockIdx.x;   // heavy tiles first
    const int h  = blockIdx.y;
    const int b  = blockIdx.z;
    const int q0 = qt * 128;
    const float scale = 0.125f;

    const __half* qsrc[2] = {qhi, qlo};

    // 3 tiles x 64 rows x 8 chunks = 1536 chunks, 6 per thread
    auto load_kv = [&](int stage, int kt) {
        const int k0 = kt * 64;
#pragma unroll
        for (int i = 0; i < 6; i++) {
            int idx  = tid + i * 256;            // 0..1535
            int tile = idx >> 9;                 // 0:Khi 1:Klo 2:Vhi
            int r    = (idx >> 3) & 63;
            int c    = idx & 7;
            int colb = (tile < 2) ? C_ : 2 * C_;
            const __half* g = ((tile == 1) ? qlo : qhi) +
                (size_t)(b * T_ + k0 + r) * C3_ + colb + h * DH_ + c * 8;
            uint32_t d = sb + stage * ASTAGE_B + tile * KVT_B +
                         (uint32_t)(r * ASTR + c * 8) * 2;
            CP_ASYNC16(d, g);
        }
    };

    // ---- prologue: Q into smem (past stage 0; overlaps stage 1) ----
#pragma unroll
    for (int i = 0; i < 8; i++) {
        int idx = tid + i * 256;                 // 0..2047
        int t   = idx >> 10;                     // 0:hi 1:lo
        int r   = (idx >> 3) & 127;
        int c   = idx & 7;
        const __half* g = qsrc[t] +
            (size_t)(b * T_ + q0 + r) * C3_ + h * DH_ + c * 8;
        uint32_t d = sb + Q_OFF + t * QREG_B +
                     (uint32_t)(r * ASTR + c * 8) * 2;
        CP_ASYNC16(d, g);
    }
    CP_COMMIT();
    load_kv(0, 0);
    CP_COMMIT();
    CP_WAIT1();              // Q arrived (oldest group)
    __syncthreads();

    uint32_t qf_h[4][4], qf_l[4][4];
    {
        const int r = w * 16 + (lane & 15);
        const int cb = (lane >> 4) * 8;
#pragma unroll
        for (int kf = 0; kf < 4; kf++) {
            uint32_t off = sb + Q_OFF + (uint32_t)(r * ASTR + kf * 16 + cb) * 2;
            LDSM4(qf_h[kf][0], qf_h[kf][1], qf_h[kf][2], qf_h[kf][3], off);
            LDSM4(qf_l[kf][0], qf_l[kf][1], qf_l[kf][2], qf_l[kf][3],
                  off + QREG_B);
        }
    }
    __syncthreads();         // Q region now reusable as stage 1

    float oacc[8][4];
#pragma unroll
    for (int nf = 0; nf < 8; nf++)
#pragma unroll
        for (int r = 0; r < 4; r++) oacc[nf][r] = 0.f;
    float m0 = -1e30f, m1 = -1e30f, l0 = 0.f, l1 = 0.f;

    const int nkt = 2 * qt + 2;
    for (int kt = 0; kt < nkt; kt++) {
        const int s = kt & 1;
        if (kt + 1 < nkt) { load_kv(s ^ 1, kt + 1); CP_COMMIT(); CP_WAIT1(); }
        else              { CP_WAIT0(); }
        __syncthreads();

        const uint32_t kb_h = sb + s * ASTAGE_B;
        const uint32_t kb_l = kb_h + KVT_B;
        const uint32_t vb_h = kb_h + 2 * KVT_B;

        // ---- S = Q K^T (3-term) ----
        float sfr[8][4];
#pragma unroll
        for (int nf = 0; nf < 8; nf++)
#pragma unroll
            for (int r = 0; r < 4; r++) sfr[nf][r] = 0.f;

#pragma unroll
        for (int kf = 0; kf < 4; kf++) {
            uint32_t bh[4][4], bl[4][4];
            const int rr = (lane >> 4) * 8 + (lane & 7);
            const int cc = kf * 16 + ((lane >> 3) & 1) * 8;
#pragma unroll
            for (int p = 0; p < 4; p++) {
                uint32_t off = (uint32_t)((p * 16 + rr) * ASTR + cc) * 2;
                LDSM4(bh[p][0], bh[p][1], bh[p][2], bh[p][3], kb_h + off);
                LDSM4(bl[p][0], bl[p][1], bl[p][2], bl[p][3], kb_l + off);
            }
#pragma unroll
            for (int nf = 0; nf < 8; nf++) {
                uint32_t bh0 = bh[nf >> 1][(nf & 1) * 2];
                uint32_t bh1 = bh[nf >> 1][(nf & 1) * 2 + 1];
                uint32_t bl0 = bl[nf >> 1][(nf & 1) * 2];
                uint32_t bl1 = bl[nf >> 1][(nf & 1) * 2 + 1];
                MMAF(sfr[nf], qf_h[kf], bh0, bh1);
                MMAF(sfr[nf], qf_h[kf], bl0, bl1);
                MMAF(sfr[nf], qf_l[kf], bh0, bh1);
            }
        }

#pragma unroll
        for (int nf = 0; nf < 8; nf++)
#pragma unroll
            for (int r = 0; r < 4; r++) sfr[nf][r] *= scale;

        // ---- causal mask (last two k-tiles only) ----
        if (kt >= 2 * qt) {
            const int k0 = kt * 64;
            const int r0g = q0 + w * 16 + (lane >> 2);
            const int r1g = r0g + 8;
#pragma unroll
            for (int nf = 0; nf < 8; nf++) {
                const int c0 = k0 + nf * 8 + (lane & 3) * 2;
                if (c0     > r0g) sfr[nf][0] = -1e30f;
                if (c0 + 1 > r0g) sfr[nf][1] = -1e30f;
                if (c0     > r1g) sfr[nf][2] = -1e30f;
                if (c0 + 1 > r1g) sfr[nf][3] = -1e30f;
            }
        }

        // ---- online softmax (rows quad-local: shfl lanes^1,^2) ----
        float mx0 = -1e30f, mx1 = -1e30f;
#pragma unroll
        for (int nf = 0; nf < 8; nf++) {
            mx0 = fmaxf(mx0, fmaxf(sfr[nf][0], sfr[nf][1]));
            mx1 = fmaxf(mx1, fmaxf(sfr[nf][2], sfr[nf][3]));
        }
        mx0 = fmaxf(mx0, __shfl_xor_sync(0xffffffffu, mx0, 1));
        mx0 = fmaxf(mx0, __shfl_xor_sync(0xffffffffu, mx0, 2));
        mx1 = fmaxf(mx1, __shfl_xor_sync(0xffffffffu, mx1, 1));
        mx1 = fmaxf(mx1, __shfl_xor_sync(0xffffffffu, mx1, 2));
        const float nm0 = fmaxf(m0, mx0), nm1 = fmaxf(m1, mx1);
        const float corr0 = __expf(m0 - nm0), corr1 = __expf(m1 - nm1);
        float rs0 = 0.f, rs1 = 0.f;
#pragma unroll
        for (int nf = 0; nf < 8; nf++) {
            sfr[nf][0] = __expf(sfr[nf][0] - nm0);
            sfr[nf][1] = __expf(sfr[nf][1] - nm0);
            sfr[nf][2] = __expf(sfr[nf][2] - nm1);
            sfr[nf][3] = __expf(sfr[nf][3] - nm1);
            rs0 += sfr[nf][0] + sfr[nf][1];
            rs1 += sfr[nf][2] + sfr[nf][3];
        }
        rs0 += __shfl_xor_sync(0xffffffffu, rs0, 1);
        rs0 += __shfl_xor_sync(0xffffffffu, rs0, 2);
        rs1 += __shfl_xor_sync(0xffffffffu, rs1, 1);
        rs1 += __shfl_xor_sync(0xffffffffu, rs1, 2);
        l0 = l0 * corr0 + rs0;  m0 = nm0;
        l1 = l1 * corr1 + rs1;  m1 = nm1;
#pragma unroll
        for (int nf = 0; nf < 8; nf++) {
            oacc[nf][0] *= corr0;  oacc[nf][1] *= corr0;
            oacc[nf][2] *= corr1;  oacc[nf][3] *= corr1;
        }

        // ---- repack P (S C-frags -> A-frags, registers only) ----
        // a0=rows0-7/k0-7, a1=rows8-15/k0-7, a2=rows0-7/k8-15, a3=rows8-15/k8-15
        uint32_t pa_h[4][4], pa_l[4][4];
#pragma unroll
        for (int kf = 0; kf < 4; kf++) {
            pack2(sfr[2*kf  ][0], sfr[2*kf  ][1], pa_h[kf][0], pa_l[kf][0]);
            pack2(sfr[2*kf  ][2], sfr[2*kf  ][3], pa_h[kf][1], pa_l[kf][1]);
            pack2(sfr[2*kf+1][0], sfr[2*kf+1][1], pa_h[kf][2], pa_l[kf][2]);
            pack2(sfr[2*kf+1][2], sfr[2*kf+1][3], pa_h[kf][3], pa_l[kf][3]);
        }

        // ---- O += (Ph+Pl) Vh  (V via ldmatrix.trans from [key][d]) ----
#pragma unroll
        for (int kf = 0; kf < 4; kf++) {
            uint32_t vh[4][4];
            const int rr = kf * 16 + (lane & 7) + ((lane >> 3) & 1) * 8;
            const int cc = (lane >> 4) * 8;
#pragma unroll
            for (int p = 0; p < 4; p++) {
                uint32_t off = (uint32_t)(rr * ASTR + p * 16 + cc) * 2;
                LDSM4T(vh[p][0], vh[p][1], vh[p][2], vh[p][3], vb_h + off);
            }
#pragma unroll
            for (int nf = 0; nf < 8; nf++) {
                uint32_t bh0 = vh[nf >> 1][(nf & 1) * 2];
                uint32_t bh1 = vh[nf >> 1][(nf & 1) * 2 + 1];
                MMAF(oacc[nf], pa_h[kf], bh0, bh1);
                MMAF(oacc[nf], pa_l[kf], bh0, bh1);
            }
        }
        __syncthreads();   // all warps done with stage s before next overwrite
    }

    // ---- epilogue: O/l -> fp16 hi/lo ----
    const float inv0 = 1.f / l0, inv1 = 1.f / l1;
    const int r0g = q0 + w * 16 + (lane >> 2);
#pragma unroll
    for (int nf = 0; nf < 8; nf++) {
        const int col = h * DH_ + nf * 8 + (lane & 3) * 2;
        uint32_t h0, lo0, h1, lo1;
        pack2(oacc[nf][0] * inv0, oacc[nf][1] * inv0, h0, lo0);
        pack2(oacc[nf][2] * inv1, oacc[nf][3] * inv1, h1, lo1);
        size_t a0 = (size_t)(b * T_ + r0g) * C_ + col;
        size_t a1 = a0 + (size_t)8 * C_;
        *(uint32_t*)(ohi + a0) = h0;   *(uint32_t*)(olo + a0) = lo0;
        *(uint32_t*)(ohi + a1) = h1;   *(uint32_t*)(olo + a1) = lo1;
    }
}

// ---------------------------------------------------------------------------
// Launch
// ---------------------------------------------------------------------------
extern "C" void kernel_launch(void* const* d_in, const int* in_sizes, int n_in,
                              void* d_out, int out_size)
{
    const float* x     = (const float*)d_in[0];
    const float* w_qkv = (const float*)d_in[1];
    const float* b_qkv = (const float*)d_in[2];
    const float* w_out = (const float*)d_in[3];
    const float* b_out = (const float*)d_in[4];
    float* out = (float*)d_out;

    __half *xhi, *xlo, *wqhi, *wohi, *qhi, *qlo, *ahi, *alo;
    cudaGetSymbolAddress((void**)&xhi,  g_xhi);
    cudaGetSymbolAddress((void**)&xlo,  g_xlo);
    cudaGetSymbolAddress((void**)&wqhi, g_wqhi);
    cudaGetSymbolAddress((void**)&wohi, g_wohi);
    cudaGetSymbolAddress((void**)&qhi,  g_qhi);
    cudaGetSymbolAddress((void**)&qlo,  g_qlo);
    cudaGetSymbolAddress((void**)&ahi,  g_ahi);
    cudaGetSymbolAddress((void**)&alo,  g_alo);

    cudaFuncSetAttribute(gemm_mma_kernel,
                         cudaFuncAttributeMaxDynamicSharedMemorySize, GEMM_SMEM);
    cudaFuncSetAttribute(attn_mma_kernel,
                         cudaFuncAttributeMaxDynamicSharedMemorySize, ATTN_SMEM);

    split_kernel<<<(M_ * C_) / 4 / 256, 256>>>(x, xhi, xlo, M_ * C_);
    transpose_half_kernel<<<dim3(C3_ / 32, C_ / 32), dim3(32, 8)>>>(
        w_qkv, wqhi, C_, C3_);
    transpose_half_kernel<<<dim3(C_ / 32, C_ / 32), dim3(32, 8)>>>(
        w_out, wohi, C_, C_);

    // GEMM1: qkv = x @ Wqkv + b  -> fp16 hi/lo
    gemm_mma_kernel<<<dim3(C3_ / 64, M_ / 128), 256, GEMM_SMEM>>>(
        xhi, xlo, wqhi, b_qkv, nullptr, qhi, qlo, C3_, C_);

    // attention (mma.sync fp16) -> fp16 hi/lo
    attn_mma_kernel<<<dim3(T_ / 128, H_, B_), 256, ATTN_SMEM>>>(
        qhi, qlo, ahi, alo);

    // GEMM2: out = att @ Wout + b -> fp32
    gemm_mma_kernel<<<dim3(C_ / 64, M_ / 128), 256, GEMM_SMEM>>>(
        ahi, alo, wohi, b_out, out, nullptr, nullptr, C_, C_);
}

// round 14
// speedup vs baseline: 4.0075x; 1.2817x over previous
#include <cuda_runtime.h>
#include <cuda_fp16.h>
#include <cstdint>
#include <math.h>

// ---------------------------------------------------------------------------
// Problem:
//   x (4,2048,1024) f32; w_qkv (1024,3072); b_qkv (3072,);
//   w_out (1024,1024); b_out (1024,); out (4,2048,1024) f32
// Precision scheme (fp16):
//   GEMM1: single-fp16 x  @ single-fp16 Wqkv   (1 MMA term)
//   qkv stored hi/lo (exact split of GEMM1's fp32 result)
//   attention S: 3-term (Qh.Kh + Qh.Kl + Ql.Kh); PV: (Ph+Pl).Vh
//   GEMM2: single-fp16 a  @ single-fp16 Wout   (1 MMA term)
// Rationale: HMMA issue ceiling (~49% tensor) immovable by scheduling
// (rounds 8/9/11); error budget has 2x margin -> cut MMA count again.
// ---------------------------------------------------------------------------
#define B_   4
#define T_   2048
#define C_   1024
#define H_   16
#define DH_  64
#define M_   (B_ * T_)       // 8192
#define C3_  (3 * C_)        // 3072

__device__ __half g_xh[(size_t)M_ * C_];      // x single fp16
__device__ __half g_wqhi[(size_t)C3_ * C_];   // Wqkv^T single fp16
__device__ __half g_wohi[(size_t)C_ * C_];    // Wout^T single fp16
__device__ __half g_qhi[(size_t)M_ * C3_];    // qkv hi
__device__ __half g_qlo[(size_t)M_ * C3_];    // qkv lo
__device__ __half g_ahi[(size_t)M_ * C_];     // attention out single fp16

// ---------------------------------------------------------------------------
__device__ __forceinline__ uint32_t smem_u32(const void* p) {
    uint32_t a;
    asm("{ .reg .u64 t; cvta.to.shared.u64 t, %1; cvt.u32.u64 %0, t; }"
        : "=r"(a) : "l"(p));
    return a;
}

#define LDSM4(r0, r1, r2, r3, addr) \
    asm volatile("ldmatrix.sync.aligned.m8n8.x4.shared.b16 {%0,%1,%2,%3}, [%4];" \
        : "=r"(r0), "=r"(r1), "=r"(r2), "=r"(r3) : "r"(addr))
#define LDSM4T(r0, r1, r2, r3, addr) \
    asm volatile("ldmatrix.sync.aligned.m8n8.x4.trans.shared.b16 {%0,%1,%2,%3}, [%4];" \
        : "=r"(r0), "=r"(r1), "=r"(r2), "=r"(r3) : "r"(addr))

#define MMAF(c, a, b0r, b1r) \
    asm volatile("mma.sync.aligned.m16n8k16.row.col.f32.f16.f16.f32 " \
        "{%0,%1,%2,%3}, {%4,%5,%6,%7}, {%8,%9}, {%0,%1,%2,%3};" \
        : "+f"((c)[0]), "+f"((c)[1]), "+f"((c)[2]), "+f"((c)[3]) \
        : "r"((a)[0]), "r"((a)[1]), "r"((a)[2]), "r"((a)[3]), \
          "r"(b0r), "r"(b1r))

#define CP_ASYNC16(dst, src) \
    asm volatile("cp.async.cg.shared.global [%0], [%1], 16;" :: "r"(dst), "l"(src))
#define CP_COMMIT() asm volatile("cp.async.commit_group;" ::: "memory")
#define CP_WAIT1()  asm volatile("cp.async.wait_group 1;" ::: "memory")
#define CP_WAIT0()  asm volatile("cp.async.wait_group 0;" ::: "memory")

// pack two floats -> fp16x2 hi reg + residual lo reg
__device__ __forceinline__ void pack2(float x, float y, uint32_t& hi, uint32_t& lo) {
    __half hx = __float2half(x), hy = __float2half(y);
    __half2 hh; hh.x = hx; hh.y = hy;
    hi = *reinterpret_cast<uint32_t*>(&hh);
    __half2 ll;
    ll.x = __float2half(x - __half2float(hx));
    ll.y = __float2half(y - __half2float(hy));
    lo = *reinterpret_cast<uint32_t*>(&ll);
}

// ---------------------------------------------------------------------------
// Prep kernels
// ---------------------------------------------------------------------------
__global__ __launch_bounds__(256) void convert_half_kernel(
    const float* __restrict__ in, __half* __restrict__ out, int n)
{
    int i = (blockIdx.x * 256 + threadIdx.x) * 4;
    if (i >= n) return;
    float4 v = *(const float4*)(in + i);
    __half2 a; a.x = __float2half(v.x); a.y = __float2half(v.y);
    __half2 b; b.x = __float2half(v.z); b.y = __float2half(v.w);
    *(__half2*)(out + i)     = a;
    *(__half2*)(out + i + 2) = b;
}

// w[K][N] -> t[N][K], single fp16.  Block (32,8), grid (N/32, K/32).
__global__ __launch_bounds__(256) void transpose_half_kernel(
    const float* __restrict__ w, __half* __restrict__ thi, int K, int N)
{
    __shared__ float tile[32][33];
    int n0 = blockIdx.x * 32, k0 = blockIdx.y * 32;
    int tx = threadIdx.x, ty = threadIdx.y;
#pragma unroll
    for (int j = 0; j < 32; j += 8)
        tile[ty + j][tx] = w[(size_t)(k0 + ty + j) * N + n0 + tx];
    __syncthreads();
#pragma unroll
    for (int j = 0; j < 32; j += 8) {
        size_t idx = (size_t)(n0 + ty + j) * K + k0 + tx;
        thi[idx] = __float2half(tile[tx][ty + j]);
    }
}

// ---------------------------------------------------------------------------
// mma.sync GEMM: C = A @ B^T + bias      (A, B single fp16, 1 MMA term)
// CTA tile 128x64, BK=32, 8 warps (4x2), warp tile 32x32 (mi=2, nf=4).
// 3-stage cp.async pipeline (WAIT -> sync -> load -> compute).
// Smem/stage: A[128][40] + B[64][40] = 7680 elems (15360 B); 3 stg = 46080 B.
// ---------------------------------------------------------------------------
#define KSTRIDE 40
#define G_ATILE (128 * KSTRIDE)          // 5120 elems
#define G_BTILE (64 * KSTRIDE)           // 2560 elems
#define G_STAGE (G_ATILE + G_BTILE)      // 7680 elems
#define G_NSTG  3
#define GEMM_SMEM (G_NSTG * G_STAGE * 2) // 46080 B

__global__ __launch_bounds__(256, 2)
void gemm_mma_kernel(
    const __half* __restrict__ A, const __half* __restrict__ Bm,
    const float* __restrict__ bias,
    float* __restrict__ Cf,
    __half* __restrict__ Chi, __half* __restrict__ Clo,
    int N, int K)
{
    extern __shared__ __half smb[];
    const uint32_t sbase = smem_u32(smb);

    const int tid  = threadIdx.x;
    const int lane = tid & 31;
    const int wid  = tid >> 5;
    const int wm   = wid & 3;            // 0..3 -> m offset wm*32
    const int wn   = wid >> 2;           // 0..1 -> n offset wn*32
    const int bx = blockIdx.x, by = blockIdx.y;

    const __half* Ab = A  + (size_t)(by * 128) * K;   // 128 rows
    const __half* Bb = Bm + (size_t)(bx * 64) * K;    // 64 rows

    float acc[2][4][4];
#pragma unroll
    for (int mi = 0; mi < 2; mi++)
#pragma unroll
        for (int nf = 0; nf < 4; nf++)
#pragma unroll
            for (int r = 0; r < 4; r++) acc[mi][nf][r] = 0.f;

    // 768 x16B chunks per stage, 3 per thread
    auto load_stage = [&](int stage, int k0) {
#pragma unroll
        for (int i = 0; i < 3; i++) {
            int idx = tid + i * 256;           // 0..767
            const __half* g;
            uint32_t toff;
            if (idx < 512) {                   // A: 128 rows x 4 chunks
                int r = idx >> 2;
                g = Ab + (size_t)r * K + k0 + (idx & 3) * 8;
                toff = (uint32_t)(r * KSTRIDE + (idx & 3) * 8);
            } else {                           // B: 64 rows x 4 chunks
                int j = idx - 512;
                int r = j >> 2;
                g = Bb + (size_t)r * K + k0 + (j & 3) * 8;
                toff = (uint32_t)(G_ATILE + r * KSTRIDE + (j & 3) * 8);
            }
            uint32_t d = sbase + (uint32_t)(stage * G_STAGE + toff) * 2;
            CP_ASYNC16(d, g);
        }
    };

    auto compute = [&](int stage) {
        const uint32_t As = sbase + (uint32_t)(stage * G_STAGE) * 2;
        const uint32_t Bs = As + G_ATILE * 2;
#pragma unroll
        for (int ks = 0; ks < 2; ks++) {
            uint32_t a[2][4];
            uint32_t bh[2][4];
            const int ar = wm * 32 + (lane & 15);
            const int ac = ks * 16 + (lane >> 4) * 8;
#pragma unroll
            for (int mi = 0; mi < 2; mi++) {
                uint32_t off = (uint32_t)((ar + mi * 16) * KSTRIDE + ac) * 2;
                LDSM4(a[mi][0], a[mi][1], a[mi][2], a[mi][3], As + off);
            }
            const int br = wn * 32 + ((lane >> 4) << 3) + (lane & 7);
            const int bc = ks * 16 + ((lane >> 3) & 1) * 8;
#pragma unroll
            for (int p = 0; p < 2; p++) {
                uint32_t off = (uint32_t)((br + p * 16) * KSTRIDE + bc) * 2;
                LDSM4(bh[p][0], bh[p][1], bh[p][2], bh[p][3], Bs + off);
            }
#pragma unroll
            for (int mi = 0; mi < 2; mi++)
#pragma unroll
                for (int nf = 0; nf < 4; nf++) {
                    uint32_t b0 = bh[nf >> 1][(nf & 1) * 2];
                    uint32_t b1 = bh[nf >> 1][(nf & 1) * 2 + 1];
                    MMAF(acc[mi][nf], a[mi], b0, b1);
                }
        }
    };

    const int nch = K / 32;   // 32
    load_stage(0, 0);
    CP_COMMIT();
    load_stage(1, 32);
    CP_COMMIT();

    int cs = 0, ls = 2;
    for (int ch = 0; ch < nch; ch++) {
        if (ch + 1 < nch) CP_WAIT1();
        else              CP_WAIT0();
        __syncthreads();      // publish chunk-ch data; retire compute(ch-1)
        if (ch + 2 < nch) {
            load_stage(ls, (ch + 2) * 32);
            CP_COMMIT();
        }
        compute(cs);
        cs = (cs == 2) ? 0 : cs + 1;
        ls = (ls == 2) ? 0 : ls + 1;
    }

#pragma unroll
    for (int nf = 0; nf < 4; nf++) {
        const int col = bx * 64 + wn * 32 + nf * 8 + (lane & 3) * 2;
        const float b0 = bias[col], b1 = bias[col + 1];
#pragma unroll
        for (int mi = 0; mi < 2; mi++) {
            const int r0 = by * 128 + wm * 32 + mi * 16 + (lane >> 2);
            float v0 = acc[mi][nf][0] + b0, v1 = acc[mi][nf][1] + b1;
            float v2 = acc[mi][nf][2] + b0, v3 = acc[mi][nf][3] + b1;
            if (Cf) {
                float2 w0; w0.x = v0; w0.y = v1;
                float2 w1; w1.x = v2; w1.y = v3;
                *(float2*)(Cf + (size_t)r0 * N + col)       = w0;
                *(float2*)(Cf + (size_t)(r0 + 8) * N + col) = w1;
            } else {
                uint32_t h0, l0, h1, l1;
                pack2(v0, v1, h0, l0);
                pack2(v2, v3, h1, l1);
                *(uint32_t*)(Chi + (size_t)r0 * N + col)       = h0;
                *(uint32_t*)(Clo + (size_t)r0 * N + col)       = l0;
                *(uint32_t*)(Chi + (size_t)(r0 + 8) * N + col) = h1;
                *(uint32_t*)(Clo + (size_t)(r0 + 8) * N + col) = l1;
            }
        }
    }
}

// ---------------------------------------------------------------------------
// Flash attention, mma.sync fp16, causal. (structure = R13)
// S: 3-term; PV: (Ph+Pl).Vh.  Epilogue: single-fp16 output.
// CTA: 128 q-rows x (b,h); 8 warps; K-tiles of 64 keys, double-buffered.
// Stage = 3 tiles (Khi, Klo, Vhi).
// ---------------------------------------------------------------------------
#define ASTR 72
#define KVT_B (64 * ASTR * 2)       // 9216 B per tile
#define ASTAGE_B (3 * KVT_B)        // 27648 B
#define Q_OFF ASTAGE_B
#define QREG_B (128 * ASTR * 2)     // 18432 B per Q tile (hi or lo)
#define ATTN_SMEM (Q_OFF + 2 * QREG_B)   // 64512 B

__global__ __launch_bounds__(256)
void attn_mma_kernel(
    const __half* __restrict__ qhi, const __half* __restrict__ qlo,
    __half* __restrict__ ohi)
{
    extern __shared__ char sma[];
    const uint32_t sb = smem_u32(sma);

    const int tid  = threadIdx.x;
    const int lane = tid & 31;
    const int w    = tid >> 5;
    const int qt = (int)gridDim.x - 1 - blockIdx.x;   // heavy tiles first
    const int h  = blockIdx.y;
    const int b  = blockIdx.z;
    const int q0 = qt * 128;
    const float scale = 0.125f;

    const __half* qsrc[2] = {qhi, qlo};

    // 3 tiles x 64 rows x 8 chunks = 1536 chunks, 6 per thread
    auto load_kv = [&](int stage, int kt) {
        const int k0 = kt * 64;
#pragma unroll
        for (int i = 0; i < 6; i++) {
            int idx  = tid + i * 256;            // 0..1535
            int tile = idx >> 9;                 // 0:Khi 1:Klo 2:Vhi
            int r    = (idx >> 3) & 63;
            int c    = idx & 7;
            int colb = (tile < 2) ? C_ : 2 * C_;
            const __half* g = ((tile == 1) ? qlo : qhi) +
                (size_t)(b * T_ + k0 + r) * C3_ + colb + h * DH_ + c * 8;
            uint32_t d = sb + stage * ASTAGE_B + tile * KVT_B +
                         (uint32_t)(r * ASTR + c * 8) * 2;
            CP_ASYNC16(d, g);
        }
    };

    // ---- prologue: Q into smem (past stage 0), then to registers ----
#pragma unroll
    for (int i = 0; i < 8; i++) {
        int idx = tid + i * 256;                 // 0..2047
        int t   = idx >> 10;                     // 0:hi 1:lo
        int r   = (idx >> 3) & 127;
        int c   = idx & 7;
        const __half* g = qsrc[t] +
            (size_t)(b * T_ + q0 + r) * C3_ + h * DH_ + c * 8;
        uint32_t d = sb + Q_OFF + t * QREG_B +
                     (uint32_t)(r * ASTR + c * 8) * 2;
        CP_ASYNC16(d, g);
    }
    CP_COMMIT();
    load_kv(0, 0);
    CP_COMMIT();
    CP_WAIT1();              // Q arrived (oldest group)
    __syncthreads();

    uint32_t qf_h[4][4], qf_l[4][4];
    {
        const int r = w * 16 + (lane & 15);
        const int cb = (lane >> 4) * 8;
#pragma unroll
        for (int kf = 0; kf < 4; kf++) {
            uint32_t off = sb + Q_OFF + (uint32_t)(r * ASTR + kf * 16 + cb) * 2;
            LDSM4(qf_h[kf][0], qf_h[kf][1], qf_h[kf][2], qf_h[kf][3], off);
            LDSM4(qf_l[kf][0], qf_l[kf][1], qf_l[kf][2], qf_l[kf][3],
                  off + QREG_B);
        }
    }
    __syncthreads();         // Q region now reusable as stage 1

    float oacc[8][4];
#pragma unroll
    for (int nf = 0; nf < 8; nf++)
#pragma unroll
        for (int r = 0; r < 4; r++) oacc[nf][r] = 0.f;
    float m0 = -1e30f, m1 = -1e30f, l0 = 0.f, l1 = 0.f;

    const int nkt = 2 * qt + 2;
    for (int kt = 0; kt < nkt; kt++) {
        const int s = kt & 1;
        if (kt + 1 < nkt) { load_kv(s ^ 1, kt + 1); CP_COMMIT(); CP_WAIT1(); }
        else              { CP_WAIT0(); }
        __syncthreads();

        const uint32_t kb_h = sb + s * ASTAGE_B;
        const uint32_t kb_l = kb_h + KVT_B;
        const uint32_t vb_h = kb_h + 2 * KVT_B;

        // ---- S = Q K^T (3-term) ----
        float sfr[8][4];
#pragma unroll
        for (int nf = 0; nf < 8; nf++)
#pragma unroll
            for (int r = 0; r < 4; r++) sfr[nf][r] = 0.f;

#pragma unroll
        for (int kf = 0; kf < 4; kf++) {
            uint32_t bh[4][4], bl[4][4];
            const int rr = (lane >> 4) * 8 + (lane & 7);
            const int cc = kf * 16 + ((lane >> 3) & 1) * 8;
#pragma unroll
            for (int p = 0; p < 4; p++) {
                uint32_t off = (uint32_t)((p * 16 + rr) * ASTR + cc) * 2;
                LDSM4(bh[p][0], bh[p][1], bh[p][2], bh[p][3], kb_h + off);
                LDSM4(bl[p][0], bl[p][1], bl[p][2], bl[p][3], kb_l + off);
            }
#pragma unroll
            for (int nf = 0; nf < 8; nf++) {
                uint32_t bh0 = bh[nf >> 1][(nf & 1) * 2];
                uint32_t bh1 = bh[nf >> 1][(nf & 1) * 2 + 1];
                uint32_t bl0 = bl[nf >> 1][(nf & 1) * 2];
                uint32_t bl1 = bl[nf >> 1][(nf & 1) * 2 + 1];
                MMAF(sfr[nf], qf_h[kf], bh0, bh1);
                MMAF(sfr[nf], qf_h[kf], bl0, bl1);
                MMAF(sfr[nf], qf_l[kf], bh0, bh1);
            }
        }

#pragma unroll
        for (int nf = 0; nf < 8; nf++)
#pragma unroll
            for (int r = 0; r < 4; r++) sfr[nf][r] *= scale;

        // ---- causal mask (last two k-tiles only) ----
        if (kt >= 2 * qt) {
            const int k0 = kt * 64;
            const int r0g = q0 + w * 16 + (lane >> 2);
            const int r1g = r0g + 8;
#pragma unroll
            for (int nf = 0; nf < 8; nf++) {
                const int c0 = k0 + nf * 8 + (lane & 3) * 2;
                if (c0     > r0g) sfr[nf][0] = -1e30f;
                if (c0 + 1 > r0g) sfr[nf][1] = -1e30f;
                if (c0     > r1g) sfr[nf][2] = -1e30f;
                if (c0 + 1 > r1g) sfr[nf][3] = -1e30f;
            }
        }

        // ---- online softmax (rows quad-local: shfl lanes^1,^2) ----
        float mx0 = -1e30f, mx1 = -1e30f;
#pragma unroll
        for (int nf = 0; nf < 8; nf++) {
            mx0 = fmaxf(mx0, fmaxf(sfr[nf][0], sfr[nf][1]));
            mx1 = fmaxf(mx1, fmaxf(sfr[nf][2], sfr[nf][3]));
        }
        mx0 = fmaxf(mx0, __shfl_xor_sync(0xffffffffu, mx0, 1));
        mx0 = fmaxf(mx0, __shfl_xor_sync(0xffffffffu, mx0, 2));
        mx1 = fmaxf(mx1, __shfl_xor_sync(0xffffffffu, mx1, 1));
        mx1 = fmaxf(mx1, __shfl_xor_sync(0xffffffffu, mx1, 2));
        const float nm0 = fmaxf(m0, mx0), nm1 = fmaxf(m1, mx1);
        const float corr0 = __expf(m0 - nm0), corr1 = __expf(m1 - nm1);
        float rs0 = 0.f, rs1 = 0.f;
#pragma unroll
        for (int nf = 0; nf < 8; nf++) {
            sfr[nf][0] = __expf(sfr[nf][0] - nm0);
            sfr[nf][1] = __expf(sfr[nf][1] - nm0);
            sfr[nf][2] = __expf(sfr[nf][2] - nm1);
            sfr[nf][3] = __expf(sfr[nf][3] - nm1);
            rs0 += sfr[nf][0] + sfr[nf][1];
            rs1 += sfr[nf][2] + sfr[nf][3];
        }
        rs0 += __shfl_xor_sync(0xffffffffu, rs0, 1);
        rs0 += __shfl_xor_sync(0xffffffffu, rs0, 2);
        rs1 += __shfl_xor_sync(0xffffffffu, rs1, 1);
        rs1 += __shfl_xor_sync(0xffffffffu, rs1, 2);
        l0 = l0 * corr0 + rs0;  m0 = nm0;
        l1 = l1 * corr1 + rs1;  m1 = nm1;
#pragma unroll
        for (int nf = 0; nf < 8; nf++) {
            oacc[nf][0] *= corr0;  oacc[nf][1] *= corr0;
            oacc[nf][2] *= corr1;  oacc[nf][3] *= corr1;
        }

        // ---- repack P (S C-frags -> A-frags, registers only) ----
        // a0=rows0-7/k0-7, a1=rows8-15/k0-7, a2=rows0-7/k8-15, a3=rows8-15/k8-15
        uint32_t pa_h[4][4], pa_l[4][4];
#pragma unroll
        for (int kf = 0; kf < 4; kf++) {
            pack2(sfr[2*kf  ][0], sfr[2*kf  ][1], pa_h[kf][0], pa_l[kf][0]);
            pack2(sfr[2*kf  ][2], sfr[2*kf  ][3], pa_h[kf][1], pa_l[kf][1]);
            pack2(sfr[2*kf+1][0], sfr[2*kf+1][1], pa_h[kf][2], pa_l[kf][2]);
            pack2(sfr[2*kf+1][2], sfr[2*kf+1][3], pa_h[kf][3], pa_l[kf][3]);
        }

        // ---- O += (Ph+Pl) Vh  (V via ldmatrix.trans from [key][d]) ----
#pragma unroll
        for (int kf = 0; kf < 4; kf++) {
            uint32_t vh[4][4];
            const int rr = kf * 16 + (lane & 7) + ((lane >> 3) & 1) * 8;
            const int cc = (lane >> 4) * 8;
#pragma unroll
            for (int p = 0; p < 4; p++) {
                uint32_t off = (uint32_t)(rr * ASTR + p * 16 + cc) * 2;
                LDSM4T(vh[p][0], vh[p][1], vh[p][2], vh[p][3], vb_h + off);
            }
#pragma unroll
            for (int nf = 0; nf < 8; nf++) {
                uint32_t bh0 = vh[nf >> 1][(nf & 1) * 2];
                uint32_t bh1 = vh[nf >> 1][(nf & 1) * 2 + 1];
                MMAF(oacc[nf], pa_h[kf], bh0, bh1);
                MMAF(oacc[nf], pa_l[kf], bh0, bh1);
            }
        }
        __syncthreads();   // all warps done with stage s before next overwrite
    }

    // ---- epilogue: O/l -> single fp16 ----
    const float inv0 = 1.f / l0, inv1 = 1.f / l1;
    const int r0g = q0 + w * 16 + (lane >> 2);
#pragma unroll
    for (int nf = 0; nf < 8; nf++) {
        const int col = h * DH_ + nf * 8 + (lane & 3) * 2;
        __half2 h0, h1;
        h0.x = __float2half(oacc[nf][0] * inv0);
        h0.y = __float2half(oacc[nf][1] * inv0);
        h1.x = __float2half(oacc[nf][2] * inv1);
        h1.y = __float2half(oacc[nf][3] * inv1);
        size_t a0 = (size_t)(b * T_ + r0g) * C_ + col;
        size_t a1 = a0 + (size_t)8 * C_;
        *(__half2*)(ohi + a0) = h0;
        *(__half2*)(ohi + a1) = h1;
    }
}

// ---------------------------------------------------------------------------
// Launch
// ---------------------------------------------------------------------------
extern "C" void kernel_launch(void* const* d_in, const int* in_sizes, int n_in,
                              void* d_out, int out_size)
{
    const float* x     = (const float*)d_in[0];
    const float* w_qkv = (const float*)d_in[1];
    const float* b_qkv = (const float*)d_in[2];
    const float* w_out = (const float*)d_in[3];
    const float* b_out = (const float*)d_in[4];
    float* out = (float*)d_out;

    __half *xh, *wqhi, *wohi, *qhi, *qlo, *ahi;
    cudaGetSymbolAddress((void**)&xh,   g_xh);
    cudaGetSymbolAddress((void**)&wqhi, g_wqhi);
    cudaGetSymbolAddress((void**)&wohi, g_wohi);
    cudaGetSymbolAddress((void**)&qhi,  g_qhi);
    cudaGetSymbolAddress((void**)&qlo,  g_qlo);
    cudaGetSymbolAddress((void**)&ahi,  g_ahi);

    cudaFuncSetAttribute(gemm_mma_kernel,
                         cudaFuncAttributeMaxDynamicSharedMemorySize, GEMM_SMEM);
    cudaFuncSetAttribute(attn_mma_kernel,
                         cudaFuncAttributeMaxDynamicSharedMemorySize, ATTN_SMEM);

    convert_half_kernel<<<(M_ * C_) / 4 / 256, 256>>>(x, xh, M_ * C_);
    transpose_half_kernel<<<dim3(C3_ / 32, C_ / 32), dim3(32, 8)>>>(
        w_qkv, wqhi, C_, C3_);
    transpose_half_kernel<<<dim3(C_ / 32, C_ / 32), dim3(32, 8)>>>(
        w_out, wohi, C_, C_);

    // GEMM1: qkv = x @ Wqkv + b  -> fp16 hi/lo (1-term MMA)
    gemm_mma_kernel<<<dim3(C3_ / 64, M_ / 128), 256, GEMM_SMEM>>>(
        xh, wqhi, b_qkv, nullptr, qhi, qlo, C3_, C_);

    // attention (mma.sync fp16) -> single fp16
    attn_mma_kernel<<<dim3(T_ / 128, H_, B_), 256, ATTN_SMEM>>>(
        qhi, qlo, ahi);

    // GEMM2: out = att @ Wout + b -> fp32 (1-term MMA)
    gemm_mma_kernel<<<dim3(C_ / 64, M_ / 128), 256, GEMM_SMEM>>>(
        ahi, wohi, b_out, out, nullptr, nullptr, C_, C_);
}

// round 16
// speedup vs baseline: 4.8801x; 1.2177x over previous
#include <cuda_runtime.h>
#include <cuda_fp16.h>
#include <cstdint>
#include <math.h>

// ---------------------------------------------------------------------------
// Problem:
//   x (4,2048,1024) f32; w_qkv (1024,3072); b_qkv (3072,);
//   w_out (1024,1024); b_out (1024,); out (4,2048,1024) f32
// Precision scheme (fp16):
//   GEMM1: single-fp16 x @ single-fp16 Wqkv (1 term) -> qkv hi/lo (exact split)
//   attention S: 2-term Qh.(Kh+Kl); PV: 2-term (Ph+Pl).Vh
//   GEMM2: single-fp16 a @ single-fp16 Wout (1 term)
// R16: fix R15 smem overflow — ATTN_SMEM must cover BOTH KV stages
// (2*ASTAGE_B); Q staging overlaps stage 1 (consumed to regs first).
// ---------------------------------------------------------------------------
#define B_   4
#define T_   2048
#define C_   1024
#define H_   16
#define DH_  64
#define M_   (B_ * T_)       // 8192
#define C3_  (3 * C_)        // 3072

__device__ __half g_xh[(size_t)M_ * C_];      // x single fp16
__device__ __half g_wqhi[(size_t)C3_ * C_];   // Wqkv^T single fp16
__device__ __half g_wohi[(size_t)C_ * C_];    // Wout^T single fp16
__device__ __half g_qhi[(size_t)M_ * C3_];    // qkv hi
__device__ __half g_qlo[(size_t)M_ * C3_];    // qkv lo
__device__ __half g_ahi[(size_t)M_ * C_];     // attention out single fp16

// ---------------------------------------------------------------------------
__device__ __forceinline__ uint32_t smem_u32(const void* p) {
    uint32_t a;
    asm("{ .reg .u64 t; cvta.to.shared.u64 t, %1; cvt.u32.u64 %0, t; }"
        : "=r"(a) : "l"(p));
    return a;
}

#define LDSM4(r0, r1, r2, r3, addr) \
    asm volatile("ldmatrix.sync.aligned.m8n8.x4.shared.b16 {%0,%1,%2,%3}, [%4];" \
        : "=r"(r0), "=r"(r1), "=r"(r2), "=r"(r3) : "r"(addr))
#define LDSM4T(r0, r1, r2, r3, addr) \
    asm volatile("ldmatrix.sync.aligned.m8n8.x4.trans.shared.b16 {%0,%1,%2,%3}, [%4];" \
        : "=r"(r0), "=r"(r1), "=r"(r2), "=r"(r3) : "r"(addr))

#define MMAF(c, a, b0r, b1r) \
    asm volatile("mma.sync.aligned.m16n8k16.row.col.f32.f16.f16.f32 " \
        "{%0,%1,%2,%3}, {%4,%5,%6,%7}, {%8,%9}, {%0,%1,%2,%3};" \
        : "+f"((c)[0]), "+f"((c)[1]), "+f"((c)[2]), "+f"((c)[3]) \
        : "r"((a)[0]), "r"((a)[1]), "r"((a)[2]), "r"((a)[3]), \
          "r"(b0r), "r"(b1r))

#define CP_ASYNC16(dst, src) \
    asm volatile("cp.async.cg.shared.global [%0], [%1], 16;" :: "r"(dst), "l"(src))
#define CP_COMMIT() asm volatile("cp.async.commit_group;" ::: "memory")
#define CP_WAIT1()  asm volatile("cp.async.wait_group 1;" ::: "memory")
#define CP_WAIT0()  asm volatile("cp.async.wait_group 0;" ::: "memory")

// pack two floats -> fp16x2 hi reg + residual lo reg
__device__ __forceinline__ void pack2(float x, float y, uint32_t& hi, uint32_t& lo) {
    __half hx = __float2half(x), hy = __float2half(y);
    __half2 hh; hh.x = hx; hh.y = hy;
    hi = *reinterpret_cast<uint32_t*>(&hh);
    __half2 ll;
    ll.x = __float2half(x - __half2float(hx));
    ll.y = __float2half(y - __half2float(hy));
    lo = *reinterpret_cast<uint32_t*>(&ll);
}

// ---------------------------------------------------------------------------
// Prep kernels
// ---------------------------------------------------------------------------
__global__ __launch_bounds__(256) void convert_half_kernel(
    const float* __restrict__ in, __half* __restrict__ out, int n)
{
    int i = (blockIdx.x * 256 + threadIdx.x) * 4;
    if (i >= n) return;
    float4 v = *(const float4*)(in + i);
    __half2 a; a.x = __float2half(v.x); a.y = __float2half(v.y);
    __half2 b; b.x = __float2half(v.z); b.y = __float2half(v.w);
    *(__half2*)(out + i)     = a;
    *(__half2*)(out + i + 2) = b;
}

// w[K][N] -> t[N][K], single fp16.  Block (32,8), grid (N/32, K/32).
__global__ __launch_bounds__(256) void transpose_half_kernel(
    const float* __restrict__ w, __half* __restrict__ thi, int K, int N)
{
    __shared__ float tile[32][33];
    int n0 = blockIdx.x * 32, k0 = blockIdx.y * 32;
    int tx = threadIdx.x, ty = threadIdx.y;
#pragma unroll
    for (int j = 0; j < 32; j += 8)
        tile[ty + j][tx] = w[(size_t)(k0 + ty + j) * N + n0 + tx];
    __syncthreads();
#pragma unroll
    for (int j = 0; j < 32; j += 8) {
        size_t idx = (size_t)(n0 + ty + j) * K + k0 + tx;
        thi[idx] = __float2half(tile[tx][ty + j]);
    }
}

// ---------------------------------------------------------------------------
// mma.sync GEMM: C = A @ B^T + bias      (A, B single fp16, 1 MMA term)
// CTA tile 128x128, BK=32, 8 warps (4x2), warp tile 32x64 (mi=2, nf=8).
// 3-stage cp.async pipeline (WAIT -> sync -> load -> compute), 2 CTAs/SM.
// Smem/stage: A[128][40] + B[128][40] = 10240 elems (20480 B); 3 stg 61440 B.
// ---------------------------------------------------------------------------
#define KSTRIDE 40
#define G_ATILE (128 * KSTRIDE)          // 5120 elems
#define G_STAGE (2 * G_ATILE)            // 10240 elems
#define G_NSTG  3
#define GEMM_SMEM (G_NSTG * G_STAGE * 2) // 61440 B

__global__ __launch_bounds__(256, 2)
void gemm_mma_kernel(
    const __half* __restrict__ A, const __half* __restrict__ Bm,
    const float* __restrict__ bias,
    float* __restrict__ Cf,
    __half* __restrict__ Chi, __half* __restrict__ Clo,
    int N, int K)
{
    extern __shared__ __half smb[];
    const uint32_t sbase = smem_u32(smb);

    const int tid  = threadIdx.x;
    const int lane = tid & 31;
    const int wid  = tid >> 5;
    const int wm   = wid & 3;            // 0..3 -> m offset wm*32
    const int wn   = wid >> 2;           // 0..1 -> n offset wn*64
    const int bx = blockIdx.x, by = blockIdx.y;

    const __half* Ab = A  + (size_t)(by * 128) * K;   // 128 rows
    const __half* Bb = Bm + (size_t)(bx * 128) * K;   // 128 rows

    float acc[2][8][4];
#pragma unroll
    for (int mi = 0; mi < 2; mi++)
#pragma unroll
        for (int nf = 0; nf < 8; nf++)
#pragma unroll
            for (int r = 0; r < 4; r++) acc[mi][nf][r] = 0.f;

    // 1024 x16B chunks per stage, 4 per thread
    auto load_stage = [&](int stage, int k0) {
#pragma unroll
        for (int i = 0; i < 4; i++) {
            int idx  = tid + i * 256;          // 0..1023
            int tile = idx >> 9;               // 0:A 1:B
            int r    = (idx >> 2) & 127;
            int c    = idx & 3;
            const __half* g = (tile ? Bb : Ab) + (size_t)r * K + k0 + c * 8;
            uint32_t d = sbase +
                (uint32_t)(stage * G_STAGE + tile * G_ATILE + r * KSTRIDE + c * 8) * 2;
            CP_ASYNC16(d, g);
        }
    };

    auto compute = [&](int stage) {
        const uint32_t As = sbase + (uint32_t)(stage * G_STAGE) * 2;
        const uint32_t Bs = As + G_ATILE * 2;
#pragma unroll
        for (int ks = 0; ks < 2; ks++) {
            uint32_t a[2][4];
            uint32_t bh[4][4];
            const int ar = wm * 32 + (lane & 15);
            const int ac = ks * 16 + (lane >> 4) * 8;
#pragma unroll
            for (int mi = 0; mi < 2; mi++) {
                uint32_t off = (uint32_t)((ar + mi * 16) * KSTRIDE + ac) * 2;
                LDSM4(a[mi][0], a[mi][1], a[mi][2], a[mi][3], As + off);
            }
            const int br = wn * 64 + ((lane >> 4) << 3) + (lane & 7);
            const int bc = ks * 16 + ((lane >> 3) & 1) * 8;
#pragma unroll
            for (int p = 0; p < 4; p++) {
                uint32_t off = (uint32_t)((br + p * 16) * KSTRIDE + bc) * 2;
                LDSM4(bh[p][0], bh[p][1], bh[p][2], bh[p][3], Bs + off);
            }
#pragma unroll
            for (int mi = 0; mi < 2; mi++)
#pragma unroll
                for (int nf = 0; nf < 8; nf++) {
                    uint32_t b0 = bh[nf >> 1][(nf & 1) * 2];
                    uint32_t b1 = bh[nf >> 1][(nf & 1) * 2 + 1];
                    MMAF(acc[mi][nf], a[mi], b0, b1);
                }
        }
    };

    const int nch = K / 32;   // 32
    load_stage(0, 0);
    CP_COMMIT();
    load_stage(1, 32);
    CP_COMMIT();

    int cs = 0, ls = 2;
    for (int ch = 0; ch < nch; ch++) {
        if (ch + 1 < nch) CP_WAIT1();
        else              CP_WAIT0();
        __syncthreads();      // publish chunk-ch data; retire compute(ch-1)
        if (ch + 2 < nch) {
            load_stage(ls, (ch + 2) * 32);
            CP_COMMIT();
        }
        compute(cs);
        cs = (cs == 2) ? 0 : cs + 1;
        ls = (ls == 2) ? 0 : ls + 1;
    }

#pragma unroll
    for (int nf = 0; nf < 8; nf++) {
        const int col = bx * 128 + wn * 64 + nf * 8 + (lane & 3) * 2;
        const float b0 = bias[col], b1 = bias[col + 1];
#pragma unroll
        for (int mi = 0; mi < 2; mi++) {
            const int r0 = by * 128 + wm * 32 + mi * 16 + (lane >> 2);
            float v0 = acc[mi][nf][0] + b0, v1 = acc[mi][nf][1] + b1;
            float v2 = acc[mi][nf][2] + b0, v3 = acc[mi][nf][3] + b1;
            if (Cf) {
                float2 w0; w0.x = v0; w0.y = v1;
                float2 w1; w1.x = v2; w1.y = v3;
                *(float2*)(Cf + (size_t)r0 * N + col)       = w0;
                *(float2*)(Cf + (size_t)(r0 + 8) * N + col) = w1;
            } else {
                uint32_t h0, l0, h1, l1;
                pack2(v0, v1, h0, l0);
                pack2(v2, v3, h1, l1);
                *(uint32_t*)(Chi + (size_t)r0 * N + col)       = h0;
                *(uint32_t*)(Clo + (size_t)r0 * N + col)       = l0;
                *(uint32_t*)(Chi + (size_t)(r0 + 8) * N + col) = h1;
                *(uint32_t*)(Clo + (size_t)(r0 + 8) * N + col) = l1;
            }
        }
    }
}

// ---------------------------------------------------------------------------
// Flash attention, mma.sync fp16, causal.
// S: 2-term Qh.(Kh+Kl); PV: (Ph+Pl).Vh.  Output single fp16.
// CTA: 128 q-rows x (b,h); 8 warps; K-tiles of 64 keys, double-buffered.
// Stage = 3 tiles (Khi, Klo, Vhi).
// SMEM = BOTH stages (2*ASTAGE_B); Q (hi only, QREG_B <= ASTAGE_B) is staged
// inside stage 1's region and consumed to registers before stage 1's first
// KV load (ordered by the post-Q-read __syncthreads).
// ---------------------------------------------------------------------------
#define ASTR 72
#define KVT_B (64 * ASTR * 2)       // 9216 B per tile
#define ASTAGE_B (3 * KVT_B)        // 27648 B
#define Q_OFF ASTAGE_B              // Q staged at start of stage-1 region
#define QREG_B (128 * ASTR * 2)     // 18432 B  (<= ASTAGE_B)
#define ATTN_SMEM (2 * ASTAGE_B)    // 55296 B  (covers stage 0 AND stage 1)

__global__ __launch_bounds__(256)
void attn_mma_kernel(
    const __half* __restrict__ qhi, const __half* __restrict__ qlo,
    __half* __restrict__ ohi)
{
    extern __shared__ char sma[];
    const uint32_t sb = smem_u32(sma);

    const int tid  = threadIdx.x;
    const int lane = tid & 31;
    const int w    = tid >> 5;
    const int qt = (int)gridDim.x - 1 - blockIdx.x;   // heavy tiles first
    const int h  = blockIdx.y;
    const int b  = blockIdx.z;
    const int q0 = qt * 128;
    const float scale = 0.125f;

    // 3 tiles x 64 rows x 8 chunks = 1536 chunks, 6 per thread
    auto load_kv = [&](int stage, int kt) {
        const int k0 = kt * 64;
#pragma unroll
        for (int i = 0; i < 6; i++) {
            int idx  = tid + i * 256;            // 0..1535
            int tile = idx >> 9;                 // 0:Khi 1:Klo 2:Vhi
            int r    = (idx >> 3) & 63;
            int c    = idx & 7;
            int colb = (tile < 2) ? C_ : 2 * C_;
            const __half* g = ((tile == 1) ? qlo : qhi) +
                (size_t)(b * T_ + k0 + r) * C3_ + colb + h * DH_ + c * 8;
            uint32_t d = sb + stage * ASTAGE_B + tile * KVT_B +
                         (uint32_t)(r * ASTR + c * 8) * 2;
            CP_ASYNC16(d, g);
        }
    };

    // ---- prologue: Q (hi only) into stage-1 region, then to registers ----
#pragma unroll
    for (int i = 0; i < 4; i++) {
        int idx = tid + i * 256;                 // 0..1023
        int r   = idx >> 3;                      // 0..127
        int c   = idx & 7;
        const __half* g = qhi +
            (size_t)(b * T_ + q0 + r) * C3_ + h * DH_ + c * 8;
        uint32_t d = sb + Q_OFF + (uint32_t)(r * ASTR + c * 8) * 2;
        CP_ASYNC16(d, g);
    }
    CP_COMMIT();
    load_kv(0, 0);
    CP_COMMIT();
    CP_WAIT1();              // Q arrived (oldest group)
    __syncthreads();

    uint32_t qf_h[4][4];
    {
        const int r = w * 16 + (lane & 15);
        const int cb = (lane >> 4) * 8;
#pragma unroll
        for (int kf = 0; kf < 4; kf++) {
            uint32_t off = sb + Q_OFF + (uint32_t)(r * ASTR + kf * 16 + cb) * 2;
            LDSM4(qf_h[kf][0], qf_h[kf][1], qf_h[kf][2], qf_h[kf][3], off);
        }
    }
    __syncthreads();         // Q consumed; stage-1 region free for KV

    float oacc[8][4];
#pragma unroll
    for (int nf = 0; nf < 8; nf++)
#pragma unroll
        for (int r = 0; r < 4; r++) oacc[nf][r] = 0.f;
    float m0 = -1e30f, m1 = -1e30f, l0 = 0.f, l1 = 0.f;

    const int nkt = 2 * qt + 2;
    for (int kt = 0; kt < nkt; kt++) {
        const int s = kt & 1;
        if (kt + 1 < nkt) { load_kv(s ^ 1, kt + 1); CP_COMMIT(); CP_WAIT1(); }
        else              { CP_WAIT0(); }
        __syncthreads();

        const uint32_t kb_h = sb + s * ASTAGE_B;
        const uint32_t kb_l = kb_h + KVT_B;
        const uint32_t vb_h = kb_h + 2 * KVT_B;

        // ---- S = Qh (Kh + Kl)^T  (2-term) ----
        float sfr[8][4];
#pragma unroll
        for (int nf = 0; nf < 8; nf++)
#pragma unroll
            for (int r = 0; r < 4; r++) sfr[nf][r] = 0.f;

#pragma unroll
        for (int kf = 0; kf < 4; kf++) {
            uint32_t bh[4][4], bl[4][4];
            const int rr = (lane >> 4) * 8 + (lane & 7);
            const int cc = kf * 16 + ((lane >> 3) & 1) * 8;
#pragma unroll
            for (int p = 0; p < 4; p++) {
                uint32_t off = (uint32_t)((p * 16 + rr) * ASTR + cc) * 2;
                LDSM4(bh[p][0], bh[p][1], bh[p][2], bh[p][3], kb_h + off);
                LDSM4(bl[p][0], bl[p][1], bl[p][2], bl[p][3], kb_l + off);
            }
#pragma unroll
            for (int nf = 0; nf < 8; nf++) {
                uint32_t bh0 = bh[nf >> 1][(nf & 1) * 2];
                uint32_t bh1 = bh[nf >> 1][(nf & 1) * 2 + 1];
                uint32_t bl0 = bl[nf >> 1][(nf & 1) * 2];
                uint32_t bl1 = bl[nf >> 1][(nf & 1) * 2 + 1];
                MMAF(sfr[nf], qf_h[kf], bh0, bh1);
                MMAF(sfr[nf], qf_h[kf], bl0, bl1);
            }
        }

#pragma unroll
        for (int nf = 0; nf < 8; nf++)
#pragma unroll
            for (int r = 0; r < 4; r++) sfr[nf][r] *= scale;

        // ---- causal mask (last two k-tiles only) ----
        if (kt >= 2 * qt) {
            const int k0 = kt * 64;
            const int r0g = q0 + w * 16 + (lane >> 2);
            const int r1g = r0g + 8;
#pragma unroll
            for (int nf = 0; nf < 8; nf++) {
                const int c0 = k0 + nf * 8 + (lane & 3) * 2;
                if (c0     > r0g) sfr[nf][0] = -1e30f;
                if (c0 + 1 > r0g) sfr[nf][1] = -1e30f;
                if (c0     > r1g) sfr[nf][2] = -1e30f;
                if (c0 + 1 > r1g) sfr[nf][3] = -1e30f;
            }
        }

        // ---- online softmax (rows quad-local: shfl lanes^1,^2) ----
        float mx0 = -1e30f, mx1 = -1e30f;
#pragma unroll
        for (int nf = 0; nf < 8; nf++) {
            mx0 = fmaxf(mx0, fmaxf(sfr[nf][0], sfr[nf][1]));
            mx1 = fmaxf(mx1, fmaxf(sfr[nf][2], sfr[nf][3]));
        }
        mx0 = fmaxf(mx0, __shfl_xor_sync(0xffffffffu, mx0, 1));
        mx0 = fmaxf(mx0, __shfl_xor_sync(0xffffffffu, mx0, 2));
        mx1 = fmaxf(mx1, __shfl_xor_sync(0xffffffffu, mx1, 1));
        mx1 = fmaxf(mx1, __shfl_xor_sync(0xffffffffu, mx1, 2));
        const float nm0 = fmaxf(m0, mx0), nm1 = fmaxf(m1, mx1);
        const float corr0 = __expf(m0 - nm0), corr1 = __expf(m1 - nm1);
        float rs0 = 0.f, rs1 = 0.f;
#pragma unroll
        for (int nf = 0; nf < 8; nf++) {
            sfr[nf][0] = __expf(sfr[nf][0] - nm0);
            sfr[nf][1] = __expf(sfr[nf][1] - nm0);
            sfr[nf][2] = __expf(sfr[nf][2] - nm1);
            sfr[nf][3] = __expf(sfr[nf][3] - nm1);
            rs0 += sfr[nf][0] + sfr[nf][1];
            rs1 += sfr[nf][2] + sfr[nf][3];
        }
        rs0 += __shfl_xor_sync(0xffffffffu, rs0, 1);
        rs0 += __shfl_xor_sync(0xffffffffu, rs0, 2);
        rs1 += __shfl_xor_sync(0xffffffffu, rs1, 1);
        rs1 += __shfl_xor_sync(0xffffffffu, rs1, 2);
        l0 = l0 * corr0 + rs0;  m0 = nm0;
        l1 = l1 * corr1 + rs1;  m1 = nm1;
#pragma unroll
        for (int nf = 0; nf < 8; nf++) {
            oacc[nf][0] *= corr0;  oacc[nf][1] *= corr0;
            oacc[nf][2] *= corr1;  oacc[nf][3] *= corr1;
        }

        // ---- repack P (S C-frags -> A-frags, registers only) ----
        // a0=rows0-7/k0-7, a1=rows8-15/k0-7, a2=rows0-7/k8-15, a3=rows8-15/k8-15
        uint32_t pa_h[4][4], pa_l[4][4];
#pragma unroll
        for (int kf = 0; kf < 4; kf++) {
            pack2(sfr[2*kf  ][0], sfr[2*kf  ][1], pa_h[kf][0], pa_l[kf][0]);
            pack2(sfr[2*kf  ][2], sfr[2*kf  ][3], pa_h[kf][1], pa_l[kf][1]);
            pack2(sfr[2*kf+1][0], sfr[2*kf+1][1], pa_h[kf][2], pa_l[kf][2]);
            pack2(sfr[2*kf+1][2], sfr[2*kf+1][3], pa_h[kf][3], pa_l[kf][3]);
        }

        // ---- O += (Ph+Pl) Vh  (V via ldmatrix.trans from [key][d]) ----
#pragma unroll
        for (int kf = 0; kf < 4; kf++) {
            uint32_t vh[4][4];
            const int rr = kf * 16 + (lane & 7) + ((lane >> 3) & 1) * 8;
            const int cc = (lane >> 4) * 8;
#pragma unroll
            for (int p = 0; p < 4; p++) {
                uint32_t off = (uint32_t)(rr * ASTR + p * 16 + cc) * 2;
                LDSM4T(vh[p][0], vh[p][1], vh[p][2], vh[p][3], vb_h + off);
            }
#pragma unroll
            for (int nf = 0; nf < 8; nf++) {
                uint32_t bh0 = vh[nf >> 1][(nf & 1) * 2];
                uint32_t bh1 = vh[nf >> 1][(nf & 1) * 2 + 1];
                MMAF(oacc[nf], pa_h[kf], bh0, bh1);
                MMAF(oacc[nf], pa_l[kf], bh0, bh1);
            }
        }
        __syncthreads();   // all warps done with stage s before next overwrite
    }

    // ---- epilogue: O/l -> single fp16 ----
    const float inv0 = 1.f / l0, inv1 = 1.f / l1;
    const int r0g = q0 + w * 16 + (lane >> 2);
#pragma unroll
    for (int nf = 0; nf < 8; nf++) {
        const int col = h * DH_ + nf * 8 + (lane & 3) * 2;
        __half2 h0, h1;
        h0.x = __float2half(oacc[nf][0] * inv0);
        h0.y = __float2half(oacc[nf][1] * inv0);
        h1.x = __float2half(oacc[nf][2] * inv1);
        h1.y = __float2half(oacc[nf][3] * inv1);
        size_t a0 = (size_t)(b * T_ + r0g) * C_ + col;
        size_t a1 = a0 + (size_t)8 * C_;
        *(__half2*)(ohi + a0) = h0;
        *(__half2*)(ohi + a1) = h1;
    }
}

// ---------------------------------------------------------------------------
// Launch
// ---------------------------------------------------------------------------
extern "C" void kernel_launch(void* const* d_in, const int* in_sizes, int n_in,
                              void* d_out, int out_size)
{
    const float* x     = (const float*)d_in[0];
    const float* w_qkv = (const float*)d_in[1];
    const float* b_qkv = (const float*)d_in[2];
    const float* w_out = (const float*)d_in[3];
    const float* b_out = (const float*)d_in[4];
    float* out = (float*)d_out;

    __half *xh, *wqhi, *wohi, *qhi, *qlo, *ahi;
    cudaGetSymbolAddress((void**)&xh,   g_xh);
    cudaGetSymbolAddress((void**)&wqhi, g_wqhi);
    cudaGetSymbolAddress((void**)&wohi, g_wohi);
    cudaGetSymbolAddress((void**)&qhi,  g_qhi);
    cudaGetSymbolAddress((void**)&qlo,  g_qlo);
    cudaGetSymbolAddress((void**)&ahi,  g_ahi);

    cudaFuncSetAttribute(gemm_mma_kernel,
                         cudaFuncAttributeMaxDynamicSharedMemorySize, GEMM_SMEM);
    cudaFuncSetAttribute(attn_mma_kernel,
                         cudaFuncAttributeMaxDynamicSharedMemorySize, ATTN_SMEM);

    convert_half_kernel<<<(M_ * C_) / 4 / 256, 256>>>(x, xh, M_ * C_);
    transpose_half_kernel<<<dim3(C3_ / 32, C_ / 32), dim3(32, 8)>>>(
        w_qkv, wqhi, C_, C3_);
    transpose_half_kernel<<<dim3(C_ / 32, C_ / 32), dim3(32, 8)>>>(
        w_out, wohi, C_, C_);

    // GEMM1: qkv = x @ Wqkv + b  -> fp16 hi/lo (1-term MMA)
    gemm_mma_kernel<<<dim3(C3_ / 128, M_ / 128), 256, GEMM_SMEM>>>(
        xh, wqhi, b_qkv, nullptr, qhi, qlo, C3_, C_);

    // attention (mma.sync fp16, S 2-term) -> single fp16
    attn_mma_kernel<<<dim3(T_ / 128, H_, B_), 256, ATTN_SMEM>>>(
        qhi, qlo, ahi);

    // GEMM2: out = att @ Wout + b -> fp32 (1-term MMA)
    gemm_mma_kernel<<<dim3(C_ / 128, M_ / 128), 256, GEMM_SMEM>>>(
        ahi, wohi, b_out, out, nullptr, nullptr, C_, C_);
}

// round 17
// speedup vs baseline: 6.1669x; 1.2637x over previous
#include <cuda_runtime.h>
#include <cuda_fp16.h>
#include <cstdint>
#include <math.h>

// ---------------------------------------------------------------------------
// Problem:
//   x (4,2048,1024) f32; w_qkv (1024,3072); b_qkv (3072,);
//   w_out (1024,1024); b_out (1024,); out (4,2048,1024) f32
// Precision scheme (all single fp16 operands, fp32 accum):
//   GEMM1: xh @ Wqkv -> qkv single fp16
//   attention: pure fp16 flash attention (S = Qh.Kh, O = Ph.Vh)
//   GEMM2: ah @ Wout -> fp32
// Error budget (measured per-term ~1.9e-4 each, RMS): ~6.7e-4 < 1e-3.
// R17: drop K-lo + P-lo terms; qkv-lo buffer eliminated entirely.
// ---------------------------------------------------------------------------
#define B_   4
#define T_   2048
#define C_   1024
#define H_   16
#define DH_  64
#define M_   (B_ * T_)       // 8192
#define C3_  (3 * C_)        // 3072

__device__ __half g_xh[(size_t)M_ * C_];      // x single fp16
__device__ __half g_wqhi[(size_t)C3_ * C_];   // Wqkv^T single fp16
__device__ __half g_wohi[(size_t)C_ * C_];    // Wout^T single fp16
__device__ __half g_qh[(size_t)M_ * C3_];     // qkv single fp16
__device__ __half g_ahi[(size_t)M_ * C_];     // attention out single fp16

// ---------------------------------------------------------------------------
__device__ __forceinline__ uint32_t smem_u32(const void* p) {
    uint32_t a;
    asm("{ .reg .u64 t; cvta.to.shared.u64 t, %1; cvt.u32.u64 %0, t; }"
        : "=r"(a) : "l"(p));
    return a;
}

#define LDSM4(r0, r1, r2, r3, addr) \
    asm volatile("ldmatrix.sync.aligned.m8n8.x4.shared.b16 {%0,%1,%2,%3}, [%4];" \
        : "=r"(r0), "=r"(r1), "=r"(r2), "=r"(r3) : "r"(addr))
#define LDSM4T(r0, r1, r2, r3, addr) \
    asm volatile("ldmatrix.sync.aligned.m8n8.x4.trans.shared.b16 {%0,%1,%2,%3}, [%4];" \
        : "=r"(r0), "=r"(r1), "=r"(r2), "=r"(r3) : "r"(addr))

#define MMAF(c, a, b0r, b1r) \
    asm volatile("mma.sync.aligned.m16n8k16.row.col.f32.f16.f16.f32 " \
        "{%0,%1,%2,%3}, {%4,%5,%6,%7}, {%8,%9}, {%0,%1,%2,%3};" \
        : "+f"((c)[0]), "+f"((c)[1]), "+f"((c)[2]), "+f"((c)[3]) \
        : "r"((a)[0]), "r"((a)[1]), "r"((a)[2]), "r"((a)[3]), \
          "r"(b0r), "r"(b1r))

#define CP_ASYNC16(dst, src) \
    asm volatile("cp.async.cg.shared.global [%0], [%1], 16;" :: "r"(dst), "l"(src))
#define CP_COMMIT() asm volatile("cp.async.commit_group;" ::: "memory")
#define CP_WAIT1()  asm volatile("cp.async.wait_group 1;" ::: "memory")
#define CP_WAIT0()  asm volatile("cp.async.wait_group 0;" ::: "memory")

// pack two floats -> fp16x2 reg
__device__ __forceinline__ uint32_t packh(float x, float y) {
    __half2 hh; hh.x = __float2half(x); hh.y = __float2half(y);
    return *reinterpret_cast<uint32_t*>(&hh);
}

// ---------------------------------------------------------------------------
// Prep kernels
// ---------------------------------------------------------------------------
__global__ __launch_bounds__(256) void convert_half_kernel(
    const float* __restrict__ in, __half* __restrict__ out, int n)
{
    int i = (blockIdx.x * 256 + threadIdx.x) * 4;
    if (i >= n) return;
    float4 v = *(const float4*)(in + i);
    __half2 a; a.x = __float2half(v.x); a.y = __float2half(v.y);
    __half2 b; b.x = __float2half(v.z); b.y = __float2half(v.w);
    *(__half2*)(out + i)     = a;
    *(__half2*)(out + i + 2) = b;
}

// w[K][N] -> t[N][K], single fp16.  Block (32,8), grid (N/32, K/32).
__global__ __launch_bounds__(256) void transpose_half_kernel(
    const float* __restrict__ w, __half* __restrict__ thi, int K, int N)
{
    __shared__ float tile[32][33];
    int n0 = blockIdx.x * 32, k0 = blockIdx.y * 32;
    int tx = threadIdx.x, ty = threadIdx.y;
#pragma unroll
    for (int j = 0; j < 32; j += 8)
        tile[ty + j][tx] = w[(size_t)(k0 + ty + j) * N + n0 + tx];
    __syncthreads();
#pragma unroll
    for (int j = 0; j < 32; j += 8) {
        size_t idx = (size_t)(n0 + ty + j) * K + k0 + tx;
        thi[idx] = __float2half(tile[tx][ty + j]);
    }
}

// ---------------------------------------------------------------------------
// mma.sync GEMM: C = A @ B^T + bias      (A, B single fp16, 1 MMA term)
// CTA tile 128x128, BK=32, 8 warps (4x2), warp tile 32x64 (mi=2, nf=8).
// 3-stage cp.async pipeline (WAIT -> sync -> load -> compute), 2 CTAs/SM.
// Output fp32 (Cf) or single fp16 (Ch).
// ---------------------------------------------------------------------------
#define KSTRIDE 40
#define G_ATILE (128 * KSTRIDE)          // 5120 elems
#define G_STAGE (2 * G_ATILE)            // 10240 elems
#define G_NSTG  3
#define GEMM_SMEM (G_NSTG * G_STAGE * 2) // 61440 B

__global__ __launch_bounds__(256, 2)
void gemm_mma_kernel(
    const __half* __restrict__ A, const __half* __restrict__ Bm,
    const float* __restrict__ bias,
    float* __restrict__ Cf, __half* __restrict__ Ch,
    int N, int K)
{
    extern __shared__ __half smb[];
    const uint32_t sbase = smem_u32(smb);

    const int tid  = threadIdx.x;
    const int lane = tid & 31;
    const int wid  = tid >> 5;
    const int wm   = wid & 3;            // 0..3 -> m offset wm*32
    const int wn   = wid >> 2;           // 0..1 -> n offset wn*64
    const int bx = blockIdx.x, by = blockIdx.y;

    const __half* Ab = A  + (size_t)(by * 128) * K;
    const __half* Bb = Bm + (size_t)(bx * 128) * K;

    float acc[2][8][4];
#pragma unroll
    for (int mi = 0; mi < 2; mi++)
#pragma unroll
        for (int nf = 0; nf < 8; nf++)
#pragma unroll
            for (int r = 0; r < 4; r++) acc[mi][nf][r] = 0.f;

    // 1024 x16B chunks per stage, 4 per thread
    auto load_stage = [&](int stage, int k0) {
#pragma unroll
        for (int i = 0; i < 4; i++) {
            int idx  = tid + i * 256;          // 0..1023
            int tile = idx >> 9;               // 0:A 1:B
            int r    = (idx >> 2) & 127;
            int c    = idx & 3;
            const __half* g = (tile ? Bb : Ab) + (size_t)r * K + k0 + c * 8;
            uint32_t d = sbase +
                (uint32_t)(stage * G_STAGE + tile * G_ATILE + r * KSTRIDE + c * 8) * 2;
            CP_ASYNC16(d, g);
        }
    };

    auto compute = [&](int stage) {
        const uint32_t As = sbase + (uint32_t)(stage * G_STAGE) * 2;
        const uint32_t Bs = As + G_ATILE * 2;
#pragma unroll
        for (int ks = 0; ks < 2; ks++) {
            uint32_t a[2][4];
            uint32_t bh[4][4];
            const int ar = wm * 32 + (lane & 15);
            const int ac = ks * 16 + (lane >> 4) * 8;
#pragma unroll
            for (int mi = 0; mi < 2; mi++) {
                uint32_t off = (uint32_t)((ar + mi * 16) * KSTRIDE + ac) * 2;
                LDSM4(a[mi][0], a[mi][1], a[mi][2], a[mi][3], As + off);
            }
            const int br = wn * 64 + ((lane >> 4) << 3) + (lane & 7);
            const int bc = ks * 16 + ((lane >> 3) & 1) * 8;
#pragma unroll
            for (int p = 0; p < 4; p++) {
                uint32_t off = (uint32_t)((br + p * 16) * KSTRIDE + bc) * 2;
                LDSM4(bh[p][0], bh[p][1], bh[p][2], bh[p][3], Bs + off);
            }
#pragma unroll
            for (int mi = 0; mi < 2; mi++)
#pragma unroll
                for (int nf = 0; nf < 8; nf++) {
                    uint32_t b0 = bh[nf >> 1][(nf & 1) * 2];
                    uint32_t b1 = bh[nf >> 1][(nf & 1) * 2 + 1];
                    MMAF(acc[mi][nf], a[mi], b0, b1);
                }
        }
    };

    const int nch = K / 32;   // 32
    load_stage(0, 0);
    CP_COMMIT();
    load_stage(1, 32);
    CP_COMMIT();

    int cs = 0, ls = 2;
    for (int ch = 0; ch < nch; ch++) {
        if (ch + 1 < nch) CP_WAIT1();
        else              CP_WAIT0();
        __syncthreads();      // publish chunk-ch data; retire compute(ch-1)
        if (ch + 2 < nch) {
            load_stage(ls, (ch + 2) * 32);
            CP_COMMIT();
        }
        compute(cs);
        cs = (cs == 2) ? 0 : cs + 1;
        ls = (ls == 2) ? 0 : ls + 1;
    }

#pragma unroll
    for (int nf = 0; nf < 8; nf++) {
        const int col = bx * 128 + wn * 64 + nf * 8 + (lane & 3) * 2;
        const float b0 = bias[col], b1 = bias[col + 1];
#pragma unroll
        for (int mi = 0; mi < 2; mi++) {
            const int r0 = by * 128 + wm * 32 + mi * 16 + (lane >> 2);
            float v0 = acc[mi][nf][0] + b0, v1 = acc[mi][nf][1] + b1;
            float v2 = acc[mi][nf][2] + b0, v3 = acc[mi][nf][3] + b1;
            if (Cf) {
                float2 w0; w0.x = v0; w0.y = v1;
                float2 w1; w1.x = v2; w1.y = v3;
                *(float2*)(Cf + (size_t)r0 * N + col)       = w0;
                *(float2*)(Cf + (size_t)(r0 + 8) * N + col) = w1;
            } else {
                *(uint32_t*)(Ch + (size_t)r0 * N + col)       = packh(v0, v1);
                *(uint32_t*)(Ch + (size_t)(r0 + 8) * N + col) = packh(v2, v3);
            }
        }
    }
}

// ---------------------------------------------------------------------------
// Flash attention, mma.sync single fp16, causal.
// S = Qh.Kh; O = Ph.Vh.  Output single fp16.
// CTA: 128 q-rows x (b,h); 8 warps; K-tiles of 64 keys, double-buffered.
// Stage = 2 tiles (Kh, Vh), 18432 B. Q staged in stage-1 region (consumed
// to registers before stage 1's first KV load; ordered by __syncthreads).
// ---------------------------------------------------------------------------
#define ASTR 72
#define KVT_B (64 * ASTR * 2)       // 9216 B per tile
#define ASTAGE_B (2 * KVT_B)        // 18432 B
#define Q_OFF ASTAGE_B              // Q staged at start of stage-1 region
#define QREG_B (128 * ASTR * 2)     // 18432 B (== ASTAGE_B, fits exactly)
#define ATTN_SMEM (2 * ASTAGE_B)    // 36864 B

__global__ __launch_bounds__(256)
void attn_mma_kernel(
    const __half* __restrict__ qh, __half* __restrict__ ohi)
{
    extern __shared__ char sma[];
    const uint32_t sb = smem_u32(sma);

    const int tid  = threadIdx.x;
    const int lane = tid & 31;
    const int w    = tid >> 5;
    const int qt = (int)gridDim.x - 1 - blockIdx.x;   // heavy tiles first
    const int h  = blockIdx.y;
    const int b  = blockIdx.z;
    const int q0 = qt * 128;
    const float scale = 0.125f;

    // 2 tiles x 64 rows x 8 chunks = 1024 chunks, 4 per thread
    auto load_kv = [&](int stage, int kt) {
        const int k0 = kt * 64;
#pragma unroll
        for (int i = 0; i < 4; i++) {
            int idx  = tid + i * 256;            // 0..1023
            int tile = idx >> 9;                 // 0:Kh 1:Vh
            int r    = (idx >> 3) & 63;
            int c    = idx & 7;
            int colb = (tile == 0) ? C_ : 2 * C_;
            const __half* g = qh +
                (size_t)(b * T_ + k0 + r) * C3_ + colb + h * DH_ + c * 8;
            uint32_t d = sb + stage * ASTAGE_B + tile * KVT_B +
                         (uint32_t)(r * ASTR + c * 8) * 2;
            CP_ASYNC16(d, g);
        }
    };

    // ---- prologue: Q into stage-1 region, then to registers ----
#pragma unroll
    for (int i = 0; i < 4; i++) {
        int idx = tid + i * 256;                 // 0..1023
        int r   = idx >> 3;                      // 0..127
        int c   = idx & 7;
        const __half* g = qh +
            (size_t)(b * T_ + q0 + r) * C3_ + h * DH_ + c * 8;
        uint32_t d = sb + Q_OFF + (uint32_t)(r * ASTR + c * 8) * 2;
        CP_ASYNC16(d, g);
    }
    CP_COMMIT();
    load_kv(0, 0);
    CP_COMMIT();
    CP_WAIT1();              // Q arrived (oldest group)
    __syncthreads();

    uint32_t qf_h[4][4];
    {
        const int r = w * 16 + (lane & 15);
        const int cb = (lane >> 4) * 8;
#pragma unroll
        for (int kf = 0; kf < 4; kf++) {
            uint32_t off = sb + Q_OFF + (uint32_t)(r * ASTR + kf * 16 + cb) * 2;
            LDSM4(qf_h[kf][0], qf_h[kf][1], qf_h[kf][2], qf_h[kf][3], off);
        }
    }
    __syncthreads();         // Q consumed; stage-1 region free for KV

    float oacc[8][4];
#pragma unroll
    for (int nf = 0; nf < 8; nf++)
#pragma unroll
        for (int r = 0; r < 4; r++) oacc[nf][r] = 0.f;
    float m0 = -1e30f, m1 = -1e30f, l0 = 0.f, l1 = 0.f;

    const int nkt = 2 * qt + 2;
    for (int kt = 0; kt < nkt; kt++) {
        const int s = kt & 1;
        if (kt + 1 < nkt) { load_kv(s ^ 1, kt + 1); CP_COMMIT(); CP_WAIT1(); }
        else              { CP_WAIT0(); }
        __syncthreads();

        const uint32_t kb_h = sb + s * ASTAGE_B;
        const uint32_t vb_h = kb_h + KVT_B;

        // ---- S = Qh Kh^T ----
        float sfr[8][4];
#pragma unroll
        for (int nf = 0; nf < 8; nf++)
#pragma unroll
            for (int r = 0; r < 4; r++) sfr[nf][r] = 0.f;

#pragma unroll
        for (int kf = 0; kf < 4; kf++) {
            uint32_t bh[4][4];
            const int rr = (lane >> 4) * 8 + (lane & 7);
            const int cc = kf * 16 + ((lane >> 3) & 1) * 8;
#pragma unroll
            for (int p = 0; p < 4; p++) {
                uint32_t off = (uint32_t)((p * 16 + rr) * ASTR + cc) * 2;
                LDSM4(bh[p][0], bh[p][1], bh[p][2], bh[p][3], kb_h + off);
            }
#pragma unroll
            for (int nf = 0; nf < 8; nf++) {
                uint32_t bh0 = bh[nf >> 1][(nf & 1) * 2];
                uint32_t bh1 = bh[nf >> 1][(nf & 1) * 2 + 1];
                MMAF(sfr[nf], qf_h[kf], bh0, bh1);
            }
        }

#pragma unroll
        for (int nf = 0; nf < 8; nf++)
#pragma unroll
            for (int r = 0; r < 4; r++) sfr[nf][r] *= scale;

        // ---- causal mask (last two k-tiles only) ----
        if (kt >= 2 * qt) {
            const int k0 = kt * 64;
            const int r0g = q0 + w * 16 + (lane >> 2);
            const int r1g = r0g + 8;
#pragma unroll
            for (int nf = 0; nf < 8; nf++) {
                const int c0 = k0 + nf * 8 + (lane & 3) * 2;
                if (c0     > r0g) sfr[nf][0] = -1e30f;
                if (c0 + 1 > r0g) sfr[nf][1] = -1e30f;
                if (c0     > r1g) sfr[nf][2] = -1e30f;
                if (c0 + 1 > r1g) sfr[nf][3] = -1e30f;
            }
        }

        // ---- online softmax (rows quad-local: shfl lanes^1,^2) ----
        float mx0 = -1e30f, mx1 = -1e30f;
#pragma unroll
        for (int nf = 0; nf < 8; nf++) {
            mx0 = fmaxf(mx0, fmaxf(sfr[nf][0], sfr[nf][1]));
            mx1 = fmaxf(mx1, fmaxf(sfr[nf][2], sfr[nf][3]));
        }
        mx0 = fmaxf(mx0, __shfl_xor_sync(0xffffffffu, mx0, 1));
        mx0 = fmaxf(mx0, __shfl_xor_sync(0xffffffffu, mx0, 2));
        mx1 = fmaxf(mx1, __shfl_xor_sync(0xffffffffu, mx1, 1));
        mx1 = fmaxf(mx1, __shfl_xor_sync(0xffffffffu, mx1, 2));
        const float nm0 = fmaxf(m0, mx0), nm1 = fmaxf(m1, mx1);
        const float corr0 = __expf(m0 - nm0), corr1 = __expf(m1 - nm1);
        float rs0 = 0.f, rs1 = 0.f;
#pragma unroll
        for (int nf = 0; nf < 8; nf++) {
            sfr[nf][0] = __expf(sfr[nf][0] - nm0);
            sfr[nf][1] = __expf(sfr[nf][1] - nm0);
            sfr[nf][2] = __expf(sfr[nf][2] - nm1);
            sfr[nf][3] = __expf(sfr[nf][3] - nm1);
            rs0 += sfr[nf][0] + sfr[nf][1];
            rs1 += sfr[nf][2] + sfr[nf][3];
        }
        rs0 += __shfl_xor_sync(0xffffffffu, rs0, 1);
        rs0 += __shfl_xor_sync(0xffffffffu, rs0, 2);
        rs1 += __shfl_xor_sync(0xffffffffu, rs1, 1);
        rs1 += __shfl_xor_sync(0xffffffffu, rs1, 2);
        l0 = l0 * corr0 + rs0;  m0 = nm0;
        l1 = l1 * corr1 + rs1;  m1 = nm1;
#pragma unroll
        for (int nf = 0; nf < 8; nf++) {
            oacc[nf][0] *= corr0;  oacc[nf][1] *= corr0;
            oacc[nf][2] *= corr1;  oacc[nf][3] *= corr1;
        }

        // ---- repack P (S C-frags -> A-frags, registers only) ----
        // a0=rows0-7/k0-7, a1=rows8-15/k0-7, a2=rows0-7/k8-15, a3=rows8-15/k8-15
        uint32_t pa_h[4][4];
#pragma unroll
        for (int kf = 0; kf < 4; kf++) {
            pa_h[kf][0] = packh(sfr[2*kf  ][0], sfr[2*kf  ][1]);
            pa_h[kf][1] = packh(sfr[2*kf  ][2], sfr[2*kf  ][3]);
            pa_h[kf][2] = packh(sfr[2*kf+1][0], sfr[2*kf+1][1]);
            pa_h[kf][3] = packh(sfr[2*kf+1][2], sfr[2*kf+1][3]);
        }

        // ---- O += Ph Vh  (V via ldmatrix.trans from [key][d]) ----
#pragma unroll
        for (int kf = 0; kf < 4; kf++) {
            uint32_t vh[4][4];
            const int rr = kf * 16 + (lane & 7) + ((lane >> 3) & 1) * 8;
            const int cc = (lane >> 4) * 8;
#pragma unroll
            for (int p = 0; p < 4; p++) {
                uint32_t off = (uint32_t)(rr * ASTR + p * 16 + cc) * 2;
                LDSM4T(vh[p][0], vh[p][1], vh[p][2], vh[p][3], vb_h + off);
            }
#pragma unroll
            for (int nf = 0; nf < 8; nf++) {
                uint32_t bh0 = vh[nf >> 1][(nf & 1) * 2];
                uint32_t bh1 = vh[nf >> 1][(nf & 1) * 2 + 1];
                MMAF(oacc[nf], pa_h[kf], bh0, bh1);
            }
        }
        __syncthreads();   // all warps done with stage s before next overwrite
    }

    // ---- epilogue: O/l -> single fp16 ----
    const float inv0 = 1.f / l0, inv1 = 1.f / l1;
    const int r0g = q0 + w * 16 + (lane >> 2);
#pragma unroll
    for (int nf = 0; nf < 8; nf++) {
        const int col = h * DH_ + nf * 8 + (lane & 3) * 2;
        size_t a0 = (size_t)(b * T_ + r0g) * C_ + col;
        size_t a1 = a0 + (size_t)8 * C_;
        *(uint32_t*)(ohi + a0) = packh(oacc[nf][0] * inv0, oacc[nf][1] * inv0);
        *(uint32_t*)(ohi + a1) = packh(oacc[nf][2] * inv1, oacc[nf][3] * inv1);
    }
}

// ---------------------------------------------------------------------------
// Launch
// ---------------------------------------------------------------------------
extern "C" void kernel_launch(void* const* d_in, const int* in_sizes, int n_in,
                              void* d_out, int out_size)
{
    const float* x     = (const float*)d_in[0];
    const float* w_qkv = (const float*)d_in[1];
    const float* b_qkv = (const float*)d_in[2];
    const float* w_out = (const float*)d_in[3];
    const float* b_out = (const float*)d_in[4];
    float* out = (float*)d_out;

    __half *xh, *wqhi, *wohi, *qh, *ahi;
    cudaGetSymbolAddress((void**)&xh,   g_xh);
    cudaGetSymbolAddress((void**)&wqhi, g_wqhi);
    cudaGetSymbolAddress((void**)&wohi, g_wohi);
    cudaGetSymbolAddress((void**)&qh,   g_qh);
    cudaGetSymbolAddress((void**)&ahi,  g_ahi);

    cudaFuncSetAttribute(gemm_mma_kernel,
                         cudaFuncAttributeMaxDynamicSharedMemorySize, GEMM_SMEM);
    cudaFuncSetAttribute(attn_mma_kernel,
                         cudaFuncAttributeMaxDynamicSharedMemorySize, ATTN_SMEM);

    convert_half_kernel<<<(M_ * C_) / 4 / 256, 256>>>(x, xh, M_ * C_);
    transpose_half_kernel<<<dim3(C3_ / 32, C_ / 32), dim3(32, 8)>>>(
        w_qkv, wqhi, C_, C3_);
    transpose_half_kernel<<<dim3(C_ / 32, C_ / 32), dim3(32, 8)>>>(
        w_out, wohi, C_, C_);

    // GEMM1: qkv = x @ Wqkv + b  -> single fp16
    gemm_mma_kernel<<<dim3(C3_ / 128, M_ / 128), 256, GEMM_SMEM>>>(
        xh, wqhi, b_qkv, nullptr, qh, C3_, C_);

    // attention (pure fp16 mma.sync) -> single fp16
    attn_mma_kernel<<<dim3(T_ / 128, H_, B_), 256, ATTN_SMEM>>>(qh, ahi);

    // GEMM2: out = att @ Wout + b -> fp32
    gemm_mma_kernel<<<dim3(C_ / 128, M_ / 128), 256, GEMM_SMEM>>>(
        ahi, wohi, b_out, out, nullptr, C_, C_);
}